// round 1
// baseline (speedup 1.0000x reference)
#include <cuda_runtime.h>
#include <math.h>

#define NN   4096
#define EE   131072
#define INF_ 3000
#define HH   4
#define C1   128
#define D1   512   // H*C1
#define LATD 16
#define D2   64    // H*LATD
#define ETOT (EE + NN)

// ---------------- scratch (static device globals; no allocation) ----------------
__device__ float g_h1[NN * D1];
__device__ float g_x1[NN * D1];
__device__ float g_x2[NN * D1];
__device__ float g_hs[NN * D2];
__device__ float g_es1[NN * HH];
__device__ float g_ed1[NN * HH];
__device__ float g_es2[NN * HH];
__device__ float g_ed2[NN * HH];
__device__ int   g_off[NN + 1];
__device__ int   g_cur[NN];
__device__ int   g_srcs[ETOT];
__device__ float g_skey[HH * NN];
__device__ int   g_perm[HH * NN];
__device__ float g_w1s[HH * NN];
__device__ float g_w2s[HH * NN];
__device__ float g_Mb[HH];
__device__ float g_s1[HH * (NN + 1)];
__device__ float g_s2[HH * (NN + 1)];
__device__ float g_P1[HH * (NN + 1) * C1];
__device__ float g_S2[HH * (NN + 1) * C1];

__device__ __forceinline__ float lrelu(float v) { return v > 0.f ? v : 0.2f * v; }

// ---------------- fp32 tiled GEMM: C[M,N] = A[M,K] @ B[K,N] ----------------
// Requires M%128==0, N%64==0, K%8==0 (true for all 5 calls).
__global__ void gemm_kernel(const float* __restrict__ A, const float* __restrict__ B,
                            float* __restrict__ C, int M, int Nn, int K) {
    __shared__ float As[8][128];
    __shared__ float Bs[8][64];
    const int tid = threadIdx.x;                 // 256 threads
    const int bm = blockIdx.y * 128;
    const int bn = blockIdx.x * 64;
    const int tr = (tid >> 4) * 8;               // 0..120
    const int tc = (tid & 15) * 4;               // 0..60
    const int arow = tid >> 1;                   // 0..127
    const int acol = (tid & 1) * 4;              // 0 or 4
    const int brow = tid >> 5;                   // 0..7
    const int bcol = (tid & 31) * 2;             // 0..62

    float acc[8][4];
#pragma unroll
    for (int i = 0; i < 8; i++)
#pragma unroll
        for (int j = 0; j < 4; j++) acc[i][j] = 0.f;

    const float* Aptr = A + (bm + arow) * K + acol;
    const float* Bptr = B + brow * Nn + bn + bcol;

    for (int k0 = 0; k0 < K; k0 += 8) {
        float4 av = *reinterpret_cast<const float4*>(Aptr + k0);
        As[acol + 0][arow] = av.x;
        As[acol + 1][arow] = av.y;
        As[acol + 2][arow] = av.z;
        As[acol + 3][arow] = av.w;
        float2 bv = *reinterpret_cast<const float2*>(Bptr + k0 * Nn);
        Bs[brow][bcol]     = bv.x;
        Bs[brow][bcol + 1] = bv.y;
        __syncthreads();
#pragma unroll
        for (int kk = 0; kk < 8; kk++) {
            float ra[8], rb[4];
#pragma unroll
            for (int i = 0; i < 8; i++) ra[i] = As[kk][tr + i];
#pragma unroll
            for (int j = 0; j < 4; j++) rb[j] = Bs[kk][tc + j];
#pragma unroll
            for (int i = 0; i < 8; i++)
#pragma unroll
                for (int j = 0; j < 4; j++) acc[i][j] = fmaf(ra[i], rb[j], acc[i][j]);
        }
        __syncthreads();
    }
#pragma unroll
    for (int i = 0; i < 8; i++)
#pragma unroll
        for (int j = 0; j < 4; j++)
            C[(bm + tr + i) * Nn + bn + tc + j] = acc[i][j];
}

// ---------------- e_src / e_dst per (node, head) ----------------
template <int C>
__global__ void evals_kernel(const float* __restrict__ h, const float* __restrict__ asrc,
                             const float* __restrict__ adst, float* __restrict__ es,
                             float* __restrict__ ed) {
    int g = blockIdx.x * 4 + (threadIdx.x >> 5);   // (n,head) id, 4 warps/block
    int lane = threadIdx.x & 31;
    int n = g >> 2;
    int head = g & 3;
    float s1 = 0.f, s2 = 0.f;
    for (int c = lane; c < C; c += 32) {
        float hv = h[(n * HH + head) * C + c];
        s1 = fmaf(hv, asrc[head * C + c], s1);
        s2 = fmaf(hv, adst[head * C + c], s2);
    }
    for (int o = 16; o > 0; o >>= 1) {
        s1 += __shfl_xor_sync(0xffffffffu, s1, o);
        s2 += __shfl_xor_sync(0xffffffffu, s2, o);
    }
    if (lane == 0) { es[n * HH + head] = s1; ed[n * HH + head] = s2; }
}

// ---------------- CSR build (edges grouped by dst, self-loops appended) ----------------
__global__ void csr_zero() {
    int i = blockIdx.x * blockDim.x + threadIdx.x;
    if (i < NN) g_cur[i] = 0;
}
__global__ void csr_count(const int* __restrict__ dst) {
    int e = blockIdx.x * blockDim.x + threadIdx.x;
    if (e < EE) atomicAdd(&g_cur[dst[e]], 1);
}
__global__ void csr_scan() {   // single block, 1024 threads, 4 values each
    __shared__ int sh[1024];
    int t = threadIdx.x;
    int c[4]; int s = 0;
#pragma unroll
    for (int u = 0; u < 4; u++) { c[u] = g_cur[t * 4 + u] + 1; s += c[u]; }  // +1 self loop
    sh[t] = s;
    __syncthreads();
    for (int o = 1; o < 1024; o <<= 1) {
        int v = (t >= o) ? sh[t - o] : 0;
        __syncthreads();
        sh[t] += v;
        __syncthreads();
    }
    int base = sh[t] - s;  // exclusive prefix
#pragma unroll
    for (int u = 0; u < 4; u++) {
        g_off[t * 4 + u] = base;
        g_cur[t * 4 + u] = base;
        base += c[u];
    }
    if (t == 1023) g_off[NN] = sh[1023];
}
__global__ void csr_scatter(const int* __restrict__ src, const int* __restrict__ dst) {
    int e = blockIdx.x * blockDim.x + threadIdx.x;
    if (e < EE) {
        int p = atomicAdd(&g_cur[dst[e]], 1);
        g_srcs[p] = src[e];
    }
}
__global__ void csr_self() {
    int n = blockIdx.x * blockDim.x + threadIdx.x;
    if (n < NN) {
        int p = atomicAdd(&g_cur[n], 1);
        g_srcs[p] = n;
    }
}

// ---------------- sparse GAT layer, C=128, concat, +bias ----------------
__global__ void spagg_concat(const float* __restrict__ es, const float* __restrict__ ed,
                             const float* __restrict__ h, const float* __restrict__ b,
                             float* __restrict__ out) {
    int dst = blockIdx.x;
    int head = threadIdx.x >> 5;   // 4 warps = 4 heads
    int lane = threadIdx.x & 31;
    int beg = g_off[dst], end = g_off[dst + 1];
    float edv = ed[dst * HH + head];

    float m = -INFINITY;
    for (int e = beg + lane; e < end; e += 32)
        m = fmaxf(m, lrelu(es[g_srcs[e] * HH + head] + edv));
    for (int o = 16; o > 0; o >>= 1) m = fmaxf(m, __shfl_xor_sync(0xffffffffu, m, o));

    float den = 0.f;
    for (int e = beg + lane; e < end; e += 32)
        den += __expf(lrelu(es[g_srcs[e] * HH + head] + edv) - m);
    for (int o = 16; o > 0; o >>= 1) den += __shfl_xor_sync(0xffffffffu, den, o);
    float inv = 1.f / (den + 1e-16f);

    float a0 = 0.f, a1 = 0.f, a2 = 0.f, a3 = 0.f;
    for (int e = beg; e < end; e++) {
        int s = g_srcs[e];
        float w = __expf(lrelu(es[s * HH + head] + edv) - m) * inv;
        const float* hp = h + s * D1 + head * C1;
        a0 = fmaf(w, hp[lane], a0);
        a1 = fmaf(w, hp[lane + 32], a1);
        a2 = fmaf(w, hp[lane + 64], a2);
        a3 = fmaf(w, hp[lane + 96], a3);
    }
    float* op = out + dst * D1 + head * C1;
    const float* bp = b + head * C1;
    op[lane]      = a0 + bp[lane];
    op[lane + 32] = a1 + bp[lane + 32];
    op[lane + 64] = a2 + bp[lane + 64];
    op[lane + 96] = a3 + bp[lane + 96];
}

// ---------------- sparse GAT layer, C=16, mean over heads, +bias ----------------
__global__ void spagg_mean(const float* __restrict__ es, const float* __restrict__ ed,
                           const float* __restrict__ h, const float* __restrict__ b,
                           float* __restrict__ out) {
    int dst = blockIdx.x * 4 + (threadIdx.x >> 5);  // warp per dst
    int lane = threadIdx.x & 31;
    int beg = g_off[dst], end = g_off[dst + 1];
    float acc = 0.f;
    for (int head = 0; head < HH; head++) {
        float edv = ed[dst * HH + head];
        float m = -INFINITY;
        for (int e = beg + lane; e < end; e += 32)
            m = fmaxf(m, lrelu(es[g_srcs[e] * HH + head] + edv));
        for (int o = 16; o > 0; o >>= 1) m = fmaxf(m, __shfl_xor_sync(0xffffffffu, m, o));
        float den = 0.f;
        for (int e = beg + lane; e < end; e += 32)
            den += __expf(lrelu(es[g_srcs[e] * HH + head] + edv) - m);
        for (int o = 16; o > 0; o >>= 1) den += __shfl_xor_sync(0xffffffffu, den, o);
        float inv = 1.f / (den + 1e-16f);
        for (int e = beg; e < end; e++) {
            int s = g_srcs[e];
            float w = __expf(lrelu(es[s * HH + head] + edv) - m) * inv;
            if (lane < LATD) acc = fmaf(w, h[s * D2 + head * LATD + lane], acc);
        }
    }
    if (lane < LATD) out[dst * LATD + lane] = acc * 0.25f + b[lane];
}

// ---------------- per-head bitonic sort of e_src (descending) + weights ----------------
__global__ void sort_kernel(const float* __restrict__ es) {
    __shared__ float key[NN];
    __shared__ int   idx[NN];
    int head = blockIdx.x;
    int t = threadIdx.x;   // 1024
    for (int i = t; i < NN; i += 1024) { key[i] = es[i * HH + head]; idx[i] = i; }
    __syncthreads();
    for (int k = 2; k <= NN; k <<= 1) {
        for (int j = k >> 1; j > 0; j >>= 1) {
            for (int i = t; i < NN; i += 1024) {
                int ixj = i ^ j;
                if (ixj > i) {
                    bool up = (i & k) == 0;
                    float ki = key[i], kx = key[ixj];
                    bool sw = up ? (ki < kx) : (ki > kx);   // descending overall
                    if (sw) {
                        key[i] = kx; key[ixj] = ki;
                        int tmp = idx[i]; idx[i] = idx[ixj]; idx[ixj] = tmp;
                    }
                }
            }
            __syncthreads();
        }
    }
    float mb = key[0];
    for (int i = t; i < NN; i += 1024) {
        g_skey[head * NN + i] = key[i];
        g_perm[head * NN + i] = idx[i];
        float d = key[i] - mb;
        g_w1s[head * NN + i] = __expf(d);
        g_w2s[head * NN + i] = __expf(0.2f * d);
    }
    if (t == 0) g_Mb[head] = mb;
}

// ---------------- scalar prefix s1 / suffix s2 of sorted weights ----------------
__global__ void sscan_kernel() {
    int head = blockIdx.x;
    int lane = threadIdx.x;  // 32
    const float* w1 = g_w1s + head * NN;
    const float* w2 = g_w2s + head * NN;
    float* o1 = g_s1 + head * (NN + 1);
    float* o2 = g_s2 + head * (NN + 1);
    int base = lane * 128;
    float t1 = 0.f, t2 = 0.f;
    for (int t = 0; t < 128; t++) { t1 += w1[base + t]; t2 += w2[base + t]; }
    float i1 = t1, i2 = t2;
    for (int o = 1; o < 32; o <<= 1) {
        float v1 = __shfl_up_sync(0xffffffffu, i1, o);
        float v2 = __shfl_up_sync(0xffffffffu, i2, o);
        if (lane >= o) { i1 += v1; i2 += v2; }
    }
    float all2 = __shfl_sync(0xffffffffu, i2, 31);
    float off1 = i1 - t1;          // exclusive prefix of chunk totals
    float suf2 = all2 - i2;        // strict-suffix of chunk totals
    float s = off1;
    for (int t = 0; t < 128; t++) { o1[base + t] = s; s += w1[base + t]; }
    if (lane == 31) o1[NN] = s;
    float a = suf2;
    for (int t = 127; t >= 0; t--) { a += w2[base + t]; o2[base + t] = a; }
    if (lane == 31) o2[NN] = 0.f;
}

// ---------------- vector prefix P1 / suffix S2 of w*h (Kahan) ----------------
template <int C>
__global__ void vscan_kernel(const float* __restrict__ h) {
    int head = blockIdx.x;
    int c = threadIdx.x;   // C threads
    const int*   perm = g_perm + head * NN;
    const float* w1 = g_w1s + head * NN;
    const float* w2 = g_w2s + head * NN;
    float* p1 = g_P1 + (long)head * (NN + 1) * C + c;
    float* s2 = g_S2 + (long)head * (NN + 1) * C + c;
    float s = 0.f, comp = 0.f;
    p1[0] = 0.f;
    for (int j = 0; j < NN; j++) {
        int p = perm[j];
        float y = __fmaf_rn(w1[j], h[(p * HH + head) * C + c], -comp);
        float t = s + y;
        comp = (t - s) - y;
        s = t;
        p1[(long)(j + 1) * C] = s;
    }
    s = 0.f; comp = 0.f;
    s2[(long)NN * C] = 0.f;
    for (int j = NN - 1; j >= 0; j--) {
        int p = perm[j];
        float y = __fmaf_rn(w2[j], h[(p * HH + head) * C + c], -comp);
        float t = s + y;
        comp = (t - s) - y;
        s = t;
        s2[(long)j * C] = s;
    }
}

__device__ __forceinline__ int bsearch_gt(const float* sk, float t) {
    // count of (descending) keys strictly greater than t
    int lo = 0, hi = NN;
    while (lo < hi) {
        int mid = (lo + hi) >> 1;
        if (sk[mid] > t) lo = mid + 1; else hi = mid;
    }
    return lo;
}

// ---------------- dense GAT layer, C=128, concat, +bias ----------------
__global__ void dense_concat(const float* __restrict__ ed, const float* __restrict__ b,
                             float* __restrict__ out) {
    int i = blockIdx.x;
    int head = blockIdx.y;
    int c = threadIdx.x;   // 128
    float a = ed[i * HH + head];
    int k = bsearch_gt(g_skey + head * NN, -a);
    float am = a + g_Mb[head];
    float A1 = __expf(am), A2 = __expf(0.2f * am);
    float den = A1 * g_s1[head * (NN + 1) + k] + A2 * g_s2[head * (NN + 1) + k];
    long o = ((long)head * (NN + 1) + k) * C1 + c;
    float num = A1 * g_P1[o] + A2 * g_S2[o];
    out[i * D1 + head * C1 + c] = num / den + b[head * C1 + c];
}

// ---------------- dense GAT layer, C=16, mean over heads, +bias ----------------
__global__ void dense_mean(const float* __restrict__ ed, const float* __restrict__ b,
                           float* __restrict__ out) {
    __shared__ float sh[64];
    int i = blockIdx.x;
    int t = threadIdx.x;   // 64
    int head = t >> 4;
    int c = t & 15;
    float a = ed[i * HH + head];
    int k = bsearch_gt(g_skey + head * NN, -a);
    float am = a + g_Mb[head];
    float A1 = __expf(am), A2 = __expf(0.2f * am);
    float den = A1 * g_s1[head * (NN + 1) + k] + A2 * g_s2[head * (NN + 1) + k];
    long o = ((long)head * (NN + 1) + k) * LATD + c;
    float num = A1 * g_P1[o] + A2 * g_S2[o];
    sh[t] = num / den;
    __syncthreads();
    if (t < LATD)
        out[i * LATD + t] = 0.25f * (sh[t] + sh[16 + t] + sh[32 + t] + sh[48 + t]) + b[t];
}

// ---------------- launch ----------------
extern "C" void kernel_launch(void* const* d_in, const int* in_sizes, int n_in,
                              void* d_out, int out_size) {
    const float* x   = (const float*)d_in[0];
    const int*   ei  = (const int*)d_in[1];     // [2][E]
    const float* W1  = (const float*)d_in[3];
    const float* a1s = (const float*)d_in[4];
    const float* a1d = (const float*)d_in[5];
    const float* b1  = (const float*)d_in[6];
    const float* Wm  = (const float*)d_in[7];
    const float* ams = (const float*)d_in[8];
    const float* amd = (const float*)d_in[9];
    const float* bm  = (const float*)d_in[10];
    const float* Ws  = (const float*)d_in[11];
    const float* ass = (const float*)d_in[12];
    const float* asd = (const float*)d_in[13];
    const float* bs  = (const float*)d_in[14];
    float* out = (float*)d_out;
    float* z1m = out;
    float* z1s = out + NN * LATD;
    float* z2m = out + 2 * NN * LATD;
    float* z2s = out + 3 * NN * LATD;

    const int* src = ei;
    const int* dst = ei + EE;

    float *h1, *x1, *x2, *hs, *es1, *ed1, *es2, *ed2;
    cudaGetSymbolAddress((void**)&h1,  g_h1);
    cudaGetSymbolAddress((void**)&x1,  g_x1);
    cudaGetSymbolAddress((void**)&x2,  g_x2);
    cudaGetSymbolAddress((void**)&hs,  g_hs);
    cudaGetSymbolAddress((void**)&es1, g_es1);
    cudaGetSymbolAddress((void**)&ed1, g_ed1);
    cudaGetSymbolAddress((void**)&es2, g_es2);
    cudaGetSymbolAddress((void**)&ed2, g_ed2);

    // h1 = x @ W1  (shared by both branches)
    gemm_kernel<<<dim3(D1 / 64, NN / 128), 256>>>(x, W1, h1, NN, D1, INF_);
    evals_kernel<C1><<<NN, 128>>>(h1, a1s, a1d, es1, ed1);

    // CSR of (edges + self loops) grouped by dst
    csr_zero<<<16, 256>>>();
    csr_count<<<(EE + 255) / 256, 256>>>(dst);
    csr_scan<<<1, 1024>>>();
    csr_scatter<<<(EE + 255) / 256, 256>>>(src, dst);
    csr_self<<<16, 256>>>();

    // ---- sparse branch ----
    spagg_concat<<<NN, 128>>>(es1, ed1, h1, b1, x1);

    gemm_kernel<<<dim3(D2 / 64, NN / 128), 256>>>(x1, Wm, hs, NN, D2, D1);
    evals_kernel<LATD><<<NN, 128>>>(hs, ams, amd, es2, ed2);
    spagg_mean<<<NN / 4, 128>>>(es2, ed2, hs, bm, z1m);

    gemm_kernel<<<dim3(D2 / 64, NN / 128), 256>>>(x1, Ws, hs, NN, D2, D1);
    evals_kernel<LATD><<<NN, 128>>>(hs, ass, asd, es2, ed2);
    spagg_mean<<<NN / 4, 128>>>(es2, ed2, hs, bs, z1s);

    // ---- dense branch (rank-1 softmax: sort + prefix/suffix sums) ----
    sort_kernel<<<HH, 1024>>>(es1);
    sscan_kernel<<<HH, 32>>>();
    vscan_kernel<C1><<<HH, C1>>>(h1);
    dense_concat<<<dim3(NN, HH), C1>>>(ed1, b1, x2);

    gemm_kernel<<<dim3(D2 / 64, NN / 128), 256>>>(x2, Wm, hs, NN, D2, D1);
    evals_kernel<LATD><<<NN, 128>>>(hs, ams, amd, es2, ed2);
    sort_kernel<<<HH, 1024>>>(es2);
    sscan_kernel<<<HH, 32>>>();
    vscan_kernel<LATD><<<HH, LATD>>>(hs);
    dense_mean<<<NN, 64>>>(ed2, bm, z2m);

    gemm_kernel<<<dim3(D2 / 64, NN / 128), 256>>>(x2, Ws, hs, NN, D2, D1);
    evals_kernel<LATD><<<NN, 128>>>(hs, ass, asd, es2, ed2);
    sort_kernel<<<HH, 1024>>>(es2);
    sscan_kernel<<<HH, 32>>>();
    vscan_kernel<LATD><<<HH, LATD>>>(hs);
    dense_mean<<<NN, 64>>>(ed2, bs, z2s);
}

// round 2
// speedup vs baseline: 6.1274x; 6.1274x over previous
#include <cuda_runtime.h>
#include <math.h>
#include <stdint.h>

#define NN   4096
#define EE   131072
#define INF_ 3000
#define HH   4
#define C1   128
#define D1   512   // H*C1
#define LATD 16
#define D2   64    // H*LATD
#define ETOT (EE + NN)
#define NCH  32    // scan chunks
#define CHL  128   // chunk length (NN/NCH)

// ---------------- scratch (static device globals; no allocation) ----------------
__device__ float g_h1[NN * D1];
__device__ float g_x1[NN * D1];
__device__ float g_x2[NN * D1];
__device__ float g_hs[NN * D2];
__device__ float g_es1[NN * HH];
__device__ float g_ed1[NN * HH];
__device__ float g_es2[NN * HH];
__device__ float g_ed2[NN * HH];
__device__ int   g_off[NN + 1];
__device__ int   g_cur[NN];
__device__ int   g_srcs[ETOT];
__device__ float g_skey[HH * NN];
__device__ int   g_perm[HH * NN];
__device__ float g_w1s[HH * NN];
__device__ float g_w2s[HH * NN];
__device__ float g_Mb[HH];
__device__ float g_s1[HH * (NN + 1)];
__device__ float g_s2[HH * (NN + 1)];
__device__ float g_P1[HH * (NN + 1) * C1];
__device__ float g_S2[HH * (NN + 1) * C1];
__device__ float g_T1[HH * NCH * C1];
__device__ float g_T2[HH * NCH * C1];

__device__ __forceinline__ float lrelu(float v) { return v > 0.f ? v : 0.2f * v; }

// ---------------- cp.async helpers ----------------
__device__ __forceinline__ uint32_t smem_u32(const void* p) {
    return (uint32_t)__cvta_generic_to_shared(p);
}
__device__ __forceinline__ void cp16(uint32_t s, const void* g) {
    asm volatile("cp.async.cg.shared.global [%0], [%1], 16;\n" :: "r"(s), "l"(g));
}
__device__ __forceinline__ void cp_commit() {
    asm volatile("cp.async.commit_group;\n" ::: "memory");
}
template <int W>
__device__ __forceinline__ void cp_wait() {
    asm volatile("cp.async.wait_group %0;\n" :: "n"(W) : "memory");
}

// ---------------- fp32 GEMM 128x128 tile, double buffered ----------------
// Requires M%128==0, N%128==0, K%8==0.
__global__ void __launch_bounds__(256) gemm128(const float* __restrict__ A,
                                               const float* __restrict__ B,
                                               float* __restrict__ C, int M, int Nn, int K) {
    __shared__ float As[2][128][8];
    __shared__ float Bs[2][8][128];
    const int tid = threadIdx.x;
    const int bm = blockIdx.y * 128;
    const int bn = blockIdx.x * 128;
    const int arow = tid >> 1, acol = (tid & 1) * 4;
    const int brow = tid >> 5, bcol = (tid & 31) * 4;
    const int ty = (tid >> 4) * 8;
    const int tx = (tid & 15) * 8;

    const float* Ag = A + (long)(bm + arow) * K + acol;
    const float* Bg = B + (long)brow * Nn + bn + bcol;
    uint32_t aS[2] = { smem_u32(&As[0][arow][acol]), smem_u32(&As[1][arow][acol]) };
    uint32_t bS[2] = { smem_u32(&Bs[0][brow][bcol]), smem_u32(&Bs[1][brow][bcol]) };

    float acc[8][8];
#pragma unroll
    for (int i = 0; i < 8; i++)
#pragma unroll
        for (int j = 0; j < 8; j++) acc[i][j] = 0.f;

    cp16(aS[0], Ag);
    cp16(bS[0], Bg);
    cp_commit();

    int stage = 0;
    for (int k0 = 0; k0 < K; k0 += 8) {
        if (k0 + 8 < K) {
            cp16(aS[stage ^ 1], Ag + (k0 + 8));
            cp16(bS[stage ^ 1], Bg + (long)(k0 + 8) * Nn);
            cp_commit();
            cp_wait<1>();
        } else {
            cp_wait<0>();
        }
        __syncthreads();
#pragma unroll
        for (int kk = 0; kk < 8; kk++) {
            float4 b0 = *reinterpret_cast<const float4*>(&Bs[stage][kk][tx]);
            float4 b1 = *reinterpret_cast<const float4*>(&Bs[stage][kk][tx + 4]);
            float ra[8];
#pragma unroll
            for (int i = 0; i < 8; i++) ra[i] = As[stage][ty + i][kk];
#pragma unroll
            for (int i = 0; i < 8; i++) {
                acc[i][0] = fmaf(ra[i], b0.x, acc[i][0]);
                acc[i][1] = fmaf(ra[i], b0.y, acc[i][1]);
                acc[i][2] = fmaf(ra[i], b0.z, acc[i][2]);
                acc[i][3] = fmaf(ra[i], b0.w, acc[i][3]);
                acc[i][4] = fmaf(ra[i], b1.x, acc[i][4]);
                acc[i][5] = fmaf(ra[i], b1.y, acc[i][5]);
                acc[i][6] = fmaf(ra[i], b1.z, acc[i][6]);
                acc[i][7] = fmaf(ra[i], b1.w, acc[i][7]);
            }
        }
        __syncthreads();
        stage ^= 1;
    }
#pragma unroll
    for (int i = 0; i < 8; i++) {
        float* cp = C + (long)(bm + ty + i) * Nn + bn + tx;
        *reinterpret_cast<float4*>(cp)     = make_float4(acc[i][0], acc[i][1], acc[i][2], acc[i][3]);
        *reinterpret_cast<float4*>(cp + 4) = make_float4(acc[i][4], acc[i][5], acc[i][6], acc[i][7]);
    }
}

// ---------------- fp32 GEMM 64x64 tile, double buffered ----------------
// Requires M%64==0, N%64==0, K%8==0.
__global__ void __launch_bounds__(128) gemm64(const float* __restrict__ A,
                                              const float* __restrict__ B,
                                              float* __restrict__ C, int M, int Nn, int K) {
    __shared__ float As[2][64][8];
    __shared__ float Bs[2][8][64];
    const int tid = threadIdx.x;
    const int bm = blockIdx.y * 64;
    const int bn = blockIdx.x * 64;
    const int arow = tid >> 1, acol = (tid & 1) * 4;
    const int brow = tid >> 4, bcol = (tid & 15) * 4;
    const int ty = (tid >> 4) * 8;
    const int tx = (tid & 15) * 4;

    const float* Ag = A + (long)(bm + arow) * K + acol;
    const float* Bg = B + (long)brow * Nn + bn + bcol;
    uint32_t aS[2] = { smem_u32(&As[0][arow][acol]), smem_u32(&As[1][arow][acol]) };
    uint32_t bS[2] = { smem_u32(&Bs[0][brow][bcol]), smem_u32(&Bs[1][brow][bcol]) };

    float acc[8][4];
#pragma unroll
    for (int i = 0; i < 8; i++)
#pragma unroll
        for (int j = 0; j < 4; j++) acc[i][j] = 0.f;

    cp16(aS[0], Ag);
    cp16(bS[0], Bg);
    cp_commit();

    int stage = 0;
    for (int k0 = 0; k0 < K; k0 += 8) {
        if (k0 + 8 < K) {
            cp16(aS[stage ^ 1], Ag + (k0 + 8));
            cp16(bS[stage ^ 1], Bg + (long)(k0 + 8) * Nn);
            cp_commit();
            cp_wait<1>();
        } else {
            cp_wait<0>();
        }
        __syncthreads();
#pragma unroll
        for (int kk = 0; kk < 8; kk++) {
            float4 b0 = *reinterpret_cast<const float4*>(&Bs[stage][kk][tx]);
            float ra[8];
#pragma unroll
            for (int i = 0; i < 8; i++) ra[i] = As[stage][ty + i][kk];
#pragma unroll
            for (int i = 0; i < 8; i++) {
                acc[i][0] = fmaf(ra[i], b0.x, acc[i][0]);
                acc[i][1] = fmaf(ra[i], b0.y, acc[i][1]);
                acc[i][2] = fmaf(ra[i], b0.z, acc[i][2]);
                acc[i][3] = fmaf(ra[i], b0.w, acc[i][3]);
            }
        }
        __syncthreads();
        stage ^= 1;
    }
#pragma unroll
    for (int i = 0; i < 8; i++) {
        float* cp = C + (long)(bm + ty + i) * Nn + bn + tx;
        *reinterpret_cast<float4*>(cp) = make_float4(acc[i][0], acc[i][1], acc[i][2], acc[i][3]);
    }
}

// ---------------- e_src / e_dst per (node, head) ----------------
template <int C>
__global__ void evals_kernel(const float* __restrict__ h, const float* __restrict__ asrc,
                             const float* __restrict__ adst, float* __restrict__ es,
                             float* __restrict__ ed) {
    int g = blockIdx.x * 4 + (threadIdx.x >> 5);
    int lane = threadIdx.x & 31;
    int n = g >> 2;
    int head = g & 3;
    float s1 = 0.f, s2 = 0.f;
    for (int c = lane; c < C; c += 32) {
        float hv = h[(n * HH + head) * C + c];
        s1 = fmaf(hv, asrc[head * C + c], s1);
        s2 = fmaf(hv, adst[head * C + c], s2);
    }
    for (int o = 16; o > 0; o >>= 1) {
        s1 += __shfl_xor_sync(0xffffffffu, s1, o);
        s2 += __shfl_xor_sync(0xffffffffu, s2, o);
    }
    if (lane == 0) { es[n * HH + head] = s1; ed[n * HH + head] = s2; }
}

// ---------------- CSR build ----------------
__global__ void csr_zero() {
    int i = blockIdx.x * blockDim.x + threadIdx.x;
    if (i < NN) g_cur[i] = 0;
}
__global__ void csr_count(const int* __restrict__ dst) {
    int e = blockIdx.x * blockDim.x + threadIdx.x;
    if (e < EE) atomicAdd(&g_cur[dst[e]], 1);
}
__global__ void csr_scan() {
    __shared__ int sh[1024];
    int t = threadIdx.x;
    int c[4]; int s = 0;
#pragma unroll
    for (int u = 0; u < 4; u++) { c[u] = g_cur[t * 4 + u] + 1; s += c[u]; }
    sh[t] = s;
    __syncthreads();
    for (int o = 1; o < 1024; o <<= 1) {
        int v = (t >= o) ? sh[t - o] : 0;
        __syncthreads();
        sh[t] += v;
        __syncthreads();
    }
    int base = sh[t] - s;
#pragma unroll
    for (int u = 0; u < 4; u++) {
        g_off[t * 4 + u] = base;
        g_cur[t * 4 + u] = base;
        base += c[u];
    }
    if (t == 1023) g_off[NN] = sh[1023];
}
__global__ void csr_scatter(const int* __restrict__ src, const int* __restrict__ dst) {
    int e = blockIdx.x * blockDim.x + threadIdx.x;
    if (e < EE) {
        int p = atomicAdd(&g_cur[dst[e]], 1);
        g_srcs[p] = src[e];
    }
}
__global__ void csr_self() {
    int n = blockIdx.x * blockDim.x + threadIdx.x;
    if (n < NN) {
        int p = atomicAdd(&g_cur[n], 1);
        g_srcs[p] = n;
    }
}

// ---------------- sparse GAT layer, C=128, concat, +bias ----------------
__global__ void spagg_concat(const float* __restrict__ es, const float* __restrict__ ed,
                             const float* __restrict__ h, const float* __restrict__ b,
                             float* __restrict__ out) {
    int dst = blockIdx.x;
    int head = threadIdx.x >> 5;
    int lane = threadIdx.x & 31;
    int beg = g_off[dst], end = g_off[dst + 1];
    float edv = ed[dst * HH + head];

    float m = -INFINITY;
    for (int e = beg + lane; e < end; e += 32)
        m = fmaxf(m, lrelu(es[g_srcs[e] * HH + head] + edv));
    for (int o = 16; o > 0; o >>= 1) m = fmaxf(m, __shfl_xor_sync(0xffffffffu, m, o));

    float den = 0.f;
    for (int e = beg + lane; e < end; e += 32)
        den += __expf(lrelu(es[g_srcs[e] * HH + head] + edv) - m);
    for (int o = 16; o > 0; o >>= 1) den += __shfl_xor_sync(0xffffffffu, den, o);
    float inv = 1.f / (den + 1e-16f);

    float a0 = 0.f, a1 = 0.f, a2 = 0.f, a3 = 0.f;
    for (int e = beg; e < end; e++) {
        int s = g_srcs[e];
        float w = __expf(lrelu(es[s * HH + head] + edv) - m) * inv;
        const float* hp = h + s * D1 + head * C1;
        a0 = fmaf(w, hp[lane], a0);
        a1 = fmaf(w, hp[lane + 32], a1);
        a2 = fmaf(w, hp[lane + 64], a2);
        a3 = fmaf(w, hp[lane + 96], a3);
    }
    float* op = out + dst * D1 + head * C1;
    const float* bp = b + head * C1;
    op[lane]      = a0 + bp[lane];
    op[lane + 32] = a1 + bp[lane + 32];
    op[lane + 64] = a2 + bp[lane + 64];
    op[lane + 96] = a3 + bp[lane + 96];
}

// ---------------- sparse GAT layer, C=16, mean over heads, +bias ----------------
__global__ void spagg_mean(const float* __restrict__ es, const float* __restrict__ ed,
                           const float* __restrict__ h, const float* __restrict__ b,
                           float* __restrict__ out) {
    int dst = blockIdx.x * 4 + (threadIdx.x >> 5);
    int lane = threadIdx.x & 31;
    int beg = g_off[dst], end = g_off[dst + 1];
    float acc = 0.f;
    for (int head = 0; head < HH; head++) {
        float edv = ed[dst * HH + head];
        float m = -INFINITY;
        for (int e = beg + lane; e < end; e += 32)
            m = fmaxf(m, lrelu(es[g_srcs[e] * HH + head] + edv));
        for (int o = 16; o > 0; o >>= 1) m = fmaxf(m, __shfl_xor_sync(0xffffffffu, m, o));
        float den = 0.f;
        for (int e = beg + lane; e < end; e += 32)
            den += __expf(lrelu(es[g_srcs[e] * HH + head] + edv) - m);
        for (int o = 16; o > 0; o >>= 1) den += __shfl_xor_sync(0xffffffffu, den, o);
        float inv = 1.f / (den + 1e-16f);
        for (int e = beg; e < end; e++) {
            int s = g_srcs[e];
            float w = __expf(lrelu(es[s * HH + head] + edv) - m) * inv;
            if (lane < LATD) acc = fmaf(w, h[s * D2 + head * LATD + lane], acc);
        }
    }
    if (lane < LATD) out[dst * LATD + lane] = acc * 0.25f + b[lane];
}

// ---------------- per-head bitonic sort of e_src (descending) + weights ----------------
__global__ void sort_kernel(const float* __restrict__ es) {
    __shared__ float key[NN];
    __shared__ int   idx[NN];
    int head = blockIdx.x;
    int t = threadIdx.x;
    for (int i = t; i < NN; i += 1024) { key[i] = es[i * HH + head]; idx[i] = i; }
    __syncthreads();
    for (int k = 2; k <= NN; k <<= 1) {
        for (int j = k >> 1; j > 0; j >>= 1) {
            for (int i = t; i < NN; i += 1024) {
                int ixj = i ^ j;
                if (ixj > i) {
                    bool up = (i & k) == 0;
                    float ki = key[i], kx = key[ixj];
                    bool sw = up ? (ki < kx) : (ki > kx);
                    if (sw) {
                        key[i] = kx; key[ixj] = ki;
                        int tmp = idx[i]; idx[i] = idx[ixj]; idx[ixj] = tmp;
                    }
                }
            }
            __syncthreads();
        }
    }
    float mb = key[0];
    for (int i = t; i < NN; i += 1024) {
        g_skey[head * NN + i] = key[i];
        g_perm[head * NN + i] = idx[i];
        float d = key[i] - mb;
        g_w1s[head * NN + i] = __expf(d);
        g_w2s[head * NN + i] = __expf(0.2f * d);
    }
    if (t == 0) g_Mb[head] = mb;
}

// ---------------- scalar prefix s1 / suffix s2 of sorted weights ----------------
__global__ void sscan_kernel() {
    int head = blockIdx.x;
    int lane = threadIdx.x;
    const float* w1 = g_w1s + head * NN;
    const float* w2 = g_w2s + head * NN;
    float* o1 = g_s1 + head * (NN + 1);
    float* o2 = g_s2 + head * (NN + 1);
    int base = lane * 128;
    float t1 = 0.f, t2 = 0.f;
    for (int t = 0; t < 128; t++) { t1 += w1[base + t]; t2 += w2[base + t]; }
    float i1 = t1, i2 = t2;
    for (int o = 1; o < 32; o <<= 1) {
        float v1 = __shfl_up_sync(0xffffffffu, i1, o);
        float v2 = __shfl_up_sync(0xffffffffu, i2, o);
        if (lane >= o) { i1 += v1; i2 += v2; }
    }
    float all2 = __shfl_sync(0xffffffffu, i2, 31);
    float off1 = i1 - t1;
    float suf2 = all2 - i2;
    float s = off1;
    for (int t = 0; t < 128; t++) { o1[base + t] = s; s += w1[base + t]; }
    if (lane == 31) o1[NN] = s;
    float a = suf2;
    for (int t = 127; t >= 0; t--) { a += w2[base + t]; o2[base + t] = a; }
    if (lane == 31) o2[NN] = 0.f;
}

// ---------------- parallel vector scans of w*h (replaces serial vscan) ----------------
// Phase 1: gather & multiply. grid (HH, NN/RPB), block RPB*C.
template <int C, int RPB>
__global__ void vgather_kernel(const float* __restrict__ h) {
    int head = blockIdx.x;
    int j = blockIdx.y * RPB + threadIdx.x / C;
    int c = threadIdx.x % C;
    int p = g_perm[head * NN + j];
    float hv = h[(p * HH + head) * C + c];
    g_P1[((long)head * (NN + 1) + j + 1) * C + c] = g_w1s[head * NN + j] * hv;
    g_S2[((long)head * (NN + 1) + j) * C + c]     = g_w2s[head * NN + j] * hv;
}

// Phase 2: in-place chunk-local scans. grid (HH, NCH), block C.
template <int C>
__global__ void vchunk_kernel() {
    int head = blockIdx.x, ch = blockIdx.y, c = threadIdx.x;
    float* p1 = g_P1 + ((long)head * (NN + 1) + ch * CHL + 1) * C + c;
    float s = 0.f;
#pragma unroll 8
    for (int r = 0; r < CHL; r++) { s += p1[r * C]; p1[r * C] = s; }
    g_T1[(head * NCH + ch) * C + c] = s;
    float* s2 = g_S2 + ((long)head * (NN + 1) + ch * CHL) * C + c;
    s = 0.f;
#pragma unroll 8
    for (int r = CHL - 1; r >= 0; r--) { s += s2[r * C]; s2[r * C] = s; }
    g_T2[(head * NCH + ch) * C + c] = s;
}

// Phase 3: scan chunk totals to exclusive offsets; zero boundary rows. grid HH, block C.
template <int C>
__global__ void vofs_kernel() {
    int head = blockIdx.x, c = threadIdx.x;
    float* T1 = g_T1 + head * NCH * C + c;
    float s = 0.f;
#pragma unroll
    for (int ch = 0; ch < NCH; ch++) { float v = T1[ch * C]; T1[ch * C] = s; s += v; }
    float* T2 = g_T2 + head * NCH * C + c;
    s = 0.f;
#pragma unroll
    for (int ch = NCH - 1; ch >= 0; ch--) { float v = T2[ch * C]; T2[ch * C] = s; s += v; }
    g_P1[(long)head * (NN + 1) * C + c] = 0.f;
    g_S2[((long)head * (NN + 1) + NN) * C + c] = 0.f;
}

// Phase 4: add chunk offsets. grid (HH, NCH), block 256.
template <int C>
__global__ void vadd_kernel() {
    int head = blockIdx.x, ch = blockIdx.y;
    long base1 = ((long)head * (NN + 1) + ch * CHL + 1) * C;
    long base2 = ((long)head * (NN + 1) + ch * CHL) * C;
    const float* T1 = g_T1 + (head * NCH + ch) * C;
    const float* T2 = g_T2 + (head * NCH + ch) * C;
    for (int e = threadIdx.x; e < CHL * C; e += blockDim.x) {
        int c = e % C;
        g_P1[base1 + e] += T1[c];
        g_S2[base2 + e] += T2[c];
    }
}

__device__ __forceinline__ int bsearch_gt(const float* sk, float t) {
    int lo = 0, hi = NN;
    while (lo < hi) {
        int mid = (lo + hi) >> 1;
        if (sk[mid] > t) lo = mid + 1; else hi = mid;
    }
    return lo;
}

// ---------------- dense GAT layer, C=128, concat, +bias ----------------
__global__ void dense_concat(const float* __restrict__ ed, const float* __restrict__ b,
                             float* __restrict__ out) {
    int i = blockIdx.x;
    int head = blockIdx.y;
    int c = threadIdx.x;
    float a = ed[i * HH + head];
    int k = bsearch_gt(g_skey + head * NN, -a);
    float am = a + g_Mb[head];
    float A1 = __expf(am), A2 = __expf(0.2f * am);
    float den = A1 * g_s1[head * (NN + 1) + k] + A2 * g_s2[head * (NN + 1) + k];
    long o = ((long)head * (NN + 1) + k) * C1 + c;
    float num = A1 * g_P1[o] + A2 * g_S2[o];
    out[i * D1 + head * C1 + c] = num / den + b[head * C1 + c];
}

// ---------------- dense GAT layer, C=16, mean over heads, +bias ----------------
__global__ void dense_mean(const float* __restrict__ ed, const float* __restrict__ b,
                           float* __restrict__ out) {
    __shared__ float sh[64];
    int i = blockIdx.x;
    int t = threadIdx.x;
    int head = t >> 4;
    int c = t & 15;
    float a = ed[i * HH + head];
    int k = bsearch_gt(g_skey + head * NN, -a);
    float am = a + g_Mb[head];
    float A1 = __expf(am), A2 = __expf(0.2f * am);
    float den = A1 * g_s1[head * (NN + 1) + k] + A2 * g_s2[head * (NN + 1) + k];
    long o = ((long)head * (NN + 1) + k) * LATD + c;
    float num = A1 * g_P1[o] + A2 * g_S2[o];
    sh[t] = num / den;
    __syncthreads();
    if (t < LATD)
        out[i * LATD + t] = 0.25f * (sh[t] + sh[16 + t] + sh[32 + t] + sh[48 + t]) + b[t];
}

// ---------------- launch ----------------
extern "C" void kernel_launch(void* const* d_in, const int* in_sizes, int n_in,
                              void* d_out, int out_size) {
    const float* x   = (const float*)d_in[0];
    const int*   ei  = (const int*)d_in[1];
    const float* W1  = (const float*)d_in[3];
    const float* a1s = (const float*)d_in[4];
    const float* a1d = (const float*)d_in[5];
    const float* b1  = (const float*)d_in[6];
    const float* Wm  = (const float*)d_in[7];
    const float* ams = (const float*)d_in[8];
    const float* amd = (const float*)d_in[9];
    const float* bm  = (const float*)d_in[10];
    const float* Ws  = (const float*)d_in[11];
    const float* ass = (const float*)d_in[12];
    const float* asd = (const float*)d_in[13];
    const float* bs  = (const float*)d_in[14];
    float* out = (float*)d_out;
    float* z1m = out;
    float* z1s = out + NN * LATD;
    float* z2m = out + 2 * NN * LATD;
    float* z2s = out + 3 * NN * LATD;

    const int* src = ei;
    const int* dst = ei + EE;

    float *h1, *x1, *x2, *hs, *es1, *ed1, *es2, *ed2;
    cudaGetSymbolAddress((void**)&h1,  g_h1);
    cudaGetSymbolAddress((void**)&x1,  g_x1);
    cudaGetSymbolAddress((void**)&x2,  g_x2);
    cudaGetSymbolAddress((void**)&hs,  g_hs);
    cudaGetSymbolAddress((void**)&es1, g_es1);
    cudaGetSymbolAddress((void**)&ed1, g_ed1);
    cudaGetSymbolAddress((void**)&es2, g_es2);
    cudaGetSymbolAddress((void**)&ed2, g_ed2);

    // h1 = x @ W1  (shared by both branches)
    gemm128<<<dim3(D1 / 128, NN / 128), 256>>>(x, W1, h1, NN, D1, INF_);
    evals_kernel<C1><<<NN, 128>>>(h1, a1s, a1d, es1, ed1);

    // CSR of (edges + self loops) grouped by dst
    csr_zero<<<16, 256>>>();
    csr_count<<<(EE + 255) / 256, 256>>>(dst);
    csr_scan<<<1, 1024>>>();
    csr_scatter<<<(EE + 255) / 256, 256>>>(src, dst);
    csr_self<<<16, 256>>>();

    // ---- sparse branch ----
    spagg_concat<<<NN, 128>>>(es1, ed1, h1, b1, x1);

    gemm64<<<dim3(D2 / 64, NN / 64), 128>>>(x1, Wm, hs, NN, D2, D1);
    evals_kernel<LATD><<<NN, 128>>>(hs, ams, amd, es2, ed2);
    spagg_mean<<<NN / 4, 128>>>(es2, ed2, hs, bm, z1m);

    gemm64<<<dim3(D2 / 64, NN / 64), 128>>>(x1, Ws, hs, NN, D2, D1);
    evals_kernel<LATD><<<NN, 128>>>(hs, ass, asd, es2, ed2);
    spagg_mean<<<NN / 4, 128>>>(es2, ed2, hs, bs, z1s);

    // ---- dense branch (rank-1 softmax: sort + parallel prefix/suffix scans) ----
    sort_kernel<<<HH, 1024>>>(es1);
    sscan_kernel<<<HH, 32>>>();
    vgather_kernel<C1, 2><<<dim3(HH, NN / 2), 256>>>(h1);
    vchunk_kernel<C1><<<dim3(HH, NCH), C1>>>();
    vofs_kernel<C1><<<HH, C1>>>();
    vadd_kernel<C1><<<dim3(HH, NCH), 256>>>();
    dense_concat<<<dim3(NN, HH), C1>>>(ed1, b1, x2);

    gemm64<<<dim3(D2 / 64, NN / 64), 128>>>(x2, Wm, hs, NN, D2, D1);
    evals_kernel<LATD><<<NN, 128>>>(hs, ams, amd, es2, ed2);
    sort_kernel<<<HH, 1024>>>(es2);
    sscan_kernel<<<HH, 32>>>();
    vgather_kernel<LATD, 16><<<dim3(HH, NN / 16), 256>>>(hs);
    vchunk_kernel<LATD><<<dim3(HH, NCH), LATD>>>();
    vofs_kernel<LATD><<<HH, LATD>>>();
    vadd_kernel<LATD><<<dim3(HH, NCH), 256>>>();
    dense_mean<<<NN, 64>>>(ed2, bm, z2m);

    gemm64<<<dim3(D2 / 64, NN / 64), 128>>>(x2, Ws, hs, NN, D2, D1);
    evals_kernel<LATD><<<NN, 128>>>(hs, ass, asd, es2, ed2);
    sort_kernel<<<HH, 1024>>>(es2);
    sscan_kernel<<<HH, 32>>>();
    vgather_kernel<LATD, 16><<<dim3(HH, NN / 16), 256>>>(hs);
    vchunk_kernel<LATD><<<dim3(HH, NCH), LATD>>>();
    vofs_kernel<LATD><<<HH, LATD>>>();
    vadd_kernel<LATD><<<dim3(HH, NCH), 256>>>();
    dense_mean<<<NN, 64>>>(ed2, bs, z2s);
}

// round 4
// speedup vs baseline: 7.6480x; 1.2482x over previous
#include <cuda_runtime.h>
#include <cuda_bf16.h>
#include <math.h>
#include <stdint.h>

#define NN   4096
#define EE   131072
#define INF_ 3000
#define HH   4
#define C1   128
#define D1   512   // H*C1
#define LATD 16
#define D2   64    // H*LATD
#define ETOT (EE + NN)
#define NCH  32    // scan chunks
#define CHL  128   // chunk length (NN/NCH)
#define KP   3008  // padded K for MMA (94*32)
#define KST  32    // K per pipeline stage
#define NSTG (KP / KST)
#define ROWP 40    // padded smem row length in bf16 (32 + 8)
#define TILE_B (128 * ROWP * 2)          // one matrix tile bytes = 10240
#define STG_B  (4 * TILE_B)              // per-stage bytes = 40960

// ---------------- scratch (static device globals; no allocation) ----------------
__device__ float g_h1[NN * D1];
__device__ float g_x1[NN * D1];
__device__ float g_x2[NN * D1];
__device__ float g_hs[NN * D2];
__device__ float g_es1[NN * HH];
__device__ float g_ed1[NN * HH];
__device__ float g_es2[NN * HH];
__device__ float g_ed2[NN * HH];
__device__ int   g_off[NN + 1];
__device__ int   g_cur[NN];
__device__ int   g_srcs[ETOT];
__device__ float g_skey[HH * NN];
__device__ int   g_perm[HH * NN];
__device__ float g_w1s[HH * NN];
__device__ float g_w2s[HH * NN];
__device__ float g_Mb[HH];
__device__ float g_s1[HH * (NN + 1)];
__device__ float g_s2[HH * (NN + 1)];
__device__ float g_P1[HH * (NN + 1) * C1];
__device__ float g_S2[HH * (NN + 1) * C1];
__device__ float g_T1[HH * NCH * C1];
__device__ float g_T2[HH * NCH * C1];
// bf16 hi/lo split operands for HMMA GEMM
__device__ __align__(256) __nv_bfloat16 g_Ahi[(long)NN * KP];
__device__ __align__(256) __nv_bfloat16 g_Alo[(long)NN * KP];
__device__ __align__(256) __nv_bfloat16 g_Bhi[(long)D1 * KP];
__device__ __align__(256) __nv_bfloat16 g_Blo[(long)D1 * KP];

__device__ __forceinline__ float lrelu(float v) { return v > 0.f ? v : 0.2f * v; }

// ---------------- PTX helpers ----------------
__device__ __forceinline__ uint32_t smem_u32(const void* p) {
    return (uint32_t)__cvta_generic_to_shared(p);
}
__device__ __forceinline__ void cp16(uint32_t s, const void* g) {
    asm volatile("cp.async.cg.shared.global [%0], [%1], 16;\n" :: "r"(s), "l"(g));
}
__device__ __forceinline__ void cp_commit() {
    asm volatile("cp.async.commit_group;\n" ::: "memory");
}
template <int W>
__device__ __forceinline__ void cp_wait() {
    asm volatile("cp.async.wait_group %0;\n" :: "n"(W) : "memory");
}

// m16n8k16 row.col f32.bf16.bf16.f32
__device__ __forceinline__ void mma_bf16(float& d0, float& d1, float& d2, float& d3,
                                         uint32_t a0, uint32_t a1, uint32_t a2, uint32_t a3,
                                         uint32_t b0, uint32_t b1) {
    asm volatile(
        "mma.sync.aligned.m16n8k16.row.col.f32.bf16.bf16.f32 "
        "{%0,%1,%2,%3}, {%4,%5,%6,%7}, {%8,%9}, {%0,%1,%2,%3};"
        : "+f"(d0), "+f"(d1), "+f"(d2), "+f"(d3)
        : "r"(a0), "r"(a1), "r"(a2), "r"(a3), "r"(b0), "r"(b1));
}

// ---------------- fp32 -> bf16 hi/lo conversion of x (A operand) ----------------
struct __align__(16) bf8 { __nv_bfloat16 v[8]; };
__global__ void convA_kernel(const float* __restrict__ x) {
    const long nch = (long)NN * (KP / 8);
    for (long id = (long)blockIdx.x * blockDim.x + threadIdx.x; id < nch;
         id += (long)gridDim.x * blockDim.x) {
        long row = id / (KP / 8);
        int c = (int)(id % (KP / 8));
        bf8 hi, lo;
        if (c < INF_ / 8) {
            const float* xp = x + row * INF_ + c * 8;
#pragma unroll
            for (int j = 0; j < 8; j++) {
                float v = xp[j];
                __nv_bfloat16 h = __float2bfloat16(v);
                hi.v[j] = h;
                lo.v[j] = __float2bfloat16(v - __bfloat162float(h));
            }
        } else {
#pragma unroll
            for (int j = 0; j < 8; j++) { hi.v[j] = __float2bfloat16(0.f); lo.v[j] = hi.v[j]; }
        }
        *reinterpret_cast<bf8*>(&g_Ahi[row * KP + c * 8]) = hi;
        *reinterpret_cast<bf8*>(&g_Alo[row * KP + c * 8]) = lo;
    }
}

// ---------------- W1 [K,N] -> W^T hi/lo bf16 [N, KP] ----------------
__global__ void convBt_kernel(const float* __restrict__ W) {
    __shared__ float t[32][33];
    int kb = blockIdx.x * 32, nb = blockIdx.y * 32;
    int tx = threadIdx.x, ty = threadIdx.y;   // 32 x 8
#pragma unroll
    for (int r = 0; r < 32; r += 8) {
        int k = kb + ty + r, n = nb + tx;
        t[ty + r][tx] = (k < INF_) ? W[(long)k * D1 + n] : 0.f;
    }
    __syncthreads();
#pragma unroll
    for (int r = 0; r < 32; r += 8) {
        int n = nb + ty + r, k = kb + tx;
        float v = t[tx][ty + r];
        __nv_bfloat16 h = __float2bfloat16(v);
        g_Bhi[(long)n * KP + k] = h;
        g_Blo[(long)n * KP + k] = __float2bfloat16(v - __bfloat162float(h));
    }
}

// ---------------- HMMA GEMM: h1[4096,512] = A(hi+lo) @ B(hi+lo)^T ----------------
// 128x128 block tile, 8 warps (warp tile 64x32), K-step 32, 3-stage cp.async pipe.
__global__ void __launch_bounds__(256) mma_gemm(float* __restrict__ Cout) {
    extern __shared__ char smem[];
    const int tid = threadIdx.x;
    const int wid = tid >> 5, lane = tid & 31;
    const int g = lane >> 2, tig = lane & 3;
    const int wm = (wid & 1) * 64;
    const int wn = (wid >> 1) * 32;
    const int bn = blockIdx.x * 128;
    const int bm = blockIdx.y * 128;
    uint32_t sb = smem_u32(smem);

    float acc[4][4][4];
#pragma unroll
    for (int i = 0; i < 4; i++)
#pragma unroll
        for (int j = 0; j < 4; j++)
#pragma unroll
            for (int q = 0; q < 4; q++) acc[i][j][q] = 0.f;

    // cp.async stage loader: 2048 cp16 tasks, 8 per thread
    auto load_stage = [&](int s) {
        uint32_t base = sb + (uint32_t)(s % 3) * STG_B;
        long gk = (long)s * KST;
#pragma unroll
        for (int t = 0; t < 8; t++) {
            int id = tid + t * 256;           // 0..2047
            int mat = id >> 9;                // 0..3
            int r = (id >> 2) & 127;
            int c16 = id & 3;                 // 16B unit within 64B row
            uint32_t so = base + (uint32_t)mat * TILE_B + (uint32_t)(r * 80 + c16 * 16);
            const __nv_bfloat16* gp;
            if (mat == 0)      gp = &g_Ahi[(long)(bm + r) * KP + gk + c16 * 8];
            else if (mat == 1) gp = &g_Alo[(long)(bm + r) * KP + gk + c16 * 8];
            else if (mat == 2) gp = &g_Bhi[(long)(bn + r) * KP + gk + c16 * 8];
            else               gp = &g_Blo[(long)(bn + r) * KP + gk + c16 * 8];
            cp16(so, gp);
        }
        cp_commit();
    };

    load_stage(0);
    load_stage(1);

    for (int s = 0; s < NSTG; s++) {
        if (s + 1 < NSTG) cp_wait<1>(); else cp_wait<0>();
        __syncthreads();
        const char* stg = smem + (s % 3) * STG_B;
        const uint32_t* Ah = (const uint32_t*)(stg);
        const uint32_t* Al = (const uint32_t*)(stg + TILE_B);
        const uint32_t* Bh = (const uint32_t*)(stg + 2 * TILE_B);
        const uint32_t* Bl = (const uint32_t*)(stg + 3 * TILE_B);
#pragma unroll
        for (int ks = 0; ks < 2; ks++) {
            int kh = ks * 8;   // u32 offset of this k16 within the 40-bf16 row (20 u32)
            uint32_t ah[4][4], al[4][4], bh[4][2], bl[4][2];
#pragma unroll
            for (int tm = 0; tm < 4; tm++) {
                int r = wm + tm * 16 + g;
                ah[tm][0] = Ah[r * 20 + kh + tig];
                ah[tm][1] = Ah[(r + 8) * 20 + kh + tig];
                ah[tm][2] = Ah[r * 20 + kh + 4 + tig];
                ah[tm][3] = Ah[(r + 8) * 20 + kh + 4 + tig];
                al[tm][0] = Al[r * 20 + kh + tig];
                al[tm][1] = Al[(r + 8) * 20 + kh + tig];
                al[tm][2] = Al[r * 20 + kh + 4 + tig];
                al[tm][3] = Al[(r + 8) * 20 + kh + 4 + tig];
            }
#pragma unroll
            for (int tn = 0; tn < 4; tn++) {
                int n = wn + tn * 8 + g;
                bh[tn][0] = Bh[n * 20 + kh + tig];
                bh[tn][1] = Bh[n * 20 + kh + 4 + tig];
                bl[tn][0] = Bl[n * 20 + kh + tig];
                bl[tn][1] = Bl[n * 20 + kh + 4 + tig];
            }
#pragma unroll
            for (int tm = 0; tm < 4; tm++)
#pragma unroll
                for (int tn = 0; tn < 4; tn++) {
                    float* d = acc[tm][tn];
                    mma_bf16(d[0], d[1], d[2], d[3],
                             ah[tm][0], ah[tm][1], ah[tm][2], ah[tm][3],
                             bh[tn][0], bh[tn][1]);
                    mma_bf16(d[0], d[1], d[2], d[3],
                             ah[tm][0], ah[tm][1], ah[tm][2], ah[tm][3],
                             bl[tn][0], bl[tn][1]);
                    mma_bf16(d[0], d[1], d[2], d[3],
                             al[tm][0], al[tm][1], al[tm][2], al[tm][3],
                             bh[tn][0], bh[tn][1]);
                }
        }
        __syncthreads();
        if (s + 2 < NSTG) load_stage(s + 2);
    }

    // epilogue
#pragma unroll
    for (int tm = 0; tm < 4; tm++)
#pragma unroll
        for (int tn = 0; tn < 4; tn++) {
            int r0 = bm + wm + tm * 16 + g;
            int c0 = bn + wn + tn * 8 + 2 * tig;
            float* d = acc[tm][tn];
            *reinterpret_cast<float2*>(&Cout[(long)r0 * D1 + c0]) = make_float2(d[0], d[1]);
            *reinterpret_cast<float2*>(&Cout[(long)(r0 + 8) * D1 + c0]) = make_float2(d[2], d[3]);
        }
}

// ---------------- fp32 GEMM 64x64 tile, double buffered (small GEMMs) ----------------
__global__ void __launch_bounds__(128) gemm64(const float* __restrict__ A,
                                              const float* __restrict__ B,
                                              float* __restrict__ C, int M, int Nn, int K) {
    __shared__ float As[2][64][8];
    __shared__ float Bs[2][8][64];
    const int tid = threadIdx.x;
    const int bm = blockIdx.y * 64;
    const int bn = blockIdx.x * 64;
    const int arow = tid >> 1, acol = (tid & 1) * 4;
    const int brow = tid >> 4, bcol = (tid & 15) * 4;
    const int ty = (tid >> 4) * 8;
    const int tx = (tid & 15) * 4;

    const float* Ag = A + (long)(bm + arow) * K + acol;
    const float* Bg = B + (long)brow * Nn + bn + bcol;
    uint32_t aS[2] = { smem_u32(&As[0][arow][acol]), smem_u32(&As[1][arow][acol]) };
    uint32_t bS[2] = { smem_u32(&Bs[0][brow][bcol]), smem_u32(&Bs[1][brow][bcol]) };

    float acc[8][4];
#pragma unroll
    for (int i = 0; i < 8; i++)
#pragma unroll
        for (int j = 0; j < 4; j++) acc[i][j] = 0.f;

    cp16(aS[0], Ag);
    cp16(bS[0], Bg);
    cp_commit();

    int stage = 0;
    for (int k0 = 0; k0 < K; k0 += 8) {
        if (k0 + 8 < K) {
            cp16(aS[stage ^ 1], Ag + (k0 + 8));
            cp16(bS[stage ^ 1], Bg + (long)(k0 + 8) * Nn);
            cp_commit();
            cp_wait<1>();
        } else {
            cp_wait<0>();
        }
        __syncthreads();
#pragma unroll
        for (int kk = 0; kk < 8; kk++) {
            float4 b0 = *reinterpret_cast<const float4*>(&Bs[stage][kk][tx]);
            float ra[8];
#pragma unroll
            for (int i = 0; i < 8; i++) ra[i] = As[stage][ty + i][kk];
#pragma unroll
            for (int i = 0; i < 8; i++) {
                acc[i][0] = fmaf(ra[i], b0.x, acc[i][0]);
                acc[i][1] = fmaf(ra[i], b0.y, acc[i][1]);
                acc[i][2] = fmaf(ra[i], b0.z, acc[i][2]);
                acc[i][3] = fmaf(ra[i], b0.w, acc[i][3]);
            }
        }
        __syncthreads();
        stage ^= 1;
    }
#pragma unroll
    for (int i = 0; i < 8; i++) {
        float* cp = C + (long)(bm + ty + i) * Nn + bn + tx;
        *reinterpret_cast<float4*>(cp) = make_float4(acc[i][0], acc[i][1], acc[i][2], acc[i][3]);
    }
}

// ---------------- e_src / e_dst per (node, head) ----------------
template <int C>
__global__ void evals_kernel(const float* __restrict__ h, const float* __restrict__ asrc,
                             const float* __restrict__ adst, float* __restrict__ es,
                             float* __restrict__ ed) {
    int g = blockIdx.x * 4 + (threadIdx.x >> 5);
    int lane = threadIdx.x & 31;
    int n = g >> 2;
    int head = g & 3;
    float s1 = 0.f, s2 = 0.f;
    for (int c = lane; c < C; c += 32) {
        float hv = h[(n * HH + head) * C + c];
        s1 = fmaf(hv, asrc[head * C + c], s1);
        s2 = fmaf(hv, adst[head * C + c], s2);
    }
    for (int o = 16; o > 0; o >>= 1) {
        s1 += __shfl_xor_sync(0xffffffffu, s1, o);
        s2 += __shfl_xor_sync(0xffffffffu, s2, o);
    }
    if (lane == 0) { es[n * HH + head] = s1; ed[n * HH + head] = s2; }
}

// ---------------- CSR build ----------------
__global__ void csr_zero() {
    int i = blockIdx.x * blockDim.x + threadIdx.x;
    if (i < NN) g_cur[i] = 0;
}
__global__ void csr_count(const int* __restrict__ dst) {
    int e = blockIdx.x * blockDim.x + threadIdx.x;
    if (e < EE) atomicAdd(&g_cur[dst[e]], 1);
}
__global__ void csr_scan() {
    __shared__ int sh[1024];
    int t = threadIdx.x;
    int c[4]; int s = 0;
#pragma unroll
    for (int u = 0; u < 4; u++) { c[u] = g_cur[t * 4 + u] + 1; s += c[u]; }
    sh[t] = s;
    __syncthreads();
    for (int o = 1; o < 1024; o <<= 1) {
        int v = (t >= o) ? sh[t - o] : 0;
        __syncthreads();
        sh[t] += v;
        __syncthreads();
    }
    int base = sh[t] - s;
#pragma unroll
    for (int u = 0; u < 4; u++) {
        g_off[t * 4 + u] = base;
        g_cur[t * 4 + u] = base;
        base += c[u];
    }
    if (t == 1023) g_off[NN] = sh[1023];
}
__global__ void csr_scatter(const int* __restrict__ src, const int* __restrict__ dst) {
    int e = blockIdx.x * blockDim.x + threadIdx.x;
    if (e < EE) {
        int p = atomicAdd(&g_cur[dst[e]], 1);
        g_srcs[p] = src[e];
    }
}
__global__ void csr_self() {
    int n = blockIdx.x * blockDim.x + threadIdx.x;
    if (n < NN) {
        int p = atomicAdd(&g_cur[n], 1);
        g_srcs[p] = n;
    }
}

// ---------------- sparse GAT layer, C=128, concat, +bias ----------------
__global__ void spagg_concat(const float* __restrict__ es, const float* __restrict__ ed,
                             const float* __restrict__ h, const float* __restrict__ b,
                             float* __restrict__ out) {
    int dst = blockIdx.x;
    int head = threadIdx.x >> 5;
    int lane = threadIdx.x & 31;
    int beg = g_off[dst], end = g_off[dst + 1];
    float edv = ed[dst * HH + head];

    float m = -INFINITY;
    for (int e = beg + lane; e < end; e += 32)
        m = fmaxf(m, lrelu(es[g_srcs[e] * HH + head] + edv));
    for (int o = 16; o > 0; o >>= 1) m = fmaxf(m, __shfl_xor_sync(0xffffffffu, m, o));

    float den = 0.f;
    for (int e = beg + lane; e < end; e += 32)
        den += __expf(lrelu(es[g_srcs[e] * HH + head] + edv) - m);
    for (int o = 16; o > 0; o >>= 1) den += __shfl_xor_sync(0xffffffffu, den, o);
    float inv = 1.f / (den + 1e-16f);

    float a0 = 0.f, a1 = 0.f, a2 = 0.f, a3 = 0.f;
    for (int e = beg; e < end; e++) {
        int s = g_srcs[e];
        float w = __expf(lrelu(es[s * HH + head] + edv) - m) * inv;
        const float* hp = h + s * D1 + head * C1;
        a0 = fmaf(w, hp[lane], a0);
        a1 = fmaf(w, hp[lane + 32], a1);
        a2 = fmaf(w, hp[lane + 64], a2);
        a3 = fmaf(w, hp[lane + 96], a3);
    }
    float* op = out + dst * D1 + head * C1;
    const float* bp = b + head * C1;
    op[lane]      = a0 + bp[lane];
    op[lane + 32] = a1 + bp[lane + 32];
    op[lane + 64] = a2 + bp[lane + 64];
    op[lane + 96] = a3 + bp[lane + 96];
}

// ---------------- sparse GAT layer, C=16, mean over heads, +bias ----------------
__global__ void spagg_mean(const float* __restrict__ es, const float* __restrict__ ed,
                           const float* __restrict__ h, const float* __restrict__ b,
                           float* __restrict__ out) {
    int dst = blockIdx.x * 4 + (threadIdx.x >> 5);
    int lane = threadIdx.x & 31;
    int beg = g_off[dst], end = g_off[dst + 1];
    float acc = 0.f;
    for (int head = 0; head < HH; head++) {
        float edv = ed[dst * HH + head];
        float m = -INFINITY;
        for (int e = beg + lane; e < end; e += 32)
            m = fmaxf(m, lrelu(es[g_srcs[e] * HH + head] + edv));
        for (int o = 16; o > 0; o >>= 1) m = fmaxf(m, __shfl_xor_sync(0xffffffffu, m, o));
        float den = 0.f;
        for (int e = beg + lane; e < end; e += 32)
            den += __expf(lrelu(es[g_srcs[e] * HH + head] + edv) - m);
        for (int o = 16; o > 0; o >>= 1) den += __shfl_xor_sync(0xffffffffu, den, o);
        float inv = 1.f / (den + 1e-16f);
        for (int e = beg; e < end; e++) {
            int s = g_srcs[e];
            float w = __expf(lrelu(es[s * HH + head] + edv) - m) * inv;
            if (lane < LATD) acc = fmaf(w, h[s * D2 + head * LATD + lane], acc);
        }
    }
    if (lane < LATD) out[dst * LATD + lane] = acc * 0.25f + b[lane];
}

// ---------------- per-head bitonic sort of e_src (descending) + weights ----------------
__global__ void sort_kernel(const float* __restrict__ es) {
    __shared__ float key[NN];
    __shared__ int   idx[NN];
    int head = blockIdx.x;
    int t = threadIdx.x;
    for (int i = t; i < NN; i += 1024) { key[i] = es[i * HH + head]; idx[i] = i; }
    __syncthreads();
    for (int k = 2; k <= NN; k <<= 1) {
        for (int j = k >> 1; j > 0; j >>= 1) {
            for (int i = t; i < NN; i += 1024) {
                int ixj = i ^ j;
                if (ixj > i) {
                    bool up = (i & k) == 0;
                    float ki = key[i], kx = key[ixj];
                    bool sw = up ? (ki < kx) : (ki > kx);
                    if (sw) {
                        key[i] = kx; key[ixj] = ki;
                        int tmp = idx[i]; idx[i] = idx[ixj]; idx[ixj] = tmp;
                    }
                }
            }
            __syncthreads();
        }
    }
    float mb = key[0];
    for (int i = t; i < NN; i += 1024) {
        g_skey[head * NN + i] = key[i];
        g_perm[head * NN + i] = idx[i];
        float d = key[i] - mb;
        g_w1s[head * NN + i] = __expf(d);
        g_w2s[head * NN + i] = __expf(0.2f * d);
    }
    if (t == 0) g_Mb[head] = mb;
}

// ---------------- scalar prefix s1 / suffix s2 of sorted weights ----------------
__global__ void sscan_kernel() {
    int head = blockIdx.x;
    int lane = threadIdx.x;
    const float* w1 = g_w1s + head * NN;
    const float* w2 = g_w2s + head * NN;
    float* o1 = g_s1 + head * (NN + 1);
    float* o2 = g_s2 + head * (NN + 1);
    int base = lane * 128;
    float t1 = 0.f, t2 = 0.f;
    for (int t = 0; t < 128; t++) { t1 += w1[base + t]; t2 += w2[base + t]; }
    float i1 = t1, i2 = t2;
    for (int o = 1; o < 32; o <<= 1) {
        float v1 = __shfl_up_sync(0xffffffffu, i1, o);
        float v2 = __shfl_up_sync(0xffffffffu, i2, o);
        if (lane >= o) { i1 += v1; i2 += v2; }
    }
    float all2 = __shfl_sync(0xffffffffu, i2, 31);
    float off1 = i1 - t1;
    float suf2 = all2 - i2;
    float s = off1;
    for (int t = 0; t < 128; t++) { o1[base + t] = s; s += w1[base + t]; }
    if (lane == 31) o1[NN] = s;
    float a = suf2;
    for (int t = 127; t >= 0; t--) { a += w2[base + t]; o2[base + t] = a; }
    if (lane == 31) o2[NN] = 0.f;
}

// ---------------- parallel vector scans of w*h ----------------
template <int C, int RPB>
__global__ void vgather_kernel(const float* __restrict__ h) {
    int head = blockIdx.x;
    int j = blockIdx.y * RPB + threadIdx.x / C;
    int c = threadIdx.x % C;
    int p = g_perm[head * NN + j];
    float hv = h[(p * HH + head) * C + c];
    g_P1[((long)head * (NN + 1) + j + 1) * C + c] = g_w1s[head * NN + j] * hv;
    g_S2[((long)head * (NN + 1) + j) * C + c]     = g_w2s[head * NN + j] * hv;
}

template <int C>
__global__ void vchunk_kernel() {
    int head = blockIdx.x, ch = blockIdx.y, c = threadIdx.x;
    float* p1 = g_P1 + ((long)head * (NN + 1) + ch * CHL + 1) * C + c;
    float s = 0.f;
#pragma unroll 8
    for (int r = 0; r < CHL; r++) { s += p1[r * C]; p1[r * C] = s; }
    g_T1[(head * NCH + ch) * C + c] = s;
    float* s2 = g_S2 + ((long)head * (NN + 1) + ch * CHL) * C + c;
    s = 0.f;
#pragma unroll 8
    for (int r = CHL - 1; r >= 0; r--) { s += s2[r * C]; s2[r * C] = s; }
    g_T2[(head * NCH + ch) * C + c] = s;
}

template <int C>
__global__ void vofs_kernel() {
    int head = blockIdx.x, c = threadIdx.x;
    float* T1 = g_T1 + head * NCH * C + c;
    float s = 0.f;
#pragma unroll
    for (int ch = 0; ch < NCH; ch++) { float v = T1[ch * C]; T1[ch * C] = s; s += v; }
    float* T2 = g_T2 + head * NCH * C + c;
    s = 0.f;
#pragma unroll
    for (int ch = NCH - 1; ch >= 0; ch--) { float v = T2[ch * C]; T2[ch * C] = s; s += v; }
    g_P1[(long)head * (NN + 1) * C + c] = 0.f;
    g_S2[((long)head * (NN + 1) + NN) * C + c] = 0.f;
}

template <int C>
__global__ void vadd_kernel() {
    int head = blockIdx.x, ch = blockIdx.y;
    long base1 = ((long)head * (NN + 1) + ch * CHL + 1) * C;
    long base2 = ((long)head * (NN + 1) + ch * CHL) * C;
    const float* T1 = g_T1 + (head * NCH + ch) * C;
    const float* T2 = g_T2 + (head * NCH + ch) * C;
    for (int e = threadIdx.x; e < CHL * C; e += blockDim.x) {
        int c = e % C;
        g_P1[base1 + e] += T1[c];
        g_S2[base2 + e] += T2[c];
    }
}

__device__ __forceinline__ int bsearch_gt(const float* sk, float t) {
    int lo = 0, hi = NN;
    while (lo < hi) {
        int mid = (lo + hi) >> 1;
        if (sk[mid] > t) lo = mid + 1; else hi = mid;
    }
    return lo;
}

// ---------------- dense GAT layer, C=128, concat, +bias ----------------
__global__ void dense_concat(const float* __restrict__ ed, const float* __restrict__ b,
                             float* __restrict__ out) {
    int i = blockIdx.x;
    int head = blockIdx.y;
    int c = threadIdx.x;
    float a = ed[i * HH + head];
    int k = bsearch_gt(g_skey + head * NN, -a);
    float am = a + g_Mb[head];
    float A1 = __expf(am), A2 = __expf(0.2f * am);
    float den = A1 * g_s1[head * (NN + 1) + k] + A2 * g_s2[head * (NN + 1) + k];
    long o = ((long)head * (NN + 1) + k) * C1 + c;
    float num = A1 * g_P1[o] + A2 * g_S2[o];
    out[i * D1 + head * C1 + c] = num / den + b[head * C1 + c];
}

// ---------------- dense GAT layer, C=16, mean over heads, +bias ----------------
__global__ void dense_mean(const float* __restrict__ ed, const float* __restrict__ b,
                           float* __restrict__ out) {
    __shared__ float sh[64];
    int i = blockIdx.x;
    int t = threadIdx.x;
    int head = t >> 4;
    int c = t & 15;
    float a = ed[i * HH + head];
    int k = bsearch_gt(g_skey + head * NN, -a);
    float am = a + g_Mb[head];
    float A1 = __expf(am), A2 = __expf(0.2f * am);
    float den = A1 * g_s1[head * (NN + 1) + k] + A2 * g_s2[head * (NN + 1) + k];
    long o = ((long)head * (NN + 1) + k) * LATD + c;
    float num = A1 * g_P1[o] + A2 * g_S2[o];
    sh[t] = num / den;
    __syncthreads();
    if (t < LATD)
        out[i * LATD + t] = 0.25f * (sh[t] + sh[16 + t] + sh[32 + t] + sh[48 + t]) + b[t];
}

// ---------------- launch ----------------
extern "C" void kernel_launch(void* const* d_in, const int* in_sizes, int n_in,
                              void* d_out, int out_size) {
    const float* x   = (const float*)d_in[0];
    const int*   ei  = (const int*)d_in[1];
    const float* W1  = (const float*)d_in[3];
    const float* a1s = (const float*)d_in[4];
    const float* a1d = (const float*)d_in[5];
    const float* b1  = (const float*)d_in[6];
    const float* Wm  = (const float*)d_in[7];
    const float* ams = (const float*)d_in[8];
    const float* amd = (const float*)d_in[9];
    const float* bm  = (const float*)d_in[10];
    const float* Ws  = (const float*)d_in[11];
    const float* ass = (const float*)d_in[12];
    const float* asd = (const float*)d_in[13];
    const float* bs  = (const float*)d_in[14];
    float* out = (float*)d_out;
    float* z1m = out;
    float* z1s = out + NN * LATD;
    float* z2m = out + 2 * NN * LATD;
    float* z2s = out + 3 * NN * LATD;

    const int* src = ei;
    const int* dst = ei + EE;

    float *h1, *x1, *x2, *hs, *es1, *ed1, *es2, *ed2;
    cudaGetSymbolAddress((void**)&h1,  g_h1);
    cudaGetSymbolAddress((void**)&x1,  g_x1);
    cudaGetSymbolAddress((void**)&x2,  g_x2);
    cudaGetSymbolAddress((void**)&hs,  g_hs);
    cudaGetSymbolAddress((void**)&es1, g_es1);
    cudaGetSymbolAddress((void**)&ed1, g_ed1);
    cudaGetSymbolAddress((void**)&es2, g_es2);
    cudaGetSymbolAddress((void**)&ed2, g_ed2);

    cudaFuncSetAttribute(mma_gemm, cudaFuncAttributeMaxDynamicSharedMemorySize, 3 * STG_B);

    // h1 = x @ W1 via HMMA (bf16 hi/lo split)
    convA_kernel<<<1024, 256>>>(x);
    convBt_kernel<<<dim3(KP / 32, D1 / 32), dim3(32, 8)>>>(W1);
    mma_gemm<<<dim3(D1 / 128, NN / 128), 256, 3 * STG_B>>>(h1);
    evals_kernel<C1><<<NN, 128>>>(h1, a1s, a1d, es1, ed1);

    // CSR of (edges + self loops) grouped by dst
    csr_zero<<<16, 256>>>();
    csr_count<<<(EE + 255) / 256, 256>>>(dst);
    csr_scan<<<1, 1024>>>();
    csr_scatter<<<(EE + 255) / 256, 256>>>(src, dst);
    csr_self<<<16, 256>>>();

    // ---- sparse branch ----
    spagg_concat<<<NN, 128>>>(es1, ed1, h1, b1, x1);

    gemm64<<<dim3(D2 / 64, NN / 64), 128>>>(x1, Wm, hs, NN, D2, D1);
    evals_kernel<LATD><<<NN, 128>>>(hs, ams, amd, es2, ed2);
    spagg_mean<<<NN / 4, 128>>>(es2, ed2, hs, bm, z1m);

    gemm64<<<dim3(D2 / 64, NN / 64), 128>>>(x1, Ws, hs, NN, D2, D1);
    evals_kernel<LATD><<<NN, 128>>>(hs, ass, asd, es2, ed2);
    spagg_mean<<<NN / 4, 128>>>(es2, ed2, hs, bs, z1s);

    // ---- dense branch (rank-1 softmax: sort + parallel prefix/suffix scans) ----
    sort_kernel<<<HH, 1024>>>(es1);
    sscan_kernel<<<HH, 32>>>();
    vgather_kernel<C1, 2><<<dim3(HH, NN / 2), 256>>>(h1);
    vchunk_kernel<C1><<<dim3(HH, NCH), C1>>>();
    vofs_kernel<C1><<<HH, C1>>>();
    vadd_kernel<C1><<<dim3(HH, NCH), 256>>>();
    dense_concat<<<dim3(NN, HH), C1>>>(ed1, b1, x2);

    gemm64<<<dim3(D2 / 64, NN / 64), 128>>>(x2, Wm, hs, NN, D2, D1);
    evals_kernel<LATD><<<NN, 128>>>(hs, ams, amd, es2, ed2);
    sort_kernel<<<HH, 1024>>>(es2);
    sscan_kernel<<<HH, 32>>>();
    vgather_kernel<LATD, 16><<<dim3(HH, NN / 16), 256>>>(hs);
    vchunk_kernel<LATD><<<dim3(HH, NCH), LATD>>>();
    vofs_kernel<LATD><<<HH, LATD>>>();
    vadd_kernel<LATD><<<dim3(HH, NCH), 256>>>();
    dense_mean<<<NN, 64>>>(ed2, bm, z2m);

    gemm64<<<dim3(D2 / 64, NN / 64), 128>>>(x2, Ws, hs, NN, D2, D1);
    evals_kernel<LATD><<<NN, 128>>>(hs, ass, asd, es2, ed2);
    sort_kernel<<<HH, 1024>>>(es2);
    sscan_kernel<<<HH, 32>>>();
    vgather_kernel<LATD, 16><<<dim3(HH, NN / 16), 256>>>(hs);
    vchunk_kernel<LATD><<<dim3(HH, NCH), LATD>>>();
    vofs_kernel<LATD><<<HH, LATD>>>();
    vadd_kernel<LATD><<<dim3(HH, NCH), 256>>>();
    dense_mean<<<NN, 64>>>(ed2, bs, z2s);
}

// round 6
// speedup vs baseline: 12.5513x; 1.6411x over previous
#include <cuda_runtime.h>
#include <cuda_bf16.h>
#include <math.h>
#include <stdint.h>

#define NN   4096
#define EE   131072
#define INF_ 3000
#define HH   4
#define C1   128
#define D1   512   // H*C1
#define LATD 16
#define D2   64    // H*LATD
#define ETOT (EE + NN)
#define NCH  32    // scan chunks
#define CHL  128   // chunk length (NN/NCH)
#define KP   3008  // padded K for MMA (94*32)
#define KST  32    // K per pipeline stage
#define NSTG (KP / KST)
#define ROWP 40    // padded smem row length in bf16 (32 + 8)
#define TILE_B (128 * ROWP * 2)
#define STG_B  (4 * TILE_B)
#define NSLOT 8    // sort slots (2 halves x 4 heads)

// ---------------- scratch (static device globals; no allocation) ----------------
__device__ float g_h1[NN * D1];
__device__ float g_x1[NN * D1];
__device__ float g_x2[NN * D1];
__device__ float g_hs2a[NN * 128];
__device__ float g_hs2b[NN * 128];
__device__ float g_Wc[D1 * 128];
__device__ float g_es1[NN * HH];
__device__ float g_ed1[NN * HH];
__device__ float g_es2am[NN * HH];
__device__ float g_ed2am[NN * HH];
__device__ float g_es2as[NN * HH];
__device__ float g_ed2as[NN * HH];
__device__ float g_es2bm[NN * HH];
__device__ float g_ed2bm[NN * HH];
__device__ float g_es2bs[NN * HH];
__device__ float g_ed2bs[NN * HH];
__device__ int   g_off[NN + 1];
__device__ int   g_cur[NN];
__device__ int   g_srcs[ETOT];
__device__ float g_skey[NSLOT * NN];
__device__ int   g_perm[NSLOT * NN];
__device__ float g_w1s[NSLOT * NN];
__device__ float g_w2s[NSLOT * NN];
__device__ float g_Mb[NSLOT];
__device__ float g_s1[NSLOT * (NN + 1)];
__device__ float g_s2[NSLOT * (NN + 1)];
__device__ float g_P1[HH * (NN + 1) * C1];
__device__ float g_S2[HH * (NN + 1) * C1];
__device__ float g_T1[HH * NCH * C1];
__device__ float g_T2[HH * NCH * C1];
// bf16 hi/lo split operands for HMMA GEMM
__device__ __align__(256) __nv_bfloat16 g_Ahi[(long)NN * KP];
__device__ __align__(256) __nv_bfloat16 g_Alo[(long)NN * KP];
__device__ __align__(256) __nv_bfloat16 g_Bhi[(long)D1 * KP];
__device__ __align__(256) __nv_bfloat16 g_Blo[(long)D1 * KP];

__device__ __forceinline__ float lrelu(float v) { return v > 0.f ? v : 0.2f * v; }

// ---------------- PTX helpers ----------------
__device__ __forceinline__ uint32_t smem_u32(const void* p) {
    return (uint32_t)__cvta_generic_to_shared(p);
}
__device__ __forceinline__ void cp16(uint32_t s, const void* g) {
    asm volatile("cp.async.cg.shared.global [%0], [%1], 16;\n" :: "r"(s), "l"(g));
}
__device__ __forceinline__ void cp_commit() {
    asm volatile("cp.async.commit_group;\n" ::: "memory");
}
template <int W>
__device__ __forceinline__ void cp_wait() {
    asm volatile("cp.async.wait_group %0;\n" :: "n"(W) : "memory");
}

__device__ __forceinline__ void mma_bf16(float& d0, float& d1, float& d2, float& d3,
                                         uint32_t a0, uint32_t a1, uint32_t a2, uint32_t a3,
                                         uint32_t b0, uint32_t b1) {
    asm volatile(
        "mma.sync.aligned.m16n8k16.row.col.f32.bf16.bf16.f32 "
        "{%0,%1,%2,%3}, {%4,%5,%6,%7}, {%8,%9}, {%0,%1,%2,%3};"
        : "+f"(d0), "+f"(d1), "+f"(d2), "+f"(d3)
        : "r"(a0), "r"(a1), "r"(a2), "r"(a3), "r"(b0), "r"(b1));
}

// ---------------- fp32 -> bf16 hi/lo conversion of x ----------------
struct __align__(16) bf8 { __nv_bfloat16 v[8]; };
__global__ void convA_kernel(const float* __restrict__ x) {
    const long nch = (long)NN * (KP / 8);
    for (long id = (long)blockIdx.x * blockDim.x + threadIdx.x; id < nch;
         id += (long)gridDim.x * blockDim.x) {
        long row = id / (KP / 8);
        int c = (int)(id % (KP / 8));
        bf8 hi, lo;
        if (c < INF_ / 8) {
            const float* xp = x + row * INF_ + c * 8;
#pragma unroll
            for (int j = 0; j < 8; j++) {
                float v = xp[j];
                __nv_bfloat16 h = __float2bfloat16(v);
                hi.v[j] = h;
                lo.v[j] = __float2bfloat16(v - __bfloat162float(h));
            }
        } else {
#pragma unroll
            for (int j = 0; j < 8; j++) { hi.v[j] = __float2bfloat16(0.f); lo.v[j] = hi.v[j]; }
        }
        *reinterpret_cast<bf8*>(&g_Ahi[row * KP + c * 8]) = hi;
        *reinterpret_cast<bf8*>(&g_Alo[row * KP + c * 8]) = lo;
    }
}

__global__ void convBt_kernel(const float* __restrict__ W) {
    __shared__ float t[32][33];
    int kb = blockIdx.x * 32, nb = blockIdx.y * 32;
    int tx = threadIdx.x, ty = threadIdx.y;
#pragma unroll
    for (int r = 0; r < 32; r += 8) {
        int k = kb + ty + r, n = nb + tx;
        t[ty + r][tx] = (k < INF_) ? W[(long)k * D1 + n] : 0.f;
    }
    __syncthreads();
#pragma unroll
    for (int r = 0; r < 32; r += 8) {
        int n = nb + ty + r, k = kb + tx;
        float v = t[tx][ty + r];
        __nv_bfloat16 h = __float2bfloat16(v);
        g_Bhi[(long)n * KP + k] = h;
        g_Blo[(long)n * KP + k] = __float2bfloat16(v - __bfloat162float(h));
    }
}

// Wc = [Wm | Ws] : [512][128]
__global__ void buildWc(const float* __restrict__ Wm, const float* __restrict__ Ws) {
    int i = blockIdx.x * 256 + threadIdx.x;
    if (i < D1 * 64) {
        int k = i >> 6, n = i & 63;
        g_Wc[k * 128 + n] = Wm[i];
        g_Wc[k * 128 + 64 + n] = Ws[i];
    }
}

// ---------------- HMMA GEMM (h1 = x @ W1) ----------------
__global__ void __launch_bounds__(256) mma_gemm(float* __restrict__ Cout) {
    extern __shared__ char smem[];
    const int tid = threadIdx.x;
    const int wid = tid >> 5, lane = tid & 31;
    const int g = lane >> 2, tig = lane & 3;
    const int wm = (wid & 1) * 64;
    const int wn = (wid >> 1) * 32;
    const int bn = blockIdx.x * 128;
    const int bm = blockIdx.y * 128;
    uint32_t sb = smem_u32(smem);

    float acc[4][4][4];
#pragma unroll
    for (int i = 0; i < 4; i++)
#pragma unroll
        for (int j = 0; j < 4; j++)
#pragma unroll
            for (int q = 0; q < 4; q++) acc[i][j][q] = 0.f;

    auto load_stage = [&](int s) {
        uint32_t base = sb + (uint32_t)(s % 3) * STG_B;
        long gk = (long)s * KST;
#pragma unroll
        for (int t = 0; t < 8; t++) {
            int id = tid + t * 256;
            int mat = id >> 9;
            int r = (id >> 2) & 127;
            int c16 = id & 3;
            uint32_t so = base + (uint32_t)mat * TILE_B + (uint32_t)(r * 80 + c16 * 16);
            const __nv_bfloat16* gp;
            if (mat == 0)      gp = &g_Ahi[(long)(bm + r) * KP + gk + c16 * 8];
            else if (mat == 1) gp = &g_Alo[(long)(bm + r) * KP + gk + c16 * 8];
            else if (mat == 2) gp = &g_Bhi[(long)(bn + r) * KP + gk + c16 * 8];
            else               gp = &g_Blo[(long)(bn + r) * KP + gk + c16 * 8];
            cp16(so, gp);
        }
        cp_commit();
    };

    load_stage(0);
    load_stage(1);

    for (int s = 0; s < NSTG; s++) {
        if (s + 1 < NSTG) cp_wait<1>(); else cp_wait<0>();
        __syncthreads();
        const char* stg = smem + (s % 3) * STG_B;
        const uint32_t* Ah = (const uint32_t*)(stg);
        const uint32_t* Al = (const uint32_t*)(stg + TILE_B);
        const uint32_t* Bh = (const uint32_t*)(stg + 2 * TILE_B);
        const uint32_t* Bl = (const uint32_t*)(stg + 3 * TILE_B);
#pragma unroll
        for (int ks = 0; ks < 2; ks++) {
            int kh = ks * 8;
            uint32_t ah[4][4], al[4][4], bh[4][2], bl[4][2];
#pragma unroll
            for (int tm = 0; tm < 4; tm++) {
                int r = wm + tm * 16 + g;
                ah[tm][0] = Ah[r * 20 + kh + tig];
                ah[tm][1] = Ah[(r + 8) * 20 + kh + tig];
                ah[tm][2] = Ah[r * 20 + kh + 4 + tig];
                ah[tm][3] = Ah[(r + 8) * 20 + kh + 4 + tig];
                al[tm][0] = Al[r * 20 + kh + tig];
                al[tm][1] = Al[(r + 8) * 20 + kh + tig];
                al[tm][2] = Al[r * 20 + kh + 4 + tig];
                al[tm][3] = Al[(r + 8) * 20 + kh + 4 + tig];
            }
#pragma unroll
            for (int tn = 0; tn < 4; tn++) {
                int n = wn + tn * 8 + g;
                bh[tn][0] = Bh[n * 20 + kh + tig];
                bh[tn][1] = Bh[n * 20 + kh + 4 + tig];
                bl[tn][0] = Bl[n * 20 + kh + tig];
                bl[tn][1] = Bl[n * 20 + kh + 4 + tig];
            }
#pragma unroll
            for (int tm = 0; tm < 4; tm++)
#pragma unroll
                for (int tn = 0; tn < 4; tn++) {
                    float* d = acc[tm][tn];
                    mma_bf16(d[0], d[1], d[2], d[3],
                             ah[tm][0], ah[tm][1], ah[tm][2], ah[tm][3],
                             bh[tn][0], bh[tn][1]);
                    mma_bf16(d[0], d[1], d[2], d[3],
                             ah[tm][0], ah[tm][1], ah[tm][2], ah[tm][3],
                             bl[tn][0], bl[tn][1]);
                    mma_bf16(d[0], d[1], d[2], d[3],
                             al[tm][0], al[tm][1], al[tm][2], al[tm][3],
                             bh[tn][0], bh[tn][1]);
                }
        }
        __syncthreads();
        if (s + 2 < NSTG) load_stage(s + 2);
    }

#pragma unroll
    for (int tm = 0; tm < 4; tm++)
#pragma unroll
        for (int tn = 0; tn < 4; tn++) {
            int r0 = bm + wm + tm * 16 + g;
            int c0 = bn + wn + tn * 8 + 2 * tig;
            float* d = acc[tm][tn];
            *reinterpret_cast<float2*>(&Cout[(long)r0 * D1 + c0]) = make_float2(d[0], d[1]);
            *reinterpret_cast<float2*>(&Cout[(long)(r0 + 8) * D1 + c0]) = make_float2(d[2], d[3]);
        }
}

// ---------------- fp32 GEMM 64x64 tile, double buffered ----------------
__global__ void __launch_bounds__(128) gemm64(const float* __restrict__ A,
                                              const float* __restrict__ B,
                                              float* __restrict__ C, int M, int Nn, int K) {
    __shared__ float As[2][64][8];
    __shared__ float Bs[2][8][64];
    const int tid = threadIdx.x;
    const int bm = blockIdx.y * 64;
    const int bn = blockIdx.x * 64;
    const int arow = tid >> 1, acol = (tid & 1) * 4;
    const int brow = tid >> 4, bcol = (tid & 15) * 4;
    const int ty = (tid >> 4) * 8;
    const int tx = (tid & 15) * 4;

    const float* Ag = A + (long)(bm + arow) * K + acol;
    const float* Bg = B + (long)brow * Nn + bn + bcol;
    uint32_t aS[2] = { smem_u32(&As[0][arow][acol]), smem_u32(&As[1][arow][acol]) };
    uint32_t bS[2] = { smem_u32(&Bs[0][brow][bcol]), smem_u32(&Bs[1][brow][bcol]) };

    float acc[8][4];
#pragma unroll
    for (int i = 0; i < 8; i++)
#pragma unroll
        for (int j = 0; j < 4; j++) acc[i][j] = 0.f;

    cp16(aS[0], Ag);
    cp16(bS[0], Bg);
    cp_commit();

    int stage = 0;
    for (int k0 = 0; k0 < K; k0 += 8) {
        if (k0 + 8 < K) {
            cp16(aS[stage ^ 1], Ag + (k0 + 8));
            cp16(bS[stage ^ 1], Bg + (long)(k0 + 8) * Nn);
            cp_commit();
            cp_wait<1>();
        } else {
            cp_wait<0>();
        }
        __syncthreads();
#pragma unroll
        for (int kk = 0; kk < 8; kk++) {
            float4 b0 = *reinterpret_cast<const float4*>(&Bs[stage][kk][tx]);
            float ra[8];
#pragma unroll
            for (int i = 0; i < 8; i++) ra[i] = As[stage][ty + i][kk];
#pragma unroll
            for (int i = 0; i < 8; i++) {
                acc[i][0] = fmaf(ra[i], b0.x, acc[i][0]);
                acc[i][1] = fmaf(ra[i], b0.y, acc[i][1]);
                acc[i][2] = fmaf(ra[i], b0.z, acc[i][2]);
                acc[i][3] = fmaf(ra[i], b0.w, acc[i][3]);
            }
        }
        __syncthreads();
        stage ^= 1;
    }
#pragma unroll
    for (int i = 0; i < 8; i++) {
        float* cp = C + (long)(bm + ty + i) * Nn + bn + tx;
        *reinterpret_cast<float4*>(cp) = make_float4(acc[i][0], acc[i][1], acc[i][2], acc[i][3]);
    }
}

// ---------------- e_src / e_dst, layer 1 (C=128) ----------------
template <int C>
__global__ void evals_kernel(const float* __restrict__ h, const float* __restrict__ asrc,
                             const float* __restrict__ adst, float* __restrict__ es,
                             float* __restrict__ ed) {
    int g = blockIdx.x * 4 + (threadIdx.x >> 5);
    int lane = threadIdx.x & 31;
    int n = g >> 2;
    int head = g & 3;
    float s1 = 0.f, s2 = 0.f;
    for (int c = lane; c < C; c += 32) {
        float hv = h[(n * HH + head) * C + c];
        s1 = fmaf(hv, asrc[head * C + c], s1);
        s2 = fmaf(hv, adst[head * C + c], s2);
    }
    for (int o = 16; o > 0; o >>= 1) {
        s1 += __shfl_xor_sync(0xffffffffu, s1, o);
        s2 += __shfl_xor_sync(0xffffffffu, s2, o);
    }
    if (lane == 0) { es[n * HH + head] = s1; ed[n * HH + head] = s2; }
}

// ---------------- e_src / e_dst for both halves of hs2 (C=16) ----------------
__global__ void evals2(const float* __restrict__ hs2,
                       const float* __restrict__ ams, const float* __restrict__ amd,
                       const float* __restrict__ ass, const float* __restrict__ asd,
                       float* __restrict__ esm, float* __restrict__ edm,
                       float* __restrict__ ess, float* __restrict__ eds) {
    int n = blockIdx.x;
    int w = threadIdx.x >> 5;
    int lane = threadIdx.x & 31;
    int half = w >> 2, head = w & 3;
    const float* avs = half ? ass : ams;
    const float* avd = half ? asd : amd;
    float s1 = 0.f, s2 = 0.f;
    if (lane < LATD) {
        float hv = hs2[n * 128 + half * 64 + head * LATD + lane];
        s1 = hv * avs[head * LATD + lane];
        s2 = hv * avd[head * LATD + lane];
    }
    for (int o = 8; o > 0; o >>= 1) {
        s1 += __shfl_xor_sync(0xffffffffu, s1, o);
        s2 += __shfl_xor_sync(0xffffffffu, s2, o);
    }
    if (lane == 0) {
        (half ? ess : esm)[n * HH + head] = s1;
        (half ? eds : edm)[n * HH + head] = s2;
    }
}

// ---------------- CSR build ----------------
__global__ void csr_zero() {
    int i = blockIdx.x * blockDim.x + threadIdx.x;
    if (i < NN) g_cur[i] = 0;
}
__global__ void csr_count(const int* __restrict__ dst) {
    int e = blockIdx.x * blockDim.x + threadIdx.x;
    if (e < EE) atomicAdd(&g_cur[dst[e]], 1);
}
__global__ void csr_scan() {
    __shared__ int sh[1024];
    int t = threadIdx.x;
    int c[4]; int s = 0;
#pragma unroll
    for (int u = 0; u < 4; u++) { c[u] = g_cur[t * 4 + u] + 1; s += c[u]; }
    sh[t] = s;
    __syncthreads();
    for (int o = 1; o < 1024; o <<= 1) {
        int v = (t >= o) ? sh[t - o] : 0;
        __syncthreads();
        sh[t] += v;
        __syncthreads();
    }
    int base = sh[t] - s;
#pragma unroll
    for (int u = 0; u < 4; u++) {
        g_off[t * 4 + u] = base;
        g_cur[t * 4 + u] = base;
        base += c[u];
    }
    if (t == 1023) g_off[NN] = sh[1023];
}
__global__ void csr_scatter(const int* __restrict__ src, const int* __restrict__ dst) {
    int e = blockIdx.x * blockDim.x + threadIdx.x;
    if (e < EE) {
        int p = atomicAdd(&g_cur[dst[e]], 1);
        g_srcs[p] = src[e];
    }
}
__global__ void csr_self() {
    int n = blockIdx.x * blockDim.x + threadIdx.x;
    if (n < NN) {
        int p = atomicAdd(&g_cur[n], 1);
        g_srcs[p] = n;
    }
}

// ---------------- sparse GAT layer, C=128, concat ----------------
__global__ void spagg_concat(const float* __restrict__ es, const float* __restrict__ ed,
                             const float* __restrict__ h, const float* __restrict__ b,
                             float* __restrict__ out) {
    int dst = blockIdx.x;
    int head = threadIdx.x >> 5;
    int lane = threadIdx.x & 31;
    int beg = g_off[dst], end = g_off[dst + 1];
    float edv = ed[dst * HH + head];

    float m = -INFINITY;
    for (int e = beg + lane; e < end; e += 32)
        m = fmaxf(m, lrelu(es[g_srcs[e] * HH + head] + edv));
    for (int o = 16; o > 0; o >>= 1) m = fmaxf(m, __shfl_xor_sync(0xffffffffu, m, o));

    float den = 0.f;
    for (int e = beg + lane; e < end; e += 32)
        den += __expf(lrelu(es[g_srcs[e] * HH + head] + edv) - m);
    for (int o = 16; o > 0; o >>= 1) den += __shfl_xor_sync(0xffffffffu, den, o);
    float inv = 1.f / (den + 1e-16f);

    float a0 = 0.f, a1 = 0.f, a2 = 0.f, a3 = 0.f;
    for (int e = beg; e < end; e++) {
        int s = g_srcs[e];
        float w = __expf(lrelu(es[s * HH + head] + edv) - m) * inv;
        const float* hp = h + s * D1 + head * C1;
        a0 = fmaf(w, hp[lane], a0);
        a1 = fmaf(w, hp[lane + 32], a1);
        a2 = fmaf(w, hp[lane + 64], a2);
        a3 = fmaf(w, hp[lane + 96], a3);
    }
    float* op = out + dst * D1 + head * C1;
    const float* bp = b + head * C1;
    op[lane]      = a0 + bp[lane];
    op[lane + 32] = a1 + bp[lane + 32];
    op[lane + 64] = a2 + bp[lane + 64];
    op[lane + 96] = a3 + bp[lane + 96];
}

// ---------------- sparse GAT mean layers, both halves in one launch ----------------
__global__ void spagg_mean2(const float* __restrict__ esm, const float* __restrict__ edm,
                            const float* __restrict__ ess, const float* __restrict__ eds,
                            const float* __restrict__ hs2,
                            const float* __restrict__ bm, const float* __restrict__ bs,
                            float* __restrict__ zm, float* __restrict__ zs) {
    int half = blockIdx.y;
    const float* es = half ? ess : esm;
    const float* ed = half ? eds : edm;
    const float* b  = half ? bs : bm;
    float* out      = half ? zs : zm;
    int dst = blockIdx.x * 4 + (threadIdx.x >> 5);
    int lane = threadIdx.x & 31;
    int beg = g_off[dst], end = g_off[dst + 1];
    float acc = 0.f;
    for (int head = 0; head < HH; head++) {
        float edv = ed[dst * HH + head];
        float m = -INFINITY;
        for (int e = beg + lane; e < end; e += 32)
            m = fmaxf(m, lrelu(es[g_srcs[e] * HH + head] + edv));
        for (int o = 16; o > 0; o >>= 1) m = fmaxf(m, __shfl_xor_sync(0xffffffffu, m, o));
        float den = 0.f;
        for (int e = beg + lane; e < end; e += 32)
            den += __expf(lrelu(es[g_srcs[e] * HH + head] + edv) - m);
        for (int o = 16; o > 0; o >>= 1) den += __shfl_xor_sync(0xffffffffu, den, o);
        float inv = 1.f / (den + 1e-16f);
        for (int e = beg; e < end; e++) {
            int s = g_srcs[e];
            float w = __expf(lrelu(es[s * HH + head] + edv) - m) * inv;
            if (lane < LATD) acc = fmaf(w, hs2[s * 128 + half * 64 + head * LATD + lane], acc);
        }
    }
    if (lane < LATD) out[dst * LATD + lane] = acc * 0.25f + b[lane];
}

// ---------------- fused sort + weights + scalar scans ----------------
__global__ void __launch_bounds__(1024) sortF(const float* __restrict__ esA,
                                              const float* __restrict__ esB) {
    __shared__ float key[NN];
    __shared__ int   idx[NN];
    __shared__ float red[1024];
    int slot = blockIdx.x;
    int t = threadIdx.x;
    const float* es = (slot < 4) ? esA : esB;
    int head = slot & 3;
    for (int i = t; i < NN; i += 1024) { key[i] = es[i * HH + head]; idx[i] = i; }
    __syncthreads();
    for (int k = 2; k <= NN; k <<= 1) {
        for (int j = k >> 1; j > 0; j >>= 1) {
            for (int i = t; i < NN; i += 1024) {
                int ixj = i ^ j;
                if (ixj > i) {
                    bool up = (i & k) == 0;
                    float ki = key[i], kx = key[ixj];
                    bool sw = up ? (ki < kx) : (ki > kx);
                    if (sw) {
                        key[i] = kx; key[ixj] = ki;
                        int tmp = idx[i]; idx[i] = idx[ixj]; idx[ixj] = tmp;
                    }
                }
            }
            __syncthreads();
        }
    }
    float mb = key[0];
    int base = t * 4;
    float w1v[4], w2v[4];
    float loc1 = 0.f, loc2 = 0.f;
#pragma unroll
    for (int u = 0; u < 4; u++) {
        int i = base + u;
        float kv = key[i];
        g_skey[slot * NN + i] = kv;
        g_perm[slot * NN + i] = idx[i];
        float d = kv - mb;
        w1v[u] = __expf(d);
        w2v[u] = __expf(0.2f * d);
        g_w1s[slot * NN + i] = w1v[u];
        g_w2s[slot * NN + i] = w2v[u];
        loc1 += w1v[u];
        loc2 += w2v[u];
    }
    red[t] = loc1;
    __syncthreads();
    for (int o = 1; o < 1024; o <<= 1) {
        float v = (t >= o) ? red[t - o] : 0.f;
        __syncthreads();
        red[t] += v;
        __syncthreads();
    }
    float incl1 = red[t];
    float tot1 = red[1023];
    __syncthreads();
    red[t] = loc2;
    __syncthreads();
    for (int o = 1; o < 1024; o <<= 1) {
        float v = (t >= o) ? red[t - o] : 0.f;
        __syncthreads();
        red[t] += v;
        __syncthreads();
    }
    float incl2 = red[t];
    float tot2 = red[1023];
    float s = incl1 - loc1;
#pragma unroll
    for (int u = 0; u < 4; u++) { g_s1[slot * (NN + 1) + base + u] = s; s += w1v[u]; }
    if (t == 1023) g_s1[slot * (NN + 1) + NN] = tot1;
    float a2 = tot2 - incl2;
#pragma unroll
    for (int u = 3; u >= 0; u--) { a2 += w2v[u]; g_s2[slot * (NN + 1) + base + u] = a2; }
    if (t == 0) { g_s2[slot * (NN + 1) + NN] = 0.f; g_Mb[slot] = mb; }
}

// ---------------- parallel vector scans of w*h ----------------
template <int C, int RPB>
__global__ void vgather_kernel(const float* __restrict__ h) {
    int head = blockIdx.x;
    int j = blockIdx.y * RPB + threadIdx.x / C;
    int c = threadIdx.x % C;
    int p = g_perm[head * NN + j];
    float hv = h[(p * HH + head) * C + c];
    g_P1[((long)head * (NN + 1) + j + 1) * C + c] = g_w1s[head * NN + j] * hv;
    g_S2[((long)head * (NN + 1) + j) * C + c]     = g_w2s[head * NN + j] * hv;
}

template <int RPB>
__global__ void vgatherL(const float* __restrict__ hs2) {
    int slot = blockIdx.x;
    int half = slot >> 2, head = slot & 3;
    int j = blockIdx.y * RPB + threadIdx.x / LATD;
    int c = threadIdx.x % LATD;
    int p = g_perm[slot * NN + j];
    float hv = hs2[p * 128 + half * 64 + head * LATD + c];
    g_P1[((long)slot * (NN + 1) + j + 1) * LATD + c] = g_w1s[slot * NN + j] * hv;
    g_S2[((long)slot * (NN + 1) + j) * LATD + c]     = g_w2s[slot * NN + j] * hv;
}

template <int C>
__global__ void vchunk_kernel() {
    int slot = blockIdx.x, ch = blockIdx.y, c = threadIdx.x;
    float* p1 = g_P1 + ((long)slot * (NN + 1) + ch * CHL + 1) * C + c;
    float s = 0.f;
#pragma unroll 8
    for (int r = 0; r < CHL; r++) { s += p1[r * C]; p1[r * C] = s; }
    g_T1[(slot * NCH + ch) * C + c] = s;
    float* s2 = g_S2 + ((long)slot * (NN + 1) + ch * CHL) * C + c;
    s = 0.f;
#pragma unroll 8
    for (int r = CHL - 1; r >= 0; r--) { s += s2[r * C]; s2[r * C] = s; }
    g_T2[(slot * NCH + ch) * C + c] = s;
}

template <int C>
__global__ void vofs_kernel() {
    int slot = blockIdx.x, c = threadIdx.x;
    float* T1 = g_T1 + slot * NCH * C + c;
    float s = 0.f;
#pragma unroll
    for (int ch = 0; ch < NCH; ch++) { float v = T1[ch * C]; T1[ch * C] = s; s += v; }
    float* T2 = g_T2 + slot * NCH * C + c;
    s = 0.f;
#pragma unroll
    for (int ch = NCH - 1; ch >= 0; ch--) { float v = T2[ch * C]; T2[ch * C] = s; s += v; }
    g_P1[(long)slot * (NN + 1) * C + c] = 0.f;
    g_S2[((long)slot * (NN + 1) + NN) * C + c] = 0.f;
}

template <int C>
__global__ void vadd_kernel() {
    int slot = blockIdx.x, ch = blockIdx.y;
    long base1 = ((long)slot * (NN + 1) + ch * CHL + 1) * C;
    long base2 = ((long)slot * (NN + 1) + ch * CHL) * C;
    const float* T1 = g_T1 + (slot * NCH + ch) * C;
    const float* T2 = g_T2 + (slot * NCH + ch) * C;
    for (int e = threadIdx.x; e < CHL * C; e += blockDim.x) {
        int c = e % C;
        g_P1[base1 + e] += T1[c];
        g_S2[base2 + e] += T2[c];
    }
}

__device__ __forceinline__ int bsearch_gt(const float* sk, float t) {
    int lo = 0, hi = NN;
    while (lo < hi) {
        int mid = (lo + hi) >> 1;
        if (sk[mid] > t) lo = mid + 1; else hi = mid;
    }
    return lo;
}

// ---------------- dense GAT layer, C=128, concat ----------------
__global__ void dense_concat(const float* __restrict__ ed, const float* __restrict__ b,
                             float* __restrict__ out) {
    int i = blockIdx.x;
    int head = blockIdx.y;
    int c = threadIdx.x;
    float a = ed[i * HH + head];
    int k = bsearch_gt(g_skey + head * NN, -a);
    float am = a + g_Mb[head];
    float A1 = __expf(am), A2 = __expf(0.2f * am);
    float den = A1 * g_s1[head * (NN + 1) + k] + A2 * g_s2[head * (NN + 1) + k];
    long o = ((long)head * (NN + 1) + k) * C1 + c;
    float num = A1 * g_P1[o] + A2 * g_S2[o];
    out[i * D1 + head * C1 + c] = num / den + b[head * C1 + c];
}

// ---------------- dense GAT mean layers, both halves in one launch ----------------
__global__ void dense_mean2(const float* __restrict__ edm, const float* __restrict__ eds,
                            const float* __restrict__ bm, const float* __restrict__ bs,
                            float* __restrict__ zm, float* __restrict__ zs) {
    __shared__ float sh[64];
    int i = blockIdx.x;
    int half = blockIdx.y;
    int t = threadIdx.x;
    int head = t >> 4;
    int c = t & 15;
    int slot = half * 4 + head;
    const float* ed = half ? eds : edm;
    float a = ed[i * HH + head];
    int k = bsearch_gt(g_skey + slot * NN, -a);
    float am = a + g_Mb[slot];
    float A1 = __expf(am), A2 = __expf(0.2f * am);
    float den = A1 * g_s1[slot * (NN + 1) + k] + A2 * g_s2[slot * (NN + 1) + k];
    long o = ((long)slot * (NN + 1) + k) * LATD + c;
    float num = A1 * g_P1[o] + A2 * g_S2[o];
    sh[t] = num / den;
    __syncthreads();
    if (t < LATD) {
        float* out = half ? zs : zm;
        const float* b = half ? bs : bm;
        out[i * LATD + t] = 0.25f * (sh[t] + sh[16 + t] + sh[32 + t] + sh[48 + t]) + b[t];
    }
}

// ---------------- launch ----------------
extern "C" void kernel_launch(void* const* d_in, const int* in_sizes, int n_in,
                              void* d_out, int out_size) {
    const float* x   = (const float*)d_in[0];
    const int*   ei  = (const int*)d_in[1];
    const float* W1  = (const float*)d_in[3];
    const float* a1s = (const float*)d_in[4];
    const float* a1d = (const float*)d_in[5];
    const float* b1  = (const float*)d_in[6];
    const float* Wm  = (const float*)d_in[7];
    const float* ams = (const float*)d_in[8];
    const float* amd = (const float*)d_in[9];
    const float* bm  = (const float*)d_in[10];
    const float* Ws  = (const float*)d_in[11];
    const float* ass = (const float*)d_in[12];
    const float* asd = (const float*)d_in[13];
    const float* bs  = (const float*)d_in[14];
    float* out = (float*)d_out;
    float* z1m = out;
    float* z1s = out + NN * LATD;
    float* z2m = out + 2 * NN * LATD;
    float* z2s = out + 3 * NN * LATD;

    const int* src = ei;
    const int* dst = ei + EE;

    float *h1, *x1, *x2, *hs2a, *hs2b, *Wc;
    float *es1, *ed1;
    float *es2am, *ed2am, *es2as, *ed2as, *es2bm, *ed2bm, *es2bs, *ed2bs;
    cudaGetSymbolAddress((void**)&h1,    g_h1);
    cudaGetSymbolAddress((void**)&x1,    g_x1);
    cudaGetSymbolAddress((void**)&x2,    g_x2);
    cudaGetSymbolAddress((void**)&hs2a,  g_hs2a);
    cudaGetSymbolAddress((void**)&hs2b,  g_hs2b);
    cudaGetSymbolAddress((void**)&Wc,    g_Wc);
    cudaGetSymbolAddress((void**)&es1,   g_es1);
    cudaGetSymbolAddress((void**)&ed1,   g_ed1);
    cudaGetSymbolAddress((void**)&es2am, g_es2am);
    cudaGetSymbolAddress((void**)&ed2am, g_ed2am);
    cudaGetSymbolAddress((void**)&es2as, g_es2as);
    cudaGetSymbolAddress((void**)&ed2as, g_ed2as);
    cudaGetSymbolAddress((void**)&es2bm, g_es2bm);
    cudaGetSymbolAddress((void**)&ed2bm, g_ed2bm);
    cudaGetSymbolAddress((void**)&es2bs, g_es2bs);
    cudaGetSymbolAddress((void**)&ed2bs, g_ed2bs);

    // Streams/events are created ONCE on the first (correctness, non-captured)
    // call and reused by the capture call. This keeps the capture call
    // allocation-free and the post-teardown memory baseline intact. The GPU
    // work issued per call is identical on every call.
    static cudaStream_t sA = nullptr, sB = nullptr;
    static cudaEvent_t ev0 = nullptr, evMain = nullptr, evA = nullptr, evB = nullptr;
    if (sA == nullptr) {
        cudaStreamCreateWithFlags(&sA, cudaStreamNonBlocking);
        cudaStreamCreateWithFlags(&sB, cudaStreamNonBlocking);
        cudaEventCreateWithFlags(&ev0,    cudaEventDisableTiming);
        cudaEventCreateWithFlags(&evMain, cudaEventDisableTiming);
        cudaEventCreateWithFlags(&evA,    cudaEventDisableTiming);
        cudaEventCreateWithFlags(&evB,    cudaEventDisableTiming);
        cudaFuncSetAttribute(mma_gemm, cudaFuncAttributeMaxDynamicSharedMemorySize, 3 * STG_B);
    }

    // fork: CSR build on stream A overlapped with conversions on main
    cudaEventRecord(ev0, 0);
    cudaStreamWaitEvent(sA, ev0, 0);
    csr_zero<<<16, 256, 0, sA>>>();
    csr_count<<<(EE + 255) / 256, 256, 0, sA>>>(dst);
    csr_scan<<<1, 1024, 0, sA>>>();
    csr_scatter<<<(EE + 255) / 256, 256, 0, sA>>>(src, dst);
    csr_self<<<16, 256, 0, sA>>>();

    // main: conversions + big GEMM + layer-1 evals
    convA_kernel<<<1024, 256>>>(x);
    convBt_kernel<<<dim3(KP / 32, D1 / 32), dim3(32, 8)>>>(W1);
    buildWc<<<(D1 * 64 + 255) / 256, 256>>>(Wm, Ws);
    mma_gemm<<<dim3(D1 / 128, NN / 128), 256, 3 * STG_B>>>(h1);
    evals_kernel<C1><<<NN, 128>>>(h1, a1s, a1d, es1, ed1);
    cudaEventRecord(evMain, 0);

    // ---- branch A (sparse) ----
    cudaStreamWaitEvent(sA, evMain, 0);
    spagg_concat<<<NN, 128, 0, sA>>>(es1, ed1, h1, b1, x1);
    gemm64<<<dim3(2, NN / 64), 128, 0, sA>>>(x1, Wc, hs2a, NN, 128, D1);
    evals2<<<NN, 256, 0, sA>>>(hs2a, ams, amd, ass, asd, es2am, ed2am, es2as, ed2as);
    spagg_mean2<<<dim3(NN / 4, 2), 128, 0, sA>>>(es2am, ed2am, es2as, ed2as, hs2a,
                                                 bm, bs, z1m, z1s);
    cudaEventRecord(evA, sA);

    // ---- branch B (dense, rank-1 softmax) ----
    cudaStreamWaitEvent(sB, evMain, 0);
    sortF<<<4, 1024, 0, sB>>>(es1, es1);
    vgather_kernel<C1, 2><<<dim3(HH, NN / 2), 256, 0, sB>>>(h1);
    vchunk_kernel<C1><<<dim3(HH, NCH), C1, 0, sB>>>();
    vofs_kernel<C1><<<HH, C1, 0, sB>>>();
    vadd_kernel<C1><<<dim3(HH, NCH), 256, 0, sB>>>();
    dense_concat<<<dim3(NN, HH), C1, 0, sB>>>(ed1, b1, x2);
    gemm64<<<dim3(2, NN / 64), 128, 0, sB>>>(x2, Wc, hs2b, NN, 128, D1);
    evals2<<<NN, 256, 0, sB>>>(hs2b, ams, amd, ass, asd, es2bm, ed2bm, es2bs, ed2bs);
    sortF<<<NSLOT, 1024, 0, sB>>>(es2bm, es2bs);
    vgatherL<16><<<dim3(NSLOT, NN / 16), 256, 0, sB>>>(hs2b);
    vchunk_kernel<LATD><<<dim3(NSLOT, NCH), LATD, 0, sB>>>();
    vofs_kernel<LATD><<<NSLOT, LATD, 0, sB>>>();
    vadd_kernel<LATD><<<dim3(NSLOT, NCH), 256, 0, sB>>>();
    dense_mean2<<<dim3(NN, 2), 64, 0, sB>>>(ed2bm, ed2bs, bm, bs, z2m, z2s);
    cudaEventRecord(evB, sB);

    // join
    cudaStreamWaitEvent(0, evA, 0);
    cudaStreamWaitEvent(0, evB, 0);
}

// round 7
// speedup vs baseline: 14.8496x; 1.1831x over previous
#include <cuda_runtime.h>
#include <cuda_bf16.h>
#include <math.h>
#include <stdint.h>

#define NN   4096
#define EE   131072
#define INF_ 3000
#define HH   4
#define C1   128
#define D1   512   // H*C1
#define LATD 16
#define D2   64    // H*LATD
#define ETOT (EE + NN)
#define NCH  32    // scan chunks
#define CHL  128   // chunk length (NN/NCH)
#define KP   3008  // padded K for MMA (94*32)
#define KST  32    // K per pipeline stage
#define NSTG (KP / KST)
#define ROWP 40    // padded smem row length in bf16 (32 + 8)
#define TILE_B (128 * ROWP * 2)
#define STG_B  (4 * TILE_B)
#define NSLOT 8    // sort slots (2 halves x 4 heads)
#define SORT_SMEM_U32 (4 * 4096 + 32 * 257 + 1024)
#define SORT_SMEM_B   (SORT_SMEM_U32 * 4)

// ---------------- scratch (static device globals; no allocation) ----------------
__device__ float g_h1[NN * D1];
__device__ float g_x1[NN * D1];
__device__ float g_x2[NN * D1];
__device__ float g_hs2a[NN * 128];
__device__ float g_hs2b[NN * 128];
__device__ float g_Wc[D1 * 128];
__device__ float g_es1[NN * HH];
__device__ float g_ed1[NN * HH];
__device__ float g_es2am[NN * HH];
__device__ float g_ed2am[NN * HH];
__device__ float g_es2as[NN * HH];
__device__ float g_ed2as[NN * HH];
__device__ float g_es2bm[NN * HH];
__device__ float g_ed2bm[NN * HH];
__device__ float g_es2bs[NN * HH];
__device__ float g_ed2bs[NN * HH];
__device__ int   g_off[NN + 1];
__device__ int   g_cur[NN];
__device__ int   g_srcs[ETOT];
__device__ float g_skey[NSLOT * NN];
__device__ int   g_perm[NSLOT * NN];
__device__ float g_w1s[NSLOT * NN];
__device__ float g_w2s[NSLOT * NN];
__device__ float g_Mb[NSLOT];
__device__ float g_s1[NSLOT * (NN + 1)];
__device__ float g_s2[NSLOT * (NN + 1)];
__device__ float g_P1[HH * (NN + 1) * C1];
__device__ float g_S2[HH * (NN + 1) * C1];
__device__ float g_T1[HH * NCH * C1];
__device__ float g_T2[HH * NCH * C1];
// bf16 hi/lo split operands for HMMA GEMM
__device__ __align__(256) __nv_bfloat16 g_Ahi[(long)NN * KP];
__device__ __align__(256) __nv_bfloat16 g_Alo[(long)NN * KP];
__device__ __align__(256) __nv_bfloat16 g_Bhi[(long)D1 * KP];
__device__ __align__(256) __nv_bfloat16 g_Blo[(long)D1 * KP];

__device__ __forceinline__ float lrelu(float v) { return v > 0.f ? v : 0.2f * v; }

// ---------------- PTX helpers ----------------
__device__ __forceinline__ uint32_t smem_u32(const void* p) {
    return (uint32_t)__cvta_generic_to_shared(p);
}
__device__ __forceinline__ void cp16(uint32_t s, const void* g) {
    asm volatile("cp.async.cg.shared.global [%0], [%1], 16;\n" :: "r"(s), "l"(g));
}
__device__ __forceinline__ void cp_commit() {
    asm volatile("cp.async.commit_group;\n" ::: "memory");
}
template <int W>
__device__ __forceinline__ void cp_wait() {
    asm volatile("cp.async.wait_group %0;\n" :: "n"(W) : "memory");
}

__device__ __forceinline__ void mma_bf16(float& d0, float& d1, float& d2, float& d3,
                                         uint32_t a0, uint32_t a1, uint32_t a2, uint32_t a3,
                                         uint32_t b0, uint32_t b1) {
    asm volatile(
        "mma.sync.aligned.m16n8k16.row.col.f32.bf16.bf16.f32 "
        "{%0,%1,%2,%3}, {%4,%5,%6,%7}, {%8,%9}, {%0,%1,%2,%3};"
        : "+f"(d0), "+f"(d1), "+f"(d2), "+f"(d3)
        : "r"(a0), "r"(a1), "r"(a2), "r"(a3), "r"(b0), "r"(b1));
}

// ---------------- fp32 -> bf16 hi/lo conversion of x ----------------
struct __align__(16) bf8 { __nv_bfloat16 v[8]; };
__global__ void convA_kernel(const float* __restrict__ x) {
    const long nch = (long)NN * (KP / 8);
    for (long id = (long)blockIdx.x * blockDim.x + threadIdx.x; id < nch;
         id += (long)gridDim.x * blockDim.x) {
        long row = id / (KP / 8);
        int c = (int)(id % (KP / 8));
        bf8 hi, lo;
        if (c < INF_ / 8) {
            const float* xp = x + row * INF_ + c * 8;
#pragma unroll
            for (int j = 0; j < 8; j++) {
                float v = xp[j];
                __nv_bfloat16 h = __float2bfloat16(v);
                hi.v[j] = h;
                lo.v[j] = __float2bfloat16(v - __bfloat162float(h));
            }
        } else {
#pragma unroll
            for (int j = 0; j < 8; j++) { hi.v[j] = __float2bfloat16(0.f); lo.v[j] = hi.v[j]; }
        }
        *reinterpret_cast<bf8*>(&g_Ahi[row * KP + c * 8]) = hi;
        *reinterpret_cast<bf8*>(&g_Alo[row * KP + c * 8]) = lo;
    }
}

__global__ void convBt_kernel(const float* __restrict__ W) {
    __shared__ float t[32][33];
    int kb = blockIdx.x * 32, nb = blockIdx.y * 32;
    int tx = threadIdx.x, ty = threadIdx.y;
#pragma unroll
    for (int r = 0; r < 32; r += 8) {
        int k = kb + ty + r, n = nb + tx;
        t[ty + r][tx] = (k < INF_) ? W[(long)k * D1 + n] : 0.f;
    }
    __syncthreads();
#pragma unroll
    for (int r = 0; r < 32; r += 8) {
        int n = nb + ty + r, k = kb + tx;
        float v = t[tx][ty + r];
        __nv_bfloat16 h = __float2bfloat16(v);
        g_Bhi[(long)n * KP + k] = h;
        g_Blo[(long)n * KP + k] = __float2bfloat16(v - __bfloat162float(h));
    }
}

// Wc = [Wm | Ws] : [512][128]
__global__ void buildWc(const float* __restrict__ Wm, const float* __restrict__ Ws) {
    int i = blockIdx.x * 256 + threadIdx.x;
    if (i < D1 * 64) {
        int k = i >> 6, n = i & 63;
        g_Wc[k * 128 + n] = Wm[i];
        g_Wc[k * 128 + 64 + n] = Ws[i];
    }
}

// ---------------- HMMA GEMM (h1 = x @ W1) ----------------
__global__ void __launch_bounds__(256) mma_gemm(float* __restrict__ Cout) {
    extern __shared__ char smem[];
    const int tid = threadIdx.x;
    const int wid = tid >> 5, lane = tid & 31;
    const int g = lane >> 2, tig = lane & 3;
    const int wm = (wid & 1) * 64;
    const int wn = (wid >> 1) * 32;
    const int bn = blockIdx.x * 128;
    const int bm = blockIdx.y * 128;
    uint32_t sb = smem_u32(smem);

    float acc[4][4][4];
#pragma unroll
    for (int i = 0; i < 4; i++)
#pragma unroll
        for (int j = 0; j < 4; j++)
#pragma unroll
            for (int q = 0; q < 4; q++) acc[i][j][q] = 0.f;

    auto load_stage = [&](int s) {
        uint32_t base = sb + (uint32_t)(s % 3) * STG_B;
        long gk = (long)s * KST;
#pragma unroll
        for (int t = 0; t < 8; t++) {
            int id = tid + t * 256;
            int mat = id >> 9;
            int r = (id >> 2) & 127;
            int c16 = id & 3;
            uint32_t so = base + (uint32_t)mat * TILE_B + (uint32_t)(r * 80 + c16 * 16);
            const __nv_bfloat16* gp;
            if (mat == 0)      gp = &g_Ahi[(long)(bm + r) * KP + gk + c16 * 8];
            else if (mat == 1) gp = &g_Alo[(long)(bm + r) * KP + gk + c16 * 8];
            else if (mat == 2) gp = &g_Bhi[(long)(bn + r) * KP + gk + c16 * 8];
            else               gp = &g_Blo[(long)(bn + r) * KP + gk + c16 * 8];
            cp16(so, gp);
        }
        cp_commit();
    };

    load_stage(0);
    load_stage(1);

    for (int s = 0; s < NSTG; s++) {
        if (s + 1 < NSTG) cp_wait<1>(); else cp_wait<0>();
        __syncthreads();
        const char* stg = smem + (s % 3) * STG_B;
        const uint32_t* Ah = (const uint32_t*)(stg);
        const uint32_t* Al = (const uint32_t*)(stg + TILE_B);
        const uint32_t* Bh = (const uint32_t*)(stg + 2 * TILE_B);
        const uint32_t* Bl = (const uint32_t*)(stg + 3 * TILE_B);
#pragma unroll
        for (int ks = 0; ks < 2; ks++) {
            int kh = ks * 8;
            uint32_t ah[4][4], al[4][4], bh[4][2], bl[4][2];
#pragma unroll
            for (int tm = 0; tm < 4; tm++) {
                int r = wm + tm * 16 + g;
                ah[tm][0] = Ah[r * 20 + kh + tig];
                ah[tm][1] = Ah[(r + 8) * 20 + kh + tig];
                ah[tm][2] = Ah[r * 20 + kh + 4 + tig];
                ah[tm][3] = Ah[(r + 8) * 20 + kh + 4 + tig];
                al[tm][0] = Al[r * 20 + kh + tig];
                al[tm][1] = Al[(r + 8) * 20 + kh + tig];
                al[tm][2] = Al[r * 20 + kh + 4 + tig];
                al[tm][3] = Al[(r + 8) * 20 + kh + 4 + tig];
            }
#pragma unroll
            for (int tn = 0; tn < 4; tn++) {
                int n = wn + tn * 8 + g;
                bh[tn][0] = Bh[n * 20 + kh + tig];
                bh[tn][1] = Bh[n * 20 + kh + 4 + tig];
                bl[tn][0] = Bl[n * 20 + kh + tig];
                bl[tn][1] = Bl[n * 20 + kh + 4 + tig];
            }
#pragma unroll
            for (int tm = 0; tm < 4; tm++)
#pragma unroll
                for (int tn = 0; tn < 4; tn++) {
                    float* d = acc[tm][tn];
                    mma_bf16(d[0], d[1], d[2], d[3],
                             ah[tm][0], ah[tm][1], ah[tm][2], ah[tm][3],
                             bh[tn][0], bh[tn][1]);
                    mma_bf16(d[0], d[1], d[2], d[3],
                             ah[tm][0], ah[tm][1], ah[tm][2], ah[tm][3],
                             bl[tn][0], bl[tn][1]);
                    mma_bf16(d[0], d[1], d[2], d[3],
                             al[tm][0], al[tm][1], al[tm][2], al[tm][3],
                             bh[tn][0], bh[tn][1]);
                }
        }
        __syncthreads();
        if (s + 2 < NSTG) load_stage(s + 2);
    }

#pragma unroll
    for (int tm = 0; tm < 4; tm++)
#pragma unroll
        for (int tn = 0; tn < 4; tn++) {
            int r0 = bm + wm + tm * 16 + g;
            int c0 = bn + wn + tn * 8 + 2 * tig;
            float* d = acc[tm][tn];
            *reinterpret_cast<float2*>(&Cout[(long)r0 * D1 + c0]) = make_float2(d[0], d[1]);
            *reinterpret_cast<float2*>(&Cout[(long)(r0 + 8) * D1 + c0]) = make_float2(d[2], d[3]);
        }
}

// ---------------- fp32 GEMM 64x64 tile, double buffered ----------------
__global__ void __launch_bounds__(128) gemm64(const float* __restrict__ A,
                                              const float* __restrict__ B,
                                              float* __restrict__ C, int M, int Nn, int K) {
    __shared__ float As[2][64][8];
    __shared__ float Bs[2][8][64];
    const int tid = threadIdx.x;
    const int bm = blockIdx.y * 64;
    const int bn = blockIdx.x * 64;
    const int arow = tid >> 1, acol = (tid & 1) * 4;
    const int brow = tid >> 4, bcol = (tid & 15) * 4;
    const int ty = (tid >> 4) * 8;
    const int tx = (tid & 15) * 4;

    const float* Ag = A + (long)(bm + arow) * K + acol;
    const float* Bg = B + (long)brow * Nn + bn + bcol;
    uint32_t aS[2] = { smem_u32(&As[0][arow][acol]), smem_u32(&As[1][arow][acol]) };
    uint32_t bS[2] = { smem_u32(&Bs[0][brow][bcol]), smem_u32(&Bs[1][brow][bcol]) };

    float acc[8][4];
#pragma unroll
    for (int i = 0; i < 8; i++)
#pragma unroll
        for (int j = 0; j < 4; j++) acc[i][j] = 0.f;

    cp16(aS[0], Ag);
    cp16(bS[0], Bg);
    cp_commit();

    int stage = 0;
    for (int k0 = 0; k0 < K; k0 += 8) {
        if (k0 + 8 < K) {
            cp16(aS[stage ^ 1], Ag + (k0 + 8));
            cp16(bS[stage ^ 1], Bg + (long)(k0 + 8) * Nn);
            cp_commit();
            cp_wait<1>();
        } else {
            cp_wait<0>();
        }
        __syncthreads();
#pragma unroll
        for (int kk = 0; kk < 8; kk++) {
            float4 b0 = *reinterpret_cast<const float4*>(&Bs[stage][kk][tx]);
            float ra[8];
#pragma unroll
            for (int i = 0; i < 8; i++) ra[i] = As[stage][ty + i][kk];
#pragma unroll
            for (int i = 0; i < 8; i++) {
                acc[i][0] = fmaf(ra[i], b0.x, acc[i][0]);
                acc[i][1] = fmaf(ra[i], b0.y, acc[i][1]);
                acc[i][2] = fmaf(ra[i], b0.z, acc[i][2]);
                acc[i][3] = fmaf(ra[i], b0.w, acc[i][3]);
            }
        }
        __syncthreads();
        stage ^= 1;
    }
#pragma unroll
    for (int i = 0; i < 8; i++) {
        float* cp = C + (long)(bm + ty + i) * Nn + bn + tx;
        *reinterpret_cast<float4*>(cp) = make_float4(acc[i][0], acc[i][1], acc[i][2], acc[i][3]);
    }
}

// ---------------- e_src / e_dst, layer 1 (C=128) ----------------
template <int C>
__global__ void evals_kernel(const float* __restrict__ h, const float* __restrict__ asrc,
                             const float* __restrict__ adst, float* __restrict__ es,
                             float* __restrict__ ed) {
    int g = blockIdx.x * 4 + (threadIdx.x >> 5);
    int lane = threadIdx.x & 31;
    int n = g >> 2;
    int head = g & 3;
    float s1 = 0.f, s2 = 0.f;
    for (int c = lane; c < C; c += 32) {
        float hv = h[(n * HH + head) * C + c];
        s1 = fmaf(hv, asrc[head * C + c], s1);
        s2 = fmaf(hv, adst[head * C + c], s2);
    }
    for (int o = 16; o > 0; o >>= 1) {
        s1 += __shfl_xor_sync(0xffffffffu, s1, o);
        s2 += __shfl_xor_sync(0xffffffffu, s2, o);
    }
    if (lane == 0) { es[n * HH + head] = s1; ed[n * HH + head] = s2; }
}

// ---------------- e_src / e_dst for both halves of hs2 (C=16) ----------------
__global__ void evals2(const float* __restrict__ hs2,
                       const float* __restrict__ ams, const float* __restrict__ amd,
                       const float* __restrict__ ass, const float* __restrict__ asd,
                       float* __restrict__ esm, float* __restrict__ edm,
                       float* __restrict__ ess, float* __restrict__ eds) {
    int n = blockIdx.x;
    int w = threadIdx.x >> 5;
    int lane = threadIdx.x & 31;
    int half = w >> 2, head = w & 3;
    const float* avs = half ? ass : ams;
    const float* avd = half ? asd : amd;
    float s1 = 0.f, s2 = 0.f;
    if (lane < LATD) {
        float hv = hs2[n * 128 + half * 64 + head * LATD + lane];
        s1 = hv * avs[head * LATD + lane];
        s2 = hv * avd[head * LATD + lane];
    }
    for (int o = 8; o > 0; o >>= 1) {
        s1 += __shfl_xor_sync(0xffffffffu, s1, o);
        s2 += __shfl_xor_sync(0xffffffffu, s2, o);
    }
    if (lane == 0) {
        (half ? ess : esm)[n * HH + head] = s1;
        (half ? eds : edm)[n * HH + head] = s2;
    }
}

// ---------------- CSR build ----------------
__global__ void csr_zero() {
    int i = blockIdx.x * blockDim.x + threadIdx.x;
    if (i < NN) g_cur[i] = 0;
}
__global__ void csr_count(const int* __restrict__ dst) {
    int e = blockIdx.x * blockDim.x + threadIdx.x;
    if (e < EE) atomicAdd(&g_cur[dst[e]], 1);
}
__global__ void csr_scan() {
    __shared__ int sh[1024];
    int t = threadIdx.x;
    int c[4]; int s = 0;
#pragma unroll
    for (int u = 0; u < 4; u++) { c[u] = g_cur[t * 4 + u] + 1; s += c[u]; }
    sh[t] = s;
    __syncthreads();
    for (int o = 1; o < 1024; o <<= 1) {
        int v = (t >= o) ? sh[t - o] : 0;
        __syncthreads();
        sh[t] += v;
        __syncthreads();
    }
    int base = sh[t] - s;
#pragma unroll
    for (int u = 0; u < 4; u++) {
        g_off[t * 4 + u] = base;
        g_cur[t * 4 + u] = base;
        base += c[u];
    }
    if (t == 1023) g_off[NN] = sh[1023];
}
__global__ void csr_scatter(const int* __restrict__ src, const int* __restrict__ dst) {
    int e = blockIdx.x * blockDim.x + threadIdx.x;
    if (e < EE) {
        int p = atomicAdd(&g_cur[dst[e]], 1);
        g_srcs[p] = src[e];
    }
}
__global__ void csr_self() {
    int n = blockIdx.x * blockDim.x + threadIdx.x;
    if (n < NN) {
        int p = atomicAdd(&g_cur[n], 1);
        g_srcs[p] = n;
    }
}

// ---------------- sparse GAT layer, C=128, concat ----------------
__global__ void spagg_concat(const float* __restrict__ es, const float* __restrict__ ed,
                             const float* __restrict__ h, const float* __restrict__ b,
                             float* __restrict__ out) {
    int dst = blockIdx.x;
    int head = threadIdx.x >> 5;
    int lane = threadIdx.x & 31;
    int beg = g_off[dst], end = g_off[dst + 1];
    float edv = ed[dst * HH + head];

    float m = -INFINITY;
    for (int e = beg + lane; e < end; e += 32)
        m = fmaxf(m, lrelu(es[g_srcs[e] * HH + head] + edv));
    for (int o = 16; o > 0; o >>= 1) m = fmaxf(m, __shfl_xor_sync(0xffffffffu, m, o));

    float den = 0.f;
    for (int e = beg + lane; e < end; e += 32)
        den += __expf(lrelu(es[g_srcs[e] * HH + head] + edv) - m);
    for (int o = 16; o > 0; o >>= 1) den += __shfl_xor_sync(0xffffffffu, den, o);
    float inv = 1.f / (den + 1e-16f);

    float a0 = 0.f, a1 = 0.f, a2 = 0.f, a3 = 0.f;
    for (int e = beg; e < end; e++) {
        int s = g_srcs[e];
        float w = __expf(lrelu(es[s * HH + head] + edv) - m) * inv;
        const float* hp = h + s * D1 + head * C1;
        a0 = fmaf(w, hp[lane], a0);
        a1 = fmaf(w, hp[lane + 32], a1);
        a2 = fmaf(w, hp[lane + 64], a2);
        a3 = fmaf(w, hp[lane + 96], a3);
    }
    float* op = out + dst * D1 + head * C1;
    const float* bp = b + head * C1;
    op[lane]      = a0 + bp[lane];
    op[lane + 32] = a1 + bp[lane + 32];
    op[lane + 64] = a2 + bp[lane + 64];
    op[lane + 96] = a3 + bp[lane + 96];
}

// ---------------- sparse GAT mean layers, both halves in one launch ----------------
__global__ void spagg_mean2(const float* __restrict__ esm, const float* __restrict__ edm,
                            const float* __restrict__ ess, const float* __restrict__ eds,
                            const float* __restrict__ hs2,
                            const float* __restrict__ bm, const float* __restrict__ bs,
                            float* __restrict__ zm, float* __restrict__ zs) {
    int half = blockIdx.y;
    const float* es = half ? ess : esm;
    const float* ed = half ? eds : edm;
    const float* b  = half ? bs : bm;
    float* out      = half ? zs : zm;
    int dst = blockIdx.x * 4 + (threadIdx.x >> 5);
    int lane = threadIdx.x & 31;
    int beg = g_off[dst], end = g_off[dst + 1];
    float acc = 0.f;
    for (int head = 0; head < HH; head++) {
        float edv = ed[dst * HH + head];
        float m = -INFINITY;
        for (int e = beg + lane; e < end; e += 32)
            m = fmaxf(m, lrelu(es[g_srcs[e] * HH + head] + edv));
        for (int o = 16; o > 0; o >>= 1) m = fmaxf(m, __shfl_xor_sync(0xffffffffu, m, o));
        float den = 0.f;
        for (int e = beg + lane; e < end; e += 32)
            den += __expf(lrelu(es[g_srcs[e] * HH + head] + edv) - m);
        for (int o = 16; o > 0; o >>= 1) den += __shfl_xor_sync(0xffffffffu, den, o);
        float inv = 1.f / (den + 1e-16f);
        for (int e = beg; e < end; e++) {
            int s = g_srcs[e];
            float w = __expf(lrelu(es[s * HH + head] + edv) - m) * inv;
            if (lane < LATD) acc = fmaf(w, hs2[s * 128 + half * 64 + head * LATD + lane], acc);
        }
    }
    if (lane < LATD) out[dst * LATD + lane] = acc * 0.25f + b[lane];
}

// ---------------- fused radix sort + weights + scalar scans ----------------
// Sorts es[:,head] descending via 4-pass LSD radix-256 (stable, exact),
// then computes exp weights and prefix/suffix scalar scans — all in one block.
__device__ __forceinline__ float unmap_key(uint32_t kk) {
    uint32_t m = ~kk;
    return __uint_as_float((m & 0x80000000u) ? (m ^ 0x80000000u) : ~m);
}

__global__ void __launch_bounds__(1024) sortF(const float* __restrict__ esA,
                                              const float* __restrict__ esB) {
    extern __shared__ uint32_t sm[];
    uint32_t* KA = sm;                  // 4096
    uint32_t* VA = sm + 4096;           // 4096
    uint32_t* KB = sm + 8192;           // 4096
    uint32_t* VB = sm + 12288;          // 4096
    uint32_t* WH = sm + 16384;          // 32*257 = 8224
    uint32_t* SU = sm + 16384 + 8224;   // 1024
    float*    SF = (float*)SU;

    int slot = blockIdx.x;
    int t = threadIdx.x;
    int w = t >> 5, lane = t & 31;
    const float* es = (slot < 4) ? esA : esB;
    int head = slot & 3;

    // load + map: key = ~orderable(f) so ascending-uint == descending-float
    for (int i = t; i < NN; i += 1024) {
        uint32_t b = __float_as_uint(es[i * HH + head]);
        uint32_t m = (b & 0x80000000u) ? ~b : (b | 0x80000000u);
        KA[i] = ~m;
        VA[i] = (uint32_t)i;
    }
    __syncthreads();

    uint32_t *KI = KA, *VI = VA, *KO = KB, *VO = VB;

#pragma unroll
    for (int pass = 0; pass < 4; pass++) {
        int shift = pass * 8;
        for (int i = t; i < 32 * 257; i += 1024) WH[i] = 0;
        __syncthreads();

        uint32_t k_[4], v_[4], d_[4], lr_[4];
#pragma unroll
        for (int r = 0; r < 4; r++) {
            int idx = w * 128 + r * 32 + lane;
            k_[r] = KI[idx];
            v_[r] = VI[idx];
            d_[r] = (k_[r] >> shift) & 255u;
            unsigned mask = __match_any_sync(0xffffffffu, d_[r]);
            int phys = w * 257 + (int)d_[r];
            uint32_t before = WH[phys];
            __syncwarp();
            lr_[r] = before + (uint32_t)__popc(mask & ((1u << lane) - 1u));
            int leader = __ffs((int)mask) - 1;
            if (lane == leader) WH[phys] = before + (uint32_t)__popc(mask);
            __syncwarp();
        }
        __syncthreads();

        // exclusive scan over logical f = d*32 + w2 (thread t owns f = t*8..t*8+7)
        uint32_t loc[8], sum = 0;
        int dbase = t >> 2;
        int wbase = (t & 3) * 8;
#pragma unroll
        for (int u = 0; u < 8; u++) {
            loc[u] = WH[(wbase + u) * 257 + dbase];
            sum += loc[u];
        }
        SU[t] = sum;
        __syncthreads();
        for (int o = 1; o < 1024; o <<= 1) {
            uint32_t v2 = (t >= o) ? SU[t - o] : 0u;
            __syncthreads();
            SU[t] += v2;
            __syncthreads();
        }
        uint32_t run = SU[t] - sum;
        __syncthreads();
#pragma unroll
        for (int u = 0; u < 8; u++) {
            uint32_t c0 = loc[u];
            WH[(wbase + u) * 257 + dbase] = run;
            run += c0;
        }
        __syncthreads();

        // stable scatter
#pragma unroll
        for (int r = 0; r < 4; r++) {
            uint32_t dest = WH[w * 257 + (int)d_[r]] + lr_[r];
            KO[dest] = k_[r];
            VO[dest] = v_[r];
        }
        __syncthreads();
        uint32_t* tk = KI; KI = KO; KO = tk;
        uint32_t* tv = VI; VI = VO; VO = tv;
    }

    // epilogue: weights + scalar scans (keys descending in KI, payload VI)
    float mb = unmap_key(KI[0]);
    int base = t * 4;
    float w1v[4], w2v[4];
    float loc1 = 0.f, loc2 = 0.f;
#pragma unroll
    for (int u = 0; u < 4; u++) {
        int i = base + u;
        float kv = unmap_key(KI[i]);
        g_skey[slot * NN + i] = kv;
        g_perm[slot * NN + i] = (int)VI[i];
        float d = kv - mb;
        w1v[u] = __expf(d);
        w2v[u] = __expf(0.2f * d);
        g_w1s[slot * NN + i] = w1v[u];
        g_w2s[slot * NN + i] = w2v[u];
        loc1 += w1v[u];
        loc2 += w2v[u];
    }
    SF[t] = loc1;
    __syncthreads();
    for (int o = 1; o < 1024; o <<= 1) {
        float v = (t >= o) ? SF[t - o] : 0.f;
        __syncthreads();
        SF[t] += v;
        __syncthreads();
    }
    float incl1 = SF[t];
    float tot1 = SF[1023];
    __syncthreads();
    SF[t] = loc2;
    __syncthreads();
    for (int o = 1; o < 1024; o <<= 1) {
        float v = (t >= o) ? SF[t - o] : 0.f;
        __syncthreads();
        SF[t] += v;
        __syncthreads();
    }
    float incl2 = SF[t];
    float tot2 = SF[1023];
    float s = incl1 - loc1;
#pragma unroll
    for (int u = 0; u < 4; u++) { g_s1[slot * (NN + 1) + base + u] = s; s += w1v[u]; }
    if (t == 1023) g_s1[slot * (NN + 1) + NN] = tot1;
    float a2 = tot2 - incl2;
#pragma unroll
    for (int u = 3; u >= 0; u--) { a2 += w2v[u]; g_s2[slot * (NN + 1) + base + u] = a2; }
    if (t == 0) { g_s2[slot * (NN + 1) + NN] = 0.f; g_Mb[slot] = mb; }
}

// ---------------- parallel vector scans of w*h ----------------
template <int C, int RPB>
__global__ void vgather_kernel(const float* __restrict__ h) {
    int head = blockIdx.x;
    int j = blockIdx.y * RPB + threadIdx.x / C;
    int c = threadIdx.x % C;
    int p = g_perm[head * NN + j];
    float hv = h[(p * HH + head) * C + c];
    g_P1[((long)head * (NN + 1) + j + 1) * C + c] = g_w1s[head * NN + j] * hv;
    g_S2[((long)head * (NN + 1) + j) * C + c]     = g_w2s[head * NN + j] * hv;
    if (j == 0)      g_P1[(long)head * (NN + 1) * C + c] = 0.f;
    if (j == NN - 1) g_S2[((long)head * (NN + 1) + NN) * C + c] = 0.f;
}

template <int RPB>
__global__ void vgatherL(const float* __restrict__ hs2) {
    int slot = blockIdx.x;
    int half = slot >> 2, head = slot & 3;
    int j = blockIdx.y * RPB + threadIdx.x / LATD;
    int c = threadIdx.x % LATD;
    int p = g_perm[slot * NN + j];
    float hv = hs2[p * 128 + half * 64 + head * LATD + c];
    g_P1[((long)slot * (NN + 1) + j + 1) * LATD + c] = g_w1s[slot * NN + j] * hv;
    g_S2[((long)slot * (NN + 1) + j) * LATD + c]     = g_w2s[slot * NN + j] * hv;
    if (j == 0)      g_P1[(long)slot * (NN + 1) * LATD + c] = 0.f;
    if (j == NN - 1) g_S2[((long)slot * (NN + 1) + NN) * LATD + c] = 0.f;
}

template <int C>
__global__ void vchunk_kernel() {
    int slot = blockIdx.x, ch = blockIdx.y, c = threadIdx.x;
    float* p1 = g_P1 + ((long)slot * (NN + 1) + ch * CHL + 1) * C + c;
    float s = 0.f;
#pragma unroll 8
    for (int r = 0; r < CHL; r++) { s += p1[r * C]; p1[r * C] = s; }
    g_T1[(slot * NCH + ch) * C + c] = s;
    float* s2 = g_S2 + ((long)slot * (NN + 1) + ch * CHL) * C + c;
    s = 0.f;
#pragma unroll 8
    for (int r = CHL - 1; r >= 0; r--) { s += s2[r * C]; s2[r * C] = s; }
    g_T2[(slot * NCH + ch) * C + c] = s;
}

// vadd with fused chunk-offset prefix (replaces vofs + vadd)
template <int C>
__global__ void vadd_kernel() {
    __shared__ float o1s[C], o2s[C];
    int slot = blockIdx.x, ch = blockIdx.y;
    if (threadIdx.x < C) {
        int c = threadIdx.x;
        float s1v = 0.f, s2v = 0.f;
        for (int q = 0; q < ch; q++)        s1v += g_T1[(slot * NCH + q) * C + c];
        for (int q = ch + 1; q < NCH; q++)  s2v += g_T2[(slot * NCH + q) * C + c];
        o1s[c] = s1v;
        o2s[c] = s2v;
    }
    __syncthreads();
    long base1 = ((long)slot * (NN + 1) + ch * CHL + 1) * C;
    long base2 = ((long)slot * (NN + 1) + ch * CHL) * C;
    for (int e = threadIdx.x; e < CHL * C; e += blockDim.x) {
        int c = e % C;
        g_P1[base1 + e] += o1s[c];
        g_S2[base2 + e] += o2s[c];
    }
}

__device__ __forceinline__ int bsearch_gt(const float* sk, float t) {
    int lo = 0, hi = NN;
    while (lo < hi) {
        int mid = (lo + hi) >> 1;
        if (sk[mid] > t) lo = mid + 1; else hi = mid;
    }
    return lo;
}

// ---------------- dense GAT layer, C=128, concat ----------------
__global__ void dense_concat(const float* __restrict__ ed, const float* __restrict__ b,
                             float* __restrict__ out) {
    int i = blockIdx.x;
    int head = blockIdx.y;
    int c = threadIdx.x;
    float a = ed[i * HH + head];
    int k = bsearch_gt(g_skey + head * NN, -a);
    float am = a + g_Mb[head];
    float A1 = __expf(am), A2 = __expf(0.2f * am);
    float den = A1 * g_s1[head * (NN + 1) + k] + A2 * g_s2[head * (NN + 1) + k];
    long o = ((long)head * (NN + 1) + k) * C1 + c;
    float num = A1 * g_P1[o] + A2 * g_S2[o];
    out[i * D1 + head * C1 + c] = num / den + b[head * C1 + c];
}

// ---------------- dense GAT mean layers, both halves in one launch ----------------
__global__ void dense_mean2(const float* __restrict__ edm, const float* __restrict__ eds,
                            const float* __restrict__ bm, const float* __restrict__ bs,
                            float* __restrict__ zm, float* __restrict__ zs) {
    __shared__ float sh[64];
    int i = blockIdx.x;
    int half = blockIdx.y;
    int t = threadIdx.x;
    int head = t >> 4;
    int c = t & 15;
    int slot = half * 4 + head;
    const float* ed = half ? eds : edm;
    float a = ed[i * HH + head];
    int k = bsearch_gt(g_skey + slot * NN, -a);
    float am = a + g_Mb[slot];
    float A1 = __expf(am), A2 = __expf(0.2f * am);
    float den = A1 * g_s1[slot * (NN + 1) + k] + A2 * g_s2[slot * (NN + 1) + k];
    long o = ((long)slot * (NN + 1) + k) * LATD + c;
    float num = A1 * g_P1[o] + A2 * g_S2[o];
    sh[t] = num / den;
    __syncthreads();
    if (t < LATD) {
        float* out = half ? zs : zm;
        const float* b = half ? bs : bm;
        out[i * LATD + t] = 0.25f * (sh[t] + sh[16 + t] + sh[32 + t] + sh[48 + t]) + b[t];
    }
}

// ---------------- launch ----------------
extern "C" void kernel_launch(void* const* d_in, const int* in_sizes, int n_in,
                              void* d_out, int out_size) {
    const float* x   = (const float*)d_in[0];
    const int*   ei  = (const int*)d_in[1];
    const float* W1  = (const float*)d_in[3];
    const float* a1s = (const float*)d_in[4];
    const float* a1d = (const float*)d_in[5];
    const float* b1  = (const float*)d_in[6];
    const float* Wm  = (const float*)d_in[7];
    const float* ams = (const float*)d_in[8];
    const float* amd = (const float*)d_in[9];
    const float* bm  = (const float*)d_in[10];
    const float* Ws  = (const float*)d_in[11];
    const float* ass = (const float*)d_in[12];
    const float* asd = (const float*)d_in[13];
    const float* bs  = (const float*)d_in[14];
    float* out = (float*)d_out;
    float* z1m = out;
    float* z1s = out + NN * LATD;
    float* z2m = out + 2 * NN * LATD;
    float* z2s = out + 3 * NN * LATD;

    const int* src = ei;
    const int* dst = ei + EE;

    float *h1, *x1, *x2, *hs2a, *hs2b, *Wc;
    float *es1, *ed1;
    float *es2am, *ed2am, *es2as, *ed2as, *es2bm, *ed2bm, *es2bs, *ed2bs;
    cudaGetSymbolAddress((void**)&h1,    g_h1);
    cudaGetSymbolAddress((void**)&x1,    g_x1);
    cudaGetSymbolAddress((void**)&x2,    g_x2);
    cudaGetSymbolAddress((void**)&hs2a,  g_hs2a);
    cudaGetSymbolAddress((void**)&hs2b,  g_hs2b);
    cudaGetSymbolAddress((void**)&Wc,    g_Wc);
    cudaGetSymbolAddress((void**)&es1,   g_es1);
    cudaGetSymbolAddress((void**)&ed1,   g_ed1);
    cudaGetSymbolAddress((void**)&es2am, g_es2am);
    cudaGetSymbolAddress((void**)&ed2am, g_ed2am);
    cudaGetSymbolAddress((void**)&es2as, g_es2as);
    cudaGetSymbolAddress((void**)&ed2as, g_ed2as);
    cudaGetSymbolAddress((void**)&es2bm, g_es2bm);
    cudaGetSymbolAddress((void**)&ed2bm, g_ed2bm);
    cudaGetSymbolAddress((void**)&es2bs, g_es2bs);
    cudaGetSymbolAddress((void**)&ed2bs, g_ed2bs);

    // Streams/events created ONCE on the first (non-captured) call; reused by
    // the capture call so the capture itself allocates nothing.
    static cudaStream_t sA = nullptr, sB = nullptr;
    static cudaEvent_t ev0 = nullptr, evMain = nullptr, evA = nullptr, evB = nullptr;
    if (sA == nullptr) {
        cudaStreamCreateWithFlags(&sA, cudaStreamNonBlocking);
        cudaStreamCreateWithFlags(&sB, cudaStreamNonBlocking);
        cudaEventCreateWithFlags(&ev0,    cudaEventDisableTiming);
        cudaEventCreateWithFlags(&evMain, cudaEventDisableTiming);
        cudaEventCreateWithFlags(&evA,    cudaEventDisableTiming);
        cudaEventCreateWithFlags(&evB,    cudaEventDisableTiming);
        cudaFuncSetAttribute(mma_gemm, cudaFuncAttributeMaxDynamicSharedMemorySize, 3 * STG_B);
        cudaFuncSetAttribute(sortF, cudaFuncAttributeMaxDynamicSharedMemorySize, SORT_SMEM_B);
    }

    // fork: CSR build on stream A overlapped with conversions on main
    cudaEventRecord(ev0, 0);
    cudaStreamWaitEvent(sA, ev0, 0);
    csr_zero<<<16, 256, 0, sA>>>();
    csr_count<<<(EE + 255) / 256, 256, 0, sA>>>(dst);
    csr_scan<<<1, 1024, 0, sA>>>();
    csr_scatter<<<(EE + 255) / 256, 256, 0, sA>>>(src, dst);
    csr_self<<<16, 256, 0, sA>>>();

    // main: conversions + big GEMM + layer-1 evals
    convA_kernel<<<1024, 256>>>(x);
    convBt_kernel<<<dim3(KP / 32, D1 / 32), dim3(32, 8)>>>(W1);
    buildWc<<<(D1 * 64 + 255) / 256, 256>>>(Wm, Ws);
    mma_gemm<<<dim3(D1 / 128, NN / 128), 256, 3 * STG_B>>>(h1);
    evals_kernel<C1><<<NN, 128>>>(h1, a1s, a1d, es1, ed1);
    cudaEventRecord(evMain, 0);

    // ---- branch A (sparse) ----
    cudaStreamWaitEvent(sA, evMain, 0);
    spagg_concat<<<NN, 128, 0, sA>>>(es1, ed1, h1, b1, x1);
    gemm64<<<dim3(2, NN / 64), 128, 0, sA>>>(x1, Wc, hs2a, NN, 128, D1);
    evals2<<<NN, 256, 0, sA>>>(hs2a, ams, amd, ass, asd, es2am, ed2am, es2as, ed2as);
    spagg_mean2<<<dim3(NN / 4, 2), 128, 0, sA>>>(es2am, ed2am, es2as, ed2as, hs2a,
                                                 bm, bs, z1m, z1s);
    cudaEventRecord(evA, sA);

    // ---- branch B (dense, rank-1 softmax) ----
    cudaStreamWaitEvent(sB, evMain, 0);
    sortF<<<4, 1024, SORT_SMEM_B, sB>>>(es1, es1);
    vgather_kernel<C1, 2><<<dim3(HH, NN / 2), 256, 0, sB>>>(h1);
    vchunk_kernel<C1><<<dim3(HH, NCH), C1, 0, sB>>>();
    vadd_kernel<C1><<<dim3(HH, NCH), 256, 0, sB>>>();
    dense_concat<<<dim3(NN, HH), C1, 0, sB>>>(ed1, b1, x2);
    gemm64<<<dim3(2, NN / 64), 128, 0, sB>>>(x2, Wc, hs2b, NN, 128, D1);
    evals2<<<NN, 256, 0, sB>>>(hs2b, ams, amd, ass, asd, es2bm, ed2bm, es2bs, ed2bs);
    sortF<<<NSLOT, 1024, SORT_SMEM_B, sB>>>(es2bm, es2bs);
    vgatherL<16><<<dim3(NSLOT, NN / 16), 256, 0, sB>>>(hs2b);
    vchunk_kernel<LATD><<<dim3(NSLOT, NCH), LATD, 0, sB>>>();
    vadd_kernel<LATD><<<dim3(NSLOT, NCH), 256, 0, sB>>>();
    dense_mean2<<<dim3(NN, 2), 64, 0, sB>>>(ed2bm, ed2bs, bm, bs, z2m, z2s);
    cudaEventRecord(evB, sB);

    // join
    cudaStreamWaitEvent(0, evA, 0);
    cudaStreamWaitEvent(0, evB, 0);
}

// round 8
// speedup vs baseline: 15.8754x; 1.0691x over previous
#include <cuda_runtime.h>
#include <cuda_bf16.h>
#include <math.h>
#include <stdint.h>

#define NN   4096
#define EE   131072
#define INF_ 3000
#define HH   4
#define C1   128
#define D1   512   // H*C1
#define LATD 16
#define D2   64    // H*LATD
#define ETOT (EE + NN)
#define NCHC 128   // C1 scan chunks
#define CHLC 32    // C1 chunk length
#define NCHL 256   // LATD scan chunks
#define CHLL 16    // LATD chunk length
#define KP   3008  // padded K for MMA (94*32)
#define KST  32    // K per pipeline stage
#define NSTG (KP / KST)
#define ROWP 40    // padded smem row length in bf16 (32 + 8)
#define TILE_B (128 * ROWP * 2)
#define STG_B  (4 * TILE_B)
#define NSLOT 8    // sort slots (2 halves x 4 heads)
#define SORT_SMEM_U32 (4 * 4096 + 32 * 257)
#define SORT_SMEM_B   (SORT_SMEM_U32 * 4)

// ---------------- scratch (static device globals; no allocation) ----------------
__device__ float g_h1[NN * D1];
__device__ float g_x1[NN * D1];
__device__ float g_x2[NN * D1];
__device__ float g_hs2a[NN * 128];
__device__ float g_hs2b[NN * 128];
__device__ float g_Wc[D1 * 128];
__device__ float g_es1[NN * HH];
__device__ float g_ed1[NN * HH];
__device__ float g_es2am[NN * HH];
__device__ float g_ed2am[NN * HH];
__device__ float g_es2as[NN * HH];
__device__ float g_ed2as[NN * HH];
__device__ float g_es2bm[NN * HH];
__device__ float g_ed2bm[NN * HH];
__device__ float g_es2bs[NN * HH];
__device__ float g_ed2bs[NN * HH];
__device__ int   g_off[NN + 1];
__device__ int   g_cur[NN];
__device__ int   g_srcs[ETOT];
__device__ float g_skey[NSLOT * NN];
__device__ int   g_perm[NSLOT * NN];
__device__ float g_w1s[NSLOT * NN];
__device__ float g_w2s[NSLOT * NN];
__device__ float g_Mb[NSLOT];
__device__ float g_s1[NSLOT * (NN + 1)];
__device__ float g_s2[NSLOT * (NN + 1)];
__device__ float g_P1[HH * (NN + 1) * C1];
__device__ float g_S2[HH * (NN + 1) * C1];
__device__ float g_T1[65536];
__device__ float g_T2[65536];
// bf16 hi/lo split operands for HMMA GEMM
__device__ __align__(256) __nv_bfloat16 g_Ahi[(long)NN * KP];
__device__ __align__(256) __nv_bfloat16 g_Alo[(long)NN * KP];
__device__ __align__(256) __nv_bfloat16 g_Bhi[(long)D1 * KP];
__device__ __align__(256) __nv_bfloat16 g_Blo[(long)D1 * KP];

__device__ __forceinline__ float lrelu(float v) { return v > 0.f ? v : 0.2f * v; }

// ---------------- PTX helpers ----------------
__device__ __forceinline__ uint32_t smem_u32(const void* p) {
    return (uint32_t)__cvta_generic_to_shared(p);
}
__device__ __forceinline__ void cp16(uint32_t s, const void* g) {
    asm volatile("cp.async.cg.shared.global [%0], [%1], 16;\n" :: "r"(s), "l"(g));
}
__device__ __forceinline__ void cp_commit() {
    asm volatile("cp.async.commit_group;\n" ::: "memory");
}
template <int W>
__device__ __forceinline__ void cp_wait() {
    asm volatile("cp.async.wait_group %0;\n" :: "n"(W) : "memory");
}

__device__ __forceinline__ void mma_bf16(float& d0, float& d1, float& d2, float& d3,
                                         uint32_t a0, uint32_t a1, uint32_t a2, uint32_t a3,
                                         uint32_t b0, uint32_t b1) {
    asm volatile(
        "mma.sync.aligned.m16n8k16.row.col.f32.bf16.bf16.f32 "
        "{%0,%1,%2,%3}, {%4,%5,%6,%7}, {%8,%9}, {%0,%1,%2,%3};"
        : "+f"(d0), "+f"(d1), "+f"(d2), "+f"(d3)
        : "r"(a0), "r"(a1), "r"(a2), "r"(a3), "r"(b0), "r"(b1));
}

// ---------------- shuffle-based block scan (NT threads, NT%32==0) ----------------
template <int NT, typename T>
__device__ __forceinline__ T bscan(T v, T& total) {
    __shared__ T ws[NT / 32];
    int t = threadIdx.x, lane = t & 31, w = t >> 5;
    __syncthreads();   // protect ws across consecutive calls
    T x = v;
#pragma unroll
    for (int o = 1; o < 32; o <<= 1) {
        T y = __shfl_up_sync(0xffffffffu, x, o);
        if (lane >= o) x += y;
    }
    if (lane == 31) ws[w] = x;
    __syncthreads();
    if (t < NT / 32) {
        T s = ws[t];
#pragma unroll
        for (int o = 1; o < NT / 32; o <<= 1) {
            T y = __shfl_up_sync((NT / 32 < 32) ? ((1u << (NT / 32)) - 1u) : 0xffffffffu, s, o);
            if (t >= o) s += y;
        }
        ws[t] = s;
    }
    __syncthreads();
    T off = (w == 0) ? (T)0 : ws[w - 1];
    total = ws[NT / 32 - 1];
    return x + off;
}

// ---------------- fp32 -> bf16 hi/lo conversion of x ----------------
struct __align__(16) bf8 { __nv_bfloat16 v[8]; };
__global__ void convA_kernel(const float* __restrict__ x) {
    const long nch = (long)NN * (KP / 8);
    for (long id = (long)blockIdx.x * blockDim.x + threadIdx.x; id < nch;
         id += (long)gridDim.x * blockDim.x) {
        long row = id / (KP / 8);
        int c = (int)(id % (KP / 8));
        bf8 hi, lo;
        if (c < INF_ / 8) {
            const float* xp = x + row * INF_ + c * 8;
#pragma unroll
            for (int j = 0; j < 8; j++) {
                float v = xp[j];
                __nv_bfloat16 h = __float2bfloat16(v);
                hi.v[j] = h;
                lo.v[j] = __float2bfloat16(v - __bfloat162float(h));
            }
        } else {
#pragma unroll
            for (int j = 0; j < 8; j++) { hi.v[j] = __float2bfloat16(0.f); lo.v[j] = hi.v[j]; }
        }
        *reinterpret_cast<bf8*>(&g_Ahi[row * KP + c * 8]) = hi;
        *reinterpret_cast<bf8*>(&g_Alo[row * KP + c * 8]) = lo;
    }
}

__global__ void convBt_kernel(const float* __restrict__ W) {
    __shared__ float t[32][33];
    int kb = blockIdx.x * 32, nb = blockIdx.y * 32;
    int tx = threadIdx.x, ty = threadIdx.y;
#pragma unroll
    for (int r = 0; r < 32; r += 8) {
        int k = kb + ty + r, n = nb + tx;
        t[ty + r][tx] = (k < INF_) ? W[(long)k * D1 + n] : 0.f;
    }
    __syncthreads();
#pragma unroll
    for (int r = 0; r < 32; r += 8) {
        int n = nb + ty + r, k = kb + tx;
        float v = t[tx][ty + r];
        __nv_bfloat16 h = __float2bfloat16(v);
        g_Bhi[(long)n * KP + k] = h;
        g_Blo[(long)n * KP + k] = __float2bfloat16(v - __bfloat162float(h));
    }
}

// Wc = [Wm | Ws] : [512][128]
__global__ void buildWc(const float* __restrict__ Wm, const float* __restrict__ Ws) {
    int i = blockIdx.x * 256 + threadIdx.x;
    if (i < D1 * 64) {
        int k = i >> 6, n = i & 63;
        g_Wc[k * 128 + n] = Wm[i];
        g_Wc[k * 128 + 64 + n] = Ws[i];
    }
}

// ---------------- HMMA GEMM (h1 = x @ W1) ----------------
__global__ void __launch_bounds__(256) mma_gemm(float* __restrict__ Cout) {
    extern __shared__ char smem[];
    const int tid = threadIdx.x;
    const int wid = tid >> 5, lane = tid & 31;
    const int g = lane >> 2, tig = lane & 3;
    const int wm = (wid & 1) * 64;
    const int wn = (wid >> 1) * 32;
    const int bn = blockIdx.x * 128;
    const int bm = blockIdx.y * 128;
    uint32_t sb = smem_u32(smem);

    float acc[4][4][4];
#pragma unroll
    for (int i = 0; i < 4; i++)
#pragma unroll
        for (int j = 0; j < 4; j++)
#pragma unroll
            for (int q = 0; q < 4; q++) acc[i][j][q] = 0.f;

    auto load_stage = [&](int s) {
        uint32_t base = sb + (uint32_t)(s % 3) * STG_B;
        long gk = (long)s * KST;
#pragma unroll
        for (int t = 0; t < 8; t++) {
            int id = tid + t * 256;
            int mat = id >> 9;
            int r = (id >> 2) & 127;
            int c16 = id & 3;
            uint32_t so = base + (uint32_t)mat * TILE_B + (uint32_t)(r * 80 + c16 * 16);
            const __nv_bfloat16* gp;
            if (mat == 0)      gp = &g_Ahi[(long)(bm + r) * KP + gk + c16 * 8];
            else if (mat == 1) gp = &g_Alo[(long)(bm + r) * KP + gk + c16 * 8];
            else if (mat == 2) gp = &g_Bhi[(long)(bn + r) * KP + gk + c16 * 8];
            else               gp = &g_Blo[(long)(bn + r) * KP + gk + c16 * 8];
            cp16(so, gp);
        }
        cp_commit();
    };

    load_stage(0);
    load_stage(1);

    for (int s = 0; s < NSTG; s++) {
        if (s + 1 < NSTG) cp_wait<1>(); else cp_wait<0>();
        __syncthreads();
        const char* stg = smem + (s % 3) * STG_B;
        const uint32_t* Ah = (const uint32_t*)(stg);
        const uint32_t* Al = (const uint32_t*)(stg + TILE_B);
        const uint32_t* Bh = (const uint32_t*)(stg + 2 * TILE_B);
        const uint32_t* Bl = (const uint32_t*)(stg + 3 * TILE_B);
#pragma unroll
        for (int ks = 0; ks < 2; ks++) {
            int kh = ks * 8;
            uint32_t ah[4][4], al[4][4], bh[4][2], bl[4][2];
#pragma unroll
            for (int tm = 0; tm < 4; tm++) {
                int r = wm + tm * 16 + g;
                ah[tm][0] = Ah[r * 20 + kh + tig];
                ah[tm][1] = Ah[(r + 8) * 20 + kh + tig];
                ah[tm][2] = Ah[r * 20 + kh + 4 + tig];
                ah[tm][3] = Ah[(r + 8) * 20 + kh + 4 + tig];
                al[tm][0] = Al[r * 20 + kh + tig];
                al[tm][1] = Al[(r + 8) * 20 + kh + tig];
                al[tm][2] = Al[r * 20 + kh + 4 + tig];
                al[tm][3] = Al[(r + 8) * 20 + kh + 4 + tig];
            }
#pragma unroll
            for (int tn = 0; tn < 4; tn++) {
                int n = wn + tn * 8 + g;
                bh[tn][0] = Bh[n * 20 + kh + tig];
                bh[tn][1] = Bh[n * 20 + kh + 4 + tig];
                bl[tn][0] = Bl[n * 20 + kh + tig];
                bl[tn][1] = Bl[n * 20 + kh + 4 + tig];
            }
#pragma unroll
            for (int tm = 0; tm < 4; tm++)
#pragma unroll
                for (int tn = 0; tn < 4; tn++) {
                    float* d = acc[tm][tn];
                    mma_bf16(d[0], d[1], d[2], d[3],
                             ah[tm][0], ah[tm][1], ah[tm][2], ah[tm][3],
                             bh[tn][0], bh[tn][1]);
                    mma_bf16(d[0], d[1], d[2], d[3],
                             ah[tm][0], ah[tm][1], ah[tm][2], ah[tm][3],
                             bl[tn][0], bl[tn][1]);
                    mma_bf16(d[0], d[1], d[2], d[3],
                             al[tm][0], al[tm][1], al[tm][2], al[tm][3],
                             bh[tn][0], bh[tn][1]);
                }
        }
        __syncthreads();
        if (s + 2 < NSTG) load_stage(s + 2);
    }

#pragma unroll
    for (int tm = 0; tm < 4; tm++)
#pragma unroll
        for (int tn = 0; tn < 4; tn++) {
            int r0 = bm + wm + tm * 16 + g;
            int c0 = bn + wn + tn * 8 + 2 * tig;
            float* d = acc[tm][tn];
            *reinterpret_cast<float2*>(&Cout[(long)r0 * D1 + c0]) = make_float2(d[0], d[1]);
            *reinterpret_cast<float2*>(&Cout[(long)(r0 + 8) * D1 + c0]) = make_float2(d[2], d[3]);
        }
}

// ---------------- fp32 GEMM 64x64 tile, double buffered ----------------
__global__ void __launch_bounds__(128) gemm64(const float* __restrict__ A,
                                              const float* __restrict__ B,
                                              float* __restrict__ C, int M, int Nn, int K) {
    __shared__ float As[2][64][8];
    __shared__ float Bs[2][8][64];
    const int tid = threadIdx.x;
    const int bm = blockIdx.y * 64;
    const int bn = blockIdx.x * 64;
    const int arow = tid >> 1, acol = (tid & 1) * 4;
    const int brow = tid >> 4, bcol = (tid & 15) * 4;
    const int ty = (tid >> 4) * 8;
    const int tx = (tid & 15) * 4;

    const float* Ag = A + (long)(bm + arow) * K + acol;
    const float* Bg = B + (long)brow * Nn + bn + bcol;
    uint32_t aS[2] = { smem_u32(&As[0][arow][acol]), smem_u32(&As[1][arow][acol]) };
    uint32_t bS[2] = { smem_u32(&Bs[0][brow][bcol]), smem_u32(&Bs[1][brow][bcol]) };

    float acc[8][4];
#pragma unroll
    for (int i = 0; i < 8; i++)
#pragma unroll
        for (int j = 0; j < 4; j++) acc[i][j] = 0.f;

    cp16(aS[0], Ag);
    cp16(bS[0], Bg);
    cp_commit();

    int stage = 0;
    for (int k0 = 0; k0 < K; k0 += 8) {
        if (k0 + 8 < K) {
            cp16(aS[stage ^ 1], Ag + (k0 + 8));
            cp16(bS[stage ^ 1], Bg + (long)(k0 + 8) * Nn);
            cp_commit();
            cp_wait<1>();
        } else {
            cp_wait<0>();
        }
        __syncthreads();
#pragma unroll
        for (int kk = 0; kk < 8; kk++) {
            float4 b0 = *reinterpret_cast<const float4*>(&Bs[stage][kk][tx]);
            float ra[8];
#pragma unroll
            for (int i = 0; i < 8; i++) ra[i] = As[stage][ty + i][kk];
#pragma unroll
            for (int i = 0; i < 8; i++) {
                acc[i][0] = fmaf(ra[i], b0.x, acc[i][0]);
                acc[i][1] = fmaf(ra[i], b0.y, acc[i][1]);
                acc[i][2] = fmaf(ra[i], b0.z, acc[i][2]);
                acc[i][3] = fmaf(ra[i], b0.w, acc[i][3]);
            }
        }
        __syncthreads();
        stage ^= 1;
    }
#pragma unroll
    for (int i = 0; i < 8; i++) {
        float* cp = C + (long)(bm + ty + i) * Nn + bn + tx;
        *reinterpret_cast<float4*>(cp) = make_float4(acc[i][0], acc[i][1], acc[i][2], acc[i][3]);
    }
}

// ---------------- e_src / e_dst, layer 1 (C=128) ----------------
template <int C>
__global__ void evals_kernel(const float* __restrict__ h, const float* __restrict__ asrc,
                             const float* __restrict__ adst, float* __restrict__ es,
                             float* __restrict__ ed) {
    int g = blockIdx.x * 4 + (threadIdx.x >> 5);
    int lane = threadIdx.x & 31;
    int n = g >> 2;
    int head = g & 3;
    float s1 = 0.f, s2 = 0.f;
    for (int c = lane; c < C; c += 32) {
        float hv = h[(n * HH + head) * C + c];
        s1 = fmaf(hv, asrc[head * C + c], s1);
        s2 = fmaf(hv, adst[head * C + c], s2);
    }
    for (int o = 16; o > 0; o >>= 1) {
        s1 += __shfl_xor_sync(0xffffffffu, s1, o);
        s2 += __shfl_xor_sync(0xffffffffu, s2, o);
    }
    if (lane == 0) { es[n * HH + head] = s1; ed[n * HH + head] = s2; }
}

// ---------------- e_src / e_dst for both halves of hs2 (C=16) ----------------
__global__ void evals2(const float* __restrict__ hs2,
                       const float* __restrict__ ams, const float* __restrict__ amd,
                       const float* __restrict__ ass, const float* __restrict__ asd,
                       float* __restrict__ esm, float* __restrict__ edm,
                       float* __restrict__ ess, float* __restrict__ eds) {
    int n = blockIdx.x;
    int w = threadIdx.x >> 5;
    int lane = threadIdx.x & 31;
    int half = w >> 2, head = w & 3;
    const float* avs = half ? ass : ams;
    const float* avd = half ? asd : amd;
    float s1 = 0.f, s2 = 0.f;
    if (lane < LATD) {
        float hv = hs2[n * 128 + half * 64 + head * LATD + lane];
        s1 = hv * avs[head * LATD + lane];
        s2 = hv * avd[head * LATD + lane];
    }
    for (int o = 8; o > 0; o >>= 1) {
        s1 += __shfl_xor_sync(0xffffffffu, s1, o);
        s2 += __shfl_xor_sync(0xffffffffu, s2, o);
    }
    if (lane == 0) {
        (half ? ess : esm)[n * HH + head] = s1;
        (half ? eds : edm)[n * HH + head] = s2;
    }
}

// ---------------- CSR build ----------------
__global__ void csr_zero() {
    int i = blockIdx.x * blockDim.x + threadIdx.x;
    if (i < NN) g_cur[i] = 0;
}
__global__ void csr_count(const int* __restrict__ dst) {
    int e = blockIdx.x * blockDim.x + threadIdx.x;
    if (e < EE) atomicAdd(&g_cur[dst[e]], 1);
}
__global__ void csr_scan() {
    __shared__ int sh[1024];
    int t = threadIdx.x;
    int c[4]; int s = 0;
#pragma unroll
    for (int u = 0; u < 4; u++) { c[u] = g_cur[t * 4 + u] + 1; s += c[u]; }
    sh[t] = s;
    __syncthreads();
    for (int o = 1; o < 1024; o <<= 1) {
        int v = (t >= o) ? sh[t - o] : 0;
        __syncthreads();
        sh[t] += v;
        __syncthreads();
    }
    int base = sh[t] - s;
#pragma unroll
    for (int u = 0; u < 4; u++) {
        g_off[t * 4 + u] = base;
        g_cur[t * 4 + u] = base;
        base += c[u];
    }
    if (t == 1023) g_off[NN] = sh[1023];
}
__global__ void csr_scatter(const int* __restrict__ src, const int* __restrict__ dst) {
    int e = blockIdx.x * blockDim.x + threadIdx.x;
    if (e < EE) {
        int p = atomicAdd(&g_cur[dst[e]], 1);
        g_srcs[p] = src[e];
    }
}
__global__ void csr_self() {
    int n = blockIdx.x * blockDim.x + threadIdx.x;
    if (n < NN) {
        int p = atomicAdd(&g_cur[n], 1);
        g_srcs[p] = n;
    }
}

// ---------------- sparse GAT layer, C=128, concat ----------------
__global__ void spagg_concat(const float* __restrict__ es, const float* __restrict__ ed,
                             const float* __restrict__ h, const float* __restrict__ b,
                             float* __restrict__ out) {
    int dst = blockIdx.x;
    int head = threadIdx.x >> 5;
    int lane = threadIdx.x & 31;
    int beg = g_off[dst], end = g_off[dst + 1];
    float edv = ed[dst * HH + head];

    float m = -INFINITY;
    for (int e = beg + lane; e < end; e += 32)
        m = fmaxf(m, lrelu(es[g_srcs[e] * HH + head] + edv));
    for (int o = 16; o > 0; o >>= 1) m = fmaxf(m, __shfl_xor_sync(0xffffffffu, m, o));

    float den = 0.f;
    for (int e = beg + lane; e < end; e += 32)
        den += __expf(lrelu(es[g_srcs[e] * HH + head] + edv) - m);
    for (int o = 16; o > 0; o >>= 1) den += __shfl_xor_sync(0xffffffffu, den, o);
    float inv = 1.f / (den + 1e-16f);

    float a0 = 0.f, a1 = 0.f, a2 = 0.f, a3 = 0.f;
    for (int e = beg; e < end; e++) {
        int s = g_srcs[e];
        float w = __expf(lrelu(es[s * HH + head] + edv) - m) * inv;
        const float* hp = h + s * D1 + head * C1;
        a0 = fmaf(w, hp[lane], a0);
        a1 = fmaf(w, hp[lane + 32], a1);
        a2 = fmaf(w, hp[lane + 64], a2);
        a3 = fmaf(w, hp[lane + 96], a3);
    }
    float* op = out + dst * D1 + head * C1;
    const float* bp = b + head * C1;
    op[lane]      = a0 + bp[lane];
    op[lane + 32] = a1 + bp[lane + 32];
    op[lane + 64] = a2 + bp[lane + 64];
    op[lane + 96] = a3 + bp[lane + 96];
}

// ---------------- sparse GAT mean layers, both halves in one launch ----------------
__global__ void spagg_mean2(const float* __restrict__ esm, const float* __restrict__ edm,
                            const float* __restrict__ ess, const float* __restrict__ eds,
                            const float* __restrict__ hs2,
                            const float* __restrict__ bm, const float* __restrict__ bs,
                            float* __restrict__ zm, float* __restrict__ zs) {
    int half = blockIdx.y;
    const float* es = half ? ess : esm;
    const float* ed = half ? eds : edm;
    const float* b  = half ? bs : bm;
    float* out      = half ? zs : zm;
    int dst = blockIdx.x * 4 + (threadIdx.x >> 5);
    int lane = threadIdx.x & 31;
    int beg = g_off[dst], end = g_off[dst + 1];
    float acc = 0.f;
    for (int head = 0; head < HH; head++) {
        float edv = ed[dst * HH + head];
        float m = -INFINITY;
        for (int e = beg + lane; e < end; e += 32)
            m = fmaxf(m, lrelu(es[g_srcs[e] * HH + head] + edv));
        for (int o = 16; o > 0; o >>= 1) m = fmaxf(m, __shfl_xor_sync(0xffffffffu, m, o));
        float den = 0.f;
        for (int e = beg + lane; e < end; e += 32)
            den += __expf(lrelu(es[g_srcs[e] * HH + head] + edv) - m);
        for (int o = 16; o > 0; o >>= 1) den += __shfl_xor_sync(0xffffffffu, den, o);
        float inv = 1.f / (den + 1e-16f);
        for (int e = beg; e < end; e++) {
            int s = g_srcs[e];
            float w = __expf(lrelu(es[s * HH + head] + edv) - m) * inv;
            if (lane < LATD) acc = fmaf(w, hs2[s * 128 + half * 64 + head * LATD + lane], acc);
        }
    }
    if (lane < LATD) out[dst * LATD + lane] = acc * 0.25f + b[lane];
}

// ---------------- fused radix sort + weights + scalar scans ----------------
__device__ __forceinline__ float unmap_key(uint32_t kk) {
    uint32_t m = ~kk;
    return __uint_as_float((m & 0x80000000u) ? (m ^ 0x80000000u) : ~m);
}

__global__ void __launch_bounds__(1024) sortF(const float* __restrict__ esA,
                                              const float* __restrict__ esB) {
    extern __shared__ uint32_t sm[];
    uint32_t* KA = sm;                  // 4096
    uint32_t* VA = sm + 4096;           // 4096
    uint32_t* KB = sm + 8192;           // 4096
    uint32_t* VB = sm + 12288;          // 4096
    uint32_t* WH = sm + 16384;          // 32*257 = 8224

    int slot = blockIdx.x;
    int t = threadIdx.x;
    int w = t >> 5, lane = t & 31;
    const float* es = (slot < 4) ? esA : esB;
    int head = slot & 3;

    for (int i = t; i < NN; i += 1024) {
        uint32_t b = __float_as_uint(es[i * HH + head]);
        uint32_t m = (b & 0x80000000u) ? ~b : (b | 0x80000000u);
        KA[i] = ~m;
        VA[i] = (uint32_t)i;
    }
    __syncthreads();

    uint32_t *KI = KA, *VI = VA, *KO = KB, *VO = VB;

#pragma unroll
    for (int pass = 0; pass < 4; pass++) {
        int shift = pass * 8;
        for (int i = t; i < 32 * 257; i += 1024) WH[i] = 0;
        __syncthreads();

        uint32_t k_[4], v_[4], d_[4], lr_[4];
#pragma unroll
        for (int r = 0; r < 4; r++) {
            int idx = w * 128 + r * 32 + lane;
            k_[r] = KI[idx];
            v_[r] = VI[idx];
            d_[r] = (k_[r] >> shift) & 255u;
            unsigned mask = __match_any_sync(0xffffffffu, d_[r]);
            int phys = w * 257 + (int)d_[r];
            uint32_t before = WH[phys];
            __syncwarp();
            lr_[r] = before + (uint32_t)__popc(mask & ((1u << lane) - 1u));
            int leader = __ffs((int)mask) - 1;
            if (lane == leader) WH[phys] = before + (uint32_t)__popc(mask);
            __syncwarp();
        }
        __syncthreads();

        // exclusive scan over logical f = d*32 + w2 (thread t owns f = t*8..t*8+7)
        uint32_t loc[8], sum = 0;
        int dbase = t >> 2;
        int wbase = (t & 3) * 8;
#pragma unroll
        for (int u = 0; u < 8; u++) {
            loc[u] = WH[(wbase + u) * 257 + dbase];
            sum += loc[u];
        }
        uint32_t totU;
        uint32_t incl = bscan<1024, uint32_t>(sum, totU);
        uint32_t run = incl - sum;
        __syncthreads();
#pragma unroll
        for (int u = 0; u < 8; u++) {
            uint32_t c0 = loc[u];
            WH[(wbase + u) * 257 + dbase] = run;
            run += c0;
        }
        __syncthreads();

#pragma unroll
        for (int r = 0; r < 4; r++) {
            uint32_t dest = WH[w * 257 + (int)d_[r]] + lr_[r];
            KO[dest] = k_[r];
            VO[dest] = v_[r];
        }
        __syncthreads();
        uint32_t* tk = KI; KI = KO; KO = tk;
        uint32_t* tv = VI; VI = VO; VO = tv;
    }

    // epilogue: weights + scalar scans
    float mb = unmap_key(KI[0]);
    int base = t * 4;
    float w1v[4], w2v[4];
    float loc1 = 0.f, loc2 = 0.f;
#pragma unroll
    for (int u = 0; u < 4; u++) {
        int i = base + u;
        float kv = unmap_key(KI[i]);
        g_skey[slot * NN + i] = kv;
        g_perm[slot * NN + i] = (int)VI[i];
        float d = kv - mb;
        w1v[u] = __expf(d);
        w2v[u] = __expf(0.2f * d);
        g_w1s[slot * NN + i] = w1v[u];
        g_w2s[slot * NN + i] = w2v[u];
        loc1 += w1v[u];
        loc2 += w2v[u];
    }
    float tot1, tot2;
    float incl1 = bscan<1024, float>(loc1, tot1);
    float incl2 = bscan<1024, float>(loc2, tot2);
    float s = incl1 - loc1;
#pragma unroll
    for (int u = 0; u < 4; u++) { g_s1[slot * (NN + 1) + base + u] = s; s += w1v[u]; }
    if (t == 1023) g_s1[slot * (NN + 1) + NN] = tot1;
    float a2 = tot2 - incl2;
#pragma unroll
    for (int u = 3; u >= 0; u--) { a2 += w2v[u]; g_s2[slot * (NN + 1) + base + u] = a2; }
    if (t == 0) { g_s2[slot * (NN + 1) + NN] = 0.f; g_Mb[slot] = mb; }
}

// ---------------- fused gather + chunk-local scans ----------------
// C1 variant: grid (HH, NCHC), block C1. Chunk = 32 rows, hv in registers.
__global__ void __launch_bounds__(C1) vscanC(const float* __restrict__ h) {
    int head = blockIdx.x, ch = blockIdx.y, c = threadIdx.x;
    const int*   perm = g_perm + head * NN + ch * CHLC;
    const float* w1p  = g_w1s + head * NN + ch * CHLC;
    const float* w2p  = g_w2s + head * NN + ch * CHLC;
    long rowbase = (long)head * (NN + 1) + ch * CHLC;
    float hv[CHLC];
    float s = 0.f;
#pragma unroll
    for (int r = 0; r < CHLC; r++) {
        int p = perm[r];
        hv[r] = h[(p * HH + head) * C1 + c];
        s = fmaf(w1p[r], hv[r], s);
        g_P1[(rowbase + r + 1) * C1 + c] = s;   // local inclusive prefix
    }
    g_T1[(head * NCHC + ch) * C1 + c] = s;
    s = 0.f;
#pragma unroll
    for (int r = CHLC - 1; r >= 0; r--) {
        s = fmaf(w2p[r], hv[r], s);
        g_S2[(rowbase + r) * C1 + c] = s;       // local inclusive suffix
    }
    g_T2[(head * NCHC + ch) * C1 + c] = s;
}

// LATD variant: grid (NSLOT, NCHL/8), block 128 = 8 groups x 16 threads.
__global__ void __launch_bounds__(128) vscanL(const float* __restrict__ hs2) {
    int slot = blockIdx.x;
    int grp = threadIdx.x >> 4;
    int c = threadIdx.x & 15;
    int ch = blockIdx.y * 8 + grp;
    int half = slot >> 2, head = slot & 3;
    const int*   perm = g_perm + slot * NN + ch * CHLL;
    const float* w1p  = g_w1s + slot * NN + ch * CHLL;
    const float* w2p  = g_w2s + slot * NN + ch * CHLL;
    long rowbase = (long)slot * (NN + 1) + ch * CHLL;
    float hv[CHLL];
    float s = 0.f;
#pragma unroll
    for (int r = 0; r < CHLL; r++) {
        int p = perm[r];
        hv[r] = hs2[p * 128 + half * 64 + head * LATD + c];
        s = fmaf(w1p[r], hv[r], s);
        g_P1[(rowbase + r + 1) * LATD + c] = s;
    }
    g_T1[(slot * NCHL + ch) * LATD + c] = s;
    s = 0.f;
#pragma unroll
    for (int r = CHLL - 1; r >= 0; r--) {
        s = fmaf(w2p[r], hv[r], s);
        g_S2[(rowbase + r) * LATD + c] = s;
    }
    g_T2[(slot * NCHL + ch) * LATD + c] = s;
}

// ---------------- chunk-total prefix/suffix (in place) ----------------
// grid (slots, C), block NCHX threads (thread = chunk).
template <int C, int NCHX>
__global__ void tpre_kernel() {
    int slot = blockIdx.x, c = blockIdx.y, t = threadIdx.x;
    float v1 = g_T1[(slot * NCHX + t) * C + c];
    float v2 = g_T2[(slot * NCHX + t) * C + c];
    float tot1, tot2;
    float i1 = bscan<NCHX, float>(v1, tot1);
    float i2 = bscan<NCHX, float>(v2, tot2);
    g_T1[(slot * NCHX + t) * C + c] = i1 - v1;    // exclusive prefix
    g_T2[(slot * NCHX + t) * C + c] = tot2 - i2;  // exclusive suffix
}

__device__ __forceinline__ int bsearch_gt(const float* sk, float t) {
    int lo = 0, hi = NN;
    while (lo < hi) {
        int mid = (lo + hi) >> 1;
        if (sk[mid] > t) lo = mid + 1; else hi = mid;
    }
    return lo;
}

// ---------------- dense GAT layer, C=128, concat ----------------
__global__ void dense_concat(const float* __restrict__ ed, const float* __restrict__ b,
                             float* __restrict__ out) {
    int i = blockIdx.x;
    int head = blockIdx.y;
    int c = threadIdx.x;
    float a = ed[i * HH + head];
    int k = bsearch_gt(g_skey + head * NN, -a);
    float am = a + g_Mb[head];
    float A1 = __expf(am), A2 = __expf(0.2f * am);
    float s1k = g_s1[head * (NN + 1) + k];
    float s2k = g_s2[head * (NN + 1) + k];
    float den = A1 * s1k + A2 * s2k;
    float p1v = 0.f, s2v = 0.f;
    if (k > 0) {
        int q = (k - 1) / CHLC;
        p1v = g_T1[(head * NCHC + q) * C1 + c] + g_P1[((long)head * (NN + 1) + k) * C1 + c];
    }
    if (k < NN) {
        int q = k / CHLC;
        s2v = g_T2[(head * NCHC + q) * C1 + c] + g_S2[((long)head * (NN + 1) + k) * C1 + c];
    }
    float num = A1 * p1v + A2 * s2v;
    out[i * D1 + head * C1 + c] = num / den + b[head * C1 + c];
}

// ---------------- dense GAT mean layers, both halves in one launch ----------------
__global__ void dense_mean2(const float* __restrict__ edm, const float* __restrict__ eds,
                            const float* __restrict__ bm, const float* __restrict__ bs,
                            float* __restrict__ zm, float* __restrict__ zs) {
    __shared__ float sh[64];
    int i = blockIdx.x;
    int half = blockIdx.y;
    int t = threadIdx.x;
    int head = t >> 4;
    int c = t & 15;
    int slot = half * 4 + head;
    const float* ed = half ? eds : edm;
    float a = ed[i * HH + head];
    int k = bsearch_gt(g_skey + slot * NN, -a);
    float am = a + g_Mb[slot];
    float A1 = __expf(am), A2 = __expf(0.2f * am);
    float den = A1 * g_s1[slot * (NN + 1) + k] + A2 * g_s2[slot * (NN + 1) + k];
    float p1v = 0.f, s2v = 0.f;
    if (k > 0) {
        int q = (k - 1) / CHLL;
        p1v = g_T1[(slot * NCHL + q) * LATD + c] + g_P1[((long)slot * (NN + 1) + k) * LATD + c];
    }
    if (k < NN) {
        int q = k / CHLL;
        s2v = g_T2[(slot * NCHL + q) * LATD + c] + g_S2[((long)slot * (NN + 1) + k) * LATD + c];
    }
    float num = A1 * p1v + A2 * s2v;
    sh[t] = num / den;
    __syncthreads();
    if (t < LATD) {
        float* out = half ? zs : zm;
        const float* b = half ? bs : bm;
        out[i * LATD + t] = 0.25f * (sh[t] + sh[16 + t] + sh[32 + t] + sh[48 + t]) + b[t];
    }
}

// ---------------- launch ----------------
extern "C" void kernel_launch(void* const* d_in, const int* in_sizes, int n_in,
                              void* d_out, int out_size) {
    const float* x   = (const float*)d_in[0];
    const int*   ei  = (const int*)d_in[1];
    const float* W1  = (const float*)d_in[3];
    const float* a1s = (const float*)d_in[4];
    const float* a1d = (const float*)d_in[5];
    const float* b1  = (const float*)d_in[6];
    const float* Wm  = (const float*)d_in[7];
    const float* ams = (const float*)d_in[8];
    const float* amd = (const float*)d_in[9];
    const float* bm  = (const float*)d_in[10];
    const float* Ws  = (const float*)d_in[11];
    const float* ass = (const float*)d_in[12];
    const float* asd = (const float*)d_in[13];
    const float* bs  = (const float*)d_in[14];
    float* out = (float*)d_out;
    float* z1m = out;
    float* z1s = out + NN * LATD;
    float* z2m = out + 2 * NN * LATD;
    float* z2s = out + 3 * NN * LATD;

    const int* src = ei;
    const int* dst = ei + EE;

    float *h1, *x1, *x2, *hs2a, *hs2b, *Wc;
    float *es1, *ed1;
    float *es2am, *ed2am, *es2as, *ed2as, *es2bm, *ed2bm, *es2bs, *ed2bs;
    cudaGetSymbolAddress((void**)&h1,    g_h1);
    cudaGetSymbolAddress((void**)&x1,    g_x1);
    cudaGetSymbolAddress((void**)&x2,    g_x2);
    cudaGetSymbolAddress((void**)&hs2a,  g_hs2a);
    cudaGetSymbolAddress((void**)&hs2b,  g_hs2b);
    cudaGetSymbolAddress((void**)&Wc,    g_Wc);
    cudaGetSymbolAddress((void**)&es1,   g_es1);
    cudaGetSymbolAddress((void**)&ed1,   g_ed1);
    cudaGetSymbolAddress((void**)&es2am, g_es2am);
    cudaGetSymbolAddress((void**)&ed2am, g_ed2am);
    cudaGetSymbolAddress((void**)&es2as, g_es2as);
    cudaGetSymbolAddress((void**)&ed2as, g_ed2as);
    cudaGetSymbolAddress((void**)&es2bm, g_es2bm);
    cudaGetSymbolAddress((void**)&ed2bm, g_ed2bm);
    cudaGetSymbolAddress((void**)&es2bs, g_es2bs);
    cudaGetSymbolAddress((void**)&ed2bs, g_ed2bs);

    static cudaStream_t sA = nullptr, sB = nullptr;
    static cudaEvent_t ev0 = nullptr, evMain = nullptr, evA = nullptr, evB = nullptr;
    if (sA == nullptr) {
        cudaStreamCreateWithFlags(&sA, cudaStreamNonBlocking);
        cudaStreamCreateWithFlags(&sB, cudaStreamNonBlocking);
        cudaEventCreateWithFlags(&ev0,    cudaEventDisableTiming);
        cudaEventCreateWithFlags(&evMain, cudaEventDisableTiming);
        cudaEventCreateWithFlags(&evA,    cudaEventDisableTiming);
        cudaEventCreateWithFlags(&evB,    cudaEventDisableTiming);
        cudaFuncSetAttribute(mma_gemm, cudaFuncAttributeMaxDynamicSharedMemorySize, 3 * STG_B);
        cudaFuncSetAttribute(sortF, cudaFuncAttributeMaxDynamicSharedMemorySize, SORT_SMEM_B);
    }

    // fork: CSR build on stream A overlapped with conversions on main
    cudaEventRecord(ev0, 0);
    cudaStreamWaitEvent(sA, ev0, 0);
    csr_zero<<<16, 256, 0, sA>>>();
    csr_count<<<(EE + 255) / 256, 256, 0, sA>>>(dst);
    csr_scan<<<1, 1024, 0, sA>>>();
    csr_scatter<<<(EE + 255) / 256, 256, 0, sA>>>(src, dst);
    csr_self<<<16, 256, 0, sA>>>();

    // main: conversions + big GEMM + layer-1 evals
    convA_kernel<<<1024, 256>>>(x);
    convBt_kernel<<<dim3(KP / 32, D1 / 32), dim3(32, 8)>>>(W1);
    buildWc<<<(D1 * 64 + 255) / 256, 256>>>(Wm, Ws);
    mma_gemm<<<dim3(D1 / 128, NN / 128), 256, 3 * STG_B>>>(h1);
    evals_kernel<C1><<<NN, 128>>>(h1, a1s, a1d, es1, ed1);
    cudaEventRecord(evMain, 0);

    // ---- branch A (sparse) ----
    cudaStreamWaitEvent(sA, evMain, 0);
    spagg_concat<<<NN, 128, 0, sA>>>(es1, ed1, h1, b1, x1);
    gemm64<<<dim3(2, NN / 64), 128, 0, sA>>>(x1, Wc, hs2a, NN, 128, D1);
    evals2<<<NN, 256, 0, sA>>>(hs2a, ams, amd, ass, asd, es2am, ed2am, es2as, ed2as);
    spagg_mean2<<<dim3(NN / 4, 2), 128, 0, sA>>>(es2am, ed2am, es2as, ed2as, hs2a,
                                                 bm, bs, z1m, z1s);
    cudaEventRecord(evA, sA);

    // ---- branch B (dense, rank-1 softmax) ----
    cudaStreamWaitEvent(sB, evMain, 0);
    sortF<<<4, 1024, SORT_SMEM_B, sB>>>(es1, es1);
    vscanC<<<dim3(HH, NCHC), C1, 0, sB>>>(h1);
    tpre_kernel<C1, NCHC><<<dim3(HH, C1), NCHC, 0, sB>>>();
    dense_concat<<<dim3(NN, HH), C1, 0, sB>>>(ed1, b1, x2);
    gemm64<<<dim3(2, NN / 64), 128, 0, sB>>>(x2, Wc, hs2b, NN, 128, D1);
    evals2<<<NN, 256, 0, sB>>>(hs2b, ams, amd, ass, asd, es2bm, ed2bm, es2bs, ed2bs);
    sortF<<<NSLOT, 1024, SORT_SMEM_B, sB>>>(es2bm, es2bs);
    vscanL<<<dim3(NSLOT, NCHL / 8), 128, 0, sB>>>(hs2b);
    tpre_kernel<LATD, NCHL><<<dim3(NSLOT, LATD), NCHL, 0, sB>>>();
    dense_mean2<<<dim3(NN, 2), 64, 0, sB>>>(ed2bm, ed2bs, bm, bs, z2m, z2s);
    cudaEventRecord(evB, sB);

    // join
    cudaStreamWaitEvent(0, evA, 0);
    cudaStreamWaitEvent(0, evB, 0);
}

// round 9
// speedup vs baseline: 16.6842x; 1.0509x over previous
#include <cuda_runtime.h>
#include <cuda_bf16.h>
#include <math.h>
#include <stdint.h>

#define NN   4096
#define EE   131072
#define INF_ 3000
#define HH   4
#define C1   128
#define D1   512   // H*C1
#define LATD 16
#define D2   64    // H*LATD
#define ETOT (EE + NN)
#define NCHC 128   // C1 scan chunks
#define CHLC 32    // C1 chunk length
#define NCHL 256   // LATD scan chunks
#define CHLL 16    // LATD chunk length
#define KP   3008  // padded K for MMA (94*32)
#define KST  32    // K per pipeline stage
#define NSTG (KP / KST)
#define ROWP 40    // padded smem row length in bf16 (32 + 8)
#define TILE_B (128 * ROWP * 2)
#define STG_B  (4 * TILE_B)
#define NSLOT 8    // sort slots (2 halves x 4 heads)
#define SORT_SMEM_U32 (4 * 4096 + 32 * 257)
#define SORT_SMEM_B   (SORT_SMEM_U32 * 4)

// ---------------- scratch (static device globals; no allocation) ----------------
__device__ float g_h1[NN * D1];
__device__ float g_x1[NN * D1];
__device__ float g_x2[NN * D1];
__device__ float g_hs2a[NN * 128];
__device__ float g_hs2b[NN * 128];
__device__ float g_Wc[D1 * 128];
__device__ float g_es1[NN * HH];
__device__ float g_ed1[NN * HH];
__device__ float g_es2am[NN * HH];
__device__ float g_ed2am[NN * HH];
__device__ float g_es2as[NN * HH];
__device__ float g_ed2as[NN * HH];
__device__ float g_es2bm[NN * HH];
__device__ float g_ed2bm[NN * HH];
__device__ float g_es2bs[NN * HH];
__device__ float g_ed2bs[NN * HH];
__device__ int   g_off[NN + 1];
__device__ int   g_cur[NN];
__device__ int   g_srcs[ETOT];
__device__ float g_skey[NSLOT * NN];
__device__ int   g_perm[NSLOT * NN];
__device__ float g_w1s[NSLOT * NN];
__device__ float g_w2s[NSLOT * NN];
__device__ float g_Mb[NSLOT];
__device__ float g_s1[NSLOT * (NN + 1)];
__device__ float g_s2[NSLOT * (NN + 1)];
__device__ float g_P1[HH * (NN + 1) * C1];
__device__ float g_S2[HH * (NN + 1) * C1];
__device__ float g_T1[65536];
__device__ float g_T2[65536];
// bf16 hi/lo split operands for HMMA GEMM
__device__ __align__(256) __nv_bfloat16 g_Ahi[(long)NN * KP];
__device__ __align__(256) __nv_bfloat16 g_Alo[(long)NN * KP];
__device__ __align__(256) __nv_bfloat16 g_Bhi[(long)D1 * KP];
__device__ __align__(256) __nv_bfloat16 g_Blo[(long)D1 * KP];

__device__ __forceinline__ float lrelu(float v) { return v > 0.f ? v : 0.2f * v; }

// ---------------- PTX helpers ----------------
__device__ __forceinline__ uint32_t smem_u32(const void* p) {
    return (uint32_t)__cvta_generic_to_shared(p);
}
__device__ __forceinline__ void cp16(uint32_t s, const void* g) {
    asm volatile("cp.async.cg.shared.global [%0], [%1], 16;\n" :: "r"(s), "l"(g));
}
__device__ __forceinline__ void cp_commit() {
    asm volatile("cp.async.commit_group;\n" ::: "memory");
}
template <int W>
__device__ __forceinline__ void cp_wait() {
    asm volatile("cp.async.wait_group %0;\n" :: "n"(W) : "memory");
}

__device__ __forceinline__ void mma_bf16(float& d0, float& d1, float& d2, float& d3,
                                         uint32_t a0, uint32_t a1, uint32_t a2, uint32_t a3,
                                         uint32_t b0, uint32_t b1) {
    asm volatile(
        "mma.sync.aligned.m16n8k16.row.col.f32.bf16.bf16.f32 "
        "{%0,%1,%2,%3}, {%4,%5,%6,%7}, {%8,%9}, {%0,%1,%2,%3};"
        : "+f"(d0), "+f"(d1), "+f"(d2), "+f"(d3)
        : "r"(a0), "r"(a1), "r"(a2), "r"(a3), "r"(b0), "r"(b1));
}

// ---------------- shuffle-based block scan (NT threads, NT%32==0) ----------------
template <int NT, typename T>
__device__ __forceinline__ T bscan(T v, T& total) {
    __shared__ T ws[NT / 32];
    int t = threadIdx.x, lane = t & 31, w = t >> 5;
    __syncthreads();
    T x = v;
#pragma unroll
    for (int o = 1; o < 32; o <<= 1) {
        T y = __shfl_up_sync(0xffffffffu, x, o);
        if (lane >= o) x += y;
    }
    if (lane == 31) ws[w] = x;
    __syncthreads();
    if (t < NT / 32) {
        T s = ws[t];
#pragma unroll
        for (int o = 1; o < NT / 32; o <<= 1) {
            T y = __shfl_up_sync((NT / 32 < 32) ? ((1u << (NT / 32)) - 1u) : 0xffffffffu, s, o);
            if (t >= o) s += y;
        }
        ws[t] = s;
    }
    __syncthreads();
    T off = (w == 0) ? (T)0 : ws[w - 1];
    total = ws[NT / 32 - 1];
    return x + off;
}

// ---------------- fp32 -> bf16 hi/lo conversion of x ----------------
struct __align__(16) bf8 { __nv_bfloat16 v[8]; };
__global__ void convA_kernel(const float* __restrict__ x) {
    const long nch = (long)NN * (KP / 8);
    for (long id = (long)blockIdx.x * blockDim.x + threadIdx.x; id < nch;
         id += (long)gridDim.x * blockDim.x) {
        long row = id / (KP / 8);
        int c = (int)(id % (KP / 8));
        bf8 hi, lo;
        if (c < INF_ / 8) {
            const float* xp = x + row * INF_ + c * 8;
#pragma unroll
            for (int j = 0; j < 8; j++) {
                float v = xp[j];
                __nv_bfloat16 h = __float2bfloat16(v);
                hi.v[j] = h;
                lo.v[j] = __float2bfloat16(v - __bfloat162float(h));
            }
        } else {
#pragma unroll
            for (int j = 0; j < 8; j++) { hi.v[j] = __float2bfloat16(0.f); lo.v[j] = hi.v[j]; }
        }
        *reinterpret_cast<bf8*>(&g_Ahi[row * KP + c * 8]) = hi;
        *reinterpret_cast<bf8*>(&g_Alo[row * KP + c * 8]) = lo;
    }
}

__global__ void convBt_kernel(const float* __restrict__ W) {
    __shared__ float t[32][33];
    int kb = blockIdx.x * 32, nb = blockIdx.y * 32;
    int tx = threadIdx.x, ty = threadIdx.y;
#pragma unroll
    for (int r = 0; r < 32; r += 8) {
        int k = kb + ty + r, n = nb + tx;
        t[ty + r][tx] = (k < INF_) ? W[(long)k * D1 + n] : 0.f;
    }
    __syncthreads();
#pragma unroll
    for (int r = 0; r < 32; r += 8) {
        int n = nb + ty + r, k = kb + tx;
        float v = t[tx][ty + r];
        __nv_bfloat16 h = __float2bfloat16(v);
        g_Bhi[(long)n * KP + k] = h;
        g_Blo[(long)n * KP + k] = __float2bfloat16(v - __bfloat162float(h));
    }
}

// Wc = [Wm | Ws] : [512][128]
__global__ void buildWc(const float* __restrict__ Wm, const float* __restrict__ Ws) {
    int i = blockIdx.x * 256 + threadIdx.x;
    if (i < D1 * 64) {
        int k = i >> 6, n = i & 63;
        g_Wc[k * 128 + n] = Wm[i];
        g_Wc[k * 128 + 64 + n] = Ws[i];
    }
}

// ---------------- HMMA GEMM (h1 = x @ W1), 4(m)x2(n) warp grid ----------------
__global__ void __launch_bounds__(256) mma_gemm(float* __restrict__ Cout) {
    extern __shared__ char smem[];
    const int tid = threadIdx.x;
    const int wid = tid >> 5, lane = tid & 31;
    const int g = lane >> 2, tig = lane & 3;
    const int wm = (wid & 3) * 32;      // 4 warps along M (32 rows each)
    const int wn = (wid >> 2) * 64;     // 2 warps along N (64 cols each)
    const int bn = blockIdx.x * 128;
    const int bm = blockIdx.y * 128;
    uint32_t sb = smem_u32(smem);

    float acc[2][8][4];
#pragma unroll
    for (int i = 0; i < 2; i++)
#pragma unroll
        for (int j = 0; j < 8; j++)
#pragma unroll
            for (int q = 0; q < 4; q++) acc[i][j][q] = 0.f;

    auto load_stage = [&](int s) {
        uint32_t base = sb + (uint32_t)(s % 3) * STG_B;
        long gk = (long)s * KST;
#pragma unroll
        for (int t = 0; t < 8; t++) {
            int id = tid + t * 256;
            int mat = id >> 9;
            int r = (id >> 2) & 127;
            int c16 = id & 3;
            uint32_t so = base + (uint32_t)mat * TILE_B + (uint32_t)(r * 80 + c16 * 16);
            const __nv_bfloat16* gp;
            if (mat == 0)      gp = &g_Ahi[(long)(bm + r) * KP + gk + c16 * 8];
            else if (mat == 1) gp = &g_Alo[(long)(bm + r) * KP + gk + c16 * 8];
            else if (mat == 2) gp = &g_Bhi[(long)(bn + r) * KP + gk + c16 * 8];
            else               gp = &g_Blo[(long)(bn + r) * KP + gk + c16 * 8];
            cp16(so, gp);
        }
        cp_commit();
    };

    load_stage(0);
    load_stage(1);

    for (int s = 0; s < NSTG; s++) {
        if (s + 1 < NSTG) cp_wait<1>(); else cp_wait<0>();
        __syncthreads();
        const char* stg = smem + (s % 3) * STG_B;
        const uint32_t* Ah = (const uint32_t*)(stg);
        const uint32_t* Al = (const uint32_t*)(stg + TILE_B);
        const uint32_t* Bh = (const uint32_t*)(stg + 2 * TILE_B);
        const uint32_t* Bl = (const uint32_t*)(stg + 3 * TILE_B);
#pragma unroll
        for (int ks = 0; ks < 2; ks++) {
            int kh = ks * 8;
            uint32_t ah[2][4], al[2][4], bh[8][2], bl[8][2];
#pragma unroll
            for (int tm = 0; tm < 2; tm++) {
                int r = wm + tm * 16 + g;
                ah[tm][0] = Ah[r * 20 + kh + tig];
                ah[tm][1] = Ah[(r + 8) * 20 + kh + tig];
                ah[tm][2] = Ah[r * 20 + kh + 4 + tig];
                ah[tm][3] = Ah[(r + 8) * 20 + kh + 4 + tig];
                al[tm][0] = Al[r * 20 + kh + tig];
                al[tm][1] = Al[(r + 8) * 20 + kh + tig];
                al[tm][2] = Al[r * 20 + kh + 4 + tig];
                al[tm][3] = Al[(r + 8) * 20 + kh + 4 + tig];
            }
#pragma unroll
            for (int tn = 0; tn < 8; tn++) {
                int n = wn + tn * 8 + g;
                bh[tn][0] = Bh[n * 20 + kh + tig];
                bh[tn][1] = Bh[n * 20 + kh + 4 + tig];
                bl[tn][0] = Bl[n * 20 + kh + tig];
                bl[tn][1] = Bl[n * 20 + kh + 4 + tig];
            }
#pragma unroll
            for (int tm = 0; tm < 2; tm++)
#pragma unroll
                for (int tn = 0; tn < 8; tn++) {
                    float* d = acc[tm][tn];
                    mma_bf16(d[0], d[1], d[2], d[3],
                             ah[tm][0], ah[tm][1], ah[tm][2], ah[tm][3],
                             bh[tn][0], bh[tn][1]);
                    mma_bf16(d[0], d[1], d[2], d[3],
                             ah[tm][0], ah[tm][1], ah[tm][2], ah[tm][3],
                             bl[tn][0], bl[tn][1]);
                    mma_bf16(d[0], d[1], d[2], d[3],
                             al[tm][0], al[tm][1], al[tm][2], al[tm][3],
                             bh[tn][0], bh[tn][1]);
                }
        }
        __syncthreads();
        if (s + 2 < NSTG) load_stage(s + 2);
    }

#pragma unroll
    for (int tm = 0; tm < 2; tm++)
#pragma unroll
        for (int tn = 0; tn < 8; tn++) {
            int r0 = bm + wm + tm * 16 + g;
            int c0 = bn + wn + tn * 8 + 2 * tig;
            float* d = acc[tm][tn];
            *reinterpret_cast<float2*>(&Cout[(long)r0 * D1 + c0]) = make_float2(d[0], d[1]);
            *reinterpret_cast<float2*>(&Cout[(long)(r0 + 8) * D1 + c0]) = make_float2(d[2], d[3]);
        }
}

// ---------------- fp32 GEMM 64x64 tile, double buffered ----------------
__global__ void __launch_bounds__(128) gemm64(const float* __restrict__ A,
                                              const float* __restrict__ B,
                                              float* __restrict__ C, int M, int Nn, int K) {
    __shared__ float As[2][64][8];
    __shared__ float Bs[2][8][64];
    const int tid = threadIdx.x;
    const int bm = blockIdx.y * 64;
    const int bn = blockIdx.x * 64;
    const int arow = tid >> 1, acol = (tid & 1) * 4;
    const int brow = tid >> 4, bcol = (tid & 15) * 4;
    const int ty = (tid >> 4) * 8;
    const int tx = (tid & 15) * 4;

    const float* Ag = A + (long)(bm + arow) * K + acol;
    const float* Bg = B + (long)brow * Nn + bn + bcol;
    uint32_t aS[2] = { smem_u32(&As[0][arow][acol]), smem_u32(&As[1][arow][acol]) };
    uint32_t bS[2] = { smem_u32(&Bs[0][brow][bcol]), smem_u32(&Bs[1][brow][bcol]) };

    float acc[8][4];
#pragma unroll
    for (int i = 0; i < 8; i++)
#pragma unroll
        for (int j = 0; j < 4; j++) acc[i][j] = 0.f;

    cp16(aS[0], Ag);
    cp16(bS[0], Bg);
    cp_commit();

    int stage = 0;
    for (int k0 = 0; k0 < K; k0 += 8) {
        if (k0 + 8 < K) {
            cp16(aS[stage ^ 1], Ag + (k0 + 8));
            cp16(bS[stage ^ 1], Bg + (long)(k0 + 8) * Nn);
            cp_commit();
            cp_wait<1>();
        } else {
            cp_wait<0>();
        }
        __syncthreads();
#pragma unroll
        for (int kk = 0; kk < 8; kk++) {
            float4 b0 = *reinterpret_cast<const float4*>(&Bs[stage][kk][tx]);
            float ra[8];
#pragma unroll
            for (int i = 0; i < 8; i++) ra[i] = As[stage][ty + i][kk];
#pragma unroll
            for (int i = 0; i < 8; i++) {
                acc[i][0] = fmaf(ra[i], b0.x, acc[i][0]);
                acc[i][1] = fmaf(ra[i], b0.y, acc[i][1]);
                acc[i][2] = fmaf(ra[i], b0.z, acc[i][2]);
                acc[i][3] = fmaf(ra[i], b0.w, acc[i][3]);
            }
        }
        __syncthreads();
        stage ^= 1;
    }
#pragma unroll
    for (int i = 0; i < 8; i++) {
        float* cp = C + (long)(bm + ty + i) * Nn + bn + tx;
        *reinterpret_cast<float4*>(cp) = make_float4(acc[i][0], acc[i][1], acc[i][2], acc[i][3]);
    }
}

// ---------------- e_src / e_dst, layer 1 (C=128) ----------------
template <int C>
__global__ void evals_kernel(const float* __restrict__ h, const float* __restrict__ asrc,
                             const float* __restrict__ adst, float* __restrict__ es,
                             float* __restrict__ ed) {
    int g = blockIdx.x * 4 + (threadIdx.x >> 5);
    int lane = threadIdx.x & 31;
    int n = g >> 2;
    int head = g & 3;
    float s1 = 0.f, s2 = 0.f;
    for (int c = lane; c < C; c += 32) {
        float hv = h[(n * HH + head) * C + c];
        s1 = fmaf(hv, asrc[head * C + c], s1);
        s2 = fmaf(hv, adst[head * C + c], s2);
    }
    for (int o = 16; o > 0; o >>= 1) {
        s1 += __shfl_xor_sync(0xffffffffu, s1, o);
        s2 += __shfl_xor_sync(0xffffffffu, s2, o);
    }
    if (lane == 0) { es[n * HH + head] = s1; ed[n * HH + head] = s2; }
}

// ---------------- e_src / e_dst for both halves of hs2 (C=16) ----------------
__global__ void evals2(const float* __restrict__ hs2,
                       const float* __restrict__ ams, const float* __restrict__ amd,
                       const float* __restrict__ ass, const float* __restrict__ asd,
                       float* __restrict__ esm, float* __restrict__ edm,
                       float* __restrict__ ess, float* __restrict__ eds) {
    int n = blockIdx.x;
    int w = threadIdx.x >> 5;
    int lane = threadIdx.x & 31;
    int half = w >> 2, head = w & 3;
    const float* avs = half ? ass : ams;
    const float* avd = half ? asd : amd;
    float s1 = 0.f, s2 = 0.f;
    if (lane < LATD) {
        float hv = hs2[n * 128 + half * 64 + head * LATD + lane];
        s1 = hv * avs[head * LATD + lane];
        s2 = hv * avd[head * LATD + lane];
    }
    for (int o = 8; o > 0; o >>= 1) {
        s1 += __shfl_xor_sync(0xffffffffu, s1, o);
        s2 += __shfl_xor_sync(0xffffffffu, s2, o);
    }
    if (lane == 0) {
        (half ? ess : esm)[n * HH + head] = s1;
        (half ? eds : edm)[n * HH + head] = s2;
    }
}

// ---------------- CSR build ----------------
__global__ void csr_zero() {
    int i = blockIdx.x * blockDim.x + threadIdx.x;
    if (i < NN) g_cur[i] = 0;
}
__global__ void csr_count(const int* __restrict__ dst) {
    int e = blockIdx.x * blockDim.x + threadIdx.x;
    if (e < EE) atomicAdd(&g_cur[dst[e]], 1);
}
__global__ void csr_scan() {
    __shared__ int sh[1024];
    int t = threadIdx.x;
    int c[4]; int s = 0;
#pragma unroll
    for (int u = 0; u < 4; u++) { c[u] = g_cur[t * 4 + u] + 1; s += c[u]; }
    sh[t] = s;
    __syncthreads();
    for (int o = 1; o < 1024; o <<= 1) {
        int v = (t >= o) ? sh[t - o] : 0;
        __syncthreads();
        sh[t] += v;
        __syncthreads();
    }
    int base = sh[t] - s;
#pragma unroll
    for (int u = 0; u < 4; u++) {
        g_off[t * 4 + u] = base;
        g_cur[t * 4 + u] = base;
        base += c[u];
    }
    if (t == 1023) g_off[NN] = sh[1023];
}
__global__ void csr_scatter(const int* __restrict__ src, const int* __restrict__ dst) {
    int e = blockIdx.x * blockDim.x + threadIdx.x;
    if (e < EE) {
        int p = atomicAdd(&g_cur[dst[e]], 1);
        g_srcs[p] = src[e];
    }
}
__global__ void csr_self() {
    int n = blockIdx.x * blockDim.x + threadIdx.x;
    if (n < NN) {
        int p = atomicAdd(&g_cur[n], 1);
        g_srcs[p] = n;
    }
}

// ---------------- sparse GAT layer, C=128, concat ----------------
__global__ void spagg_concat(const float* __restrict__ es, const float* __restrict__ ed,
                             const float* __restrict__ h, const float* __restrict__ b,
                             float* __restrict__ out) {
    int dst = blockIdx.x;
    int head = threadIdx.x >> 5;
    int lane = threadIdx.x & 31;
    int beg = g_off[dst], end = g_off[dst + 1];
    float edv = ed[dst * HH + head];

    float m = -INFINITY;
    for (int e = beg + lane; e < end; e += 32)
        m = fmaxf(m, lrelu(es[g_srcs[e] * HH + head] + edv));
    for (int o = 16; o > 0; o >>= 1) m = fmaxf(m, __shfl_xor_sync(0xffffffffu, m, o));

    float den = 0.f;
    for (int e = beg + lane; e < end; e += 32)
        den += __expf(lrelu(es[g_srcs[e] * HH + head] + edv) - m);
    for (int o = 16; o > 0; o >>= 1) den += __shfl_xor_sync(0xffffffffu, den, o);
    float inv = 1.f / (den + 1e-16f);

    float a0 = 0.f, a1 = 0.f, a2 = 0.f, a3 = 0.f;
    for (int e = beg; e < end; e++) {
        int s = g_srcs[e];
        float w = __expf(lrelu(es[s * HH + head] + edv) - m) * inv;
        const float* hp = h + s * D1 + head * C1;
        a0 = fmaf(w, hp[lane], a0);
        a1 = fmaf(w, hp[lane + 32], a1);
        a2 = fmaf(w, hp[lane + 64], a2);
        a3 = fmaf(w, hp[lane + 96], a3);
    }
    float* op = out + dst * D1 + head * C1;
    const float* bp = b + head * C1;
    op[lane]      = a0 + bp[lane];
    op[lane + 32] = a1 + bp[lane + 32];
    op[lane + 64] = a2 + bp[lane + 64];
    op[lane + 96] = a3 + bp[lane + 96];
}

// ---------------- sparse GAT mean layers; 2 edges per iter ----------------
__global__ void spagg_mean2(const float* __restrict__ esm, const float* __restrict__ edm,
                            const float* __restrict__ ess, const float* __restrict__ eds,
                            const float* __restrict__ hs2,
                            const float* __restrict__ bm, const float* __restrict__ bs,
                            float* __restrict__ zm, float* __restrict__ zs) {
    int half = blockIdx.y;
    const float* es = half ? ess : esm;
    const float* ed = half ? eds : edm;
    const float* b  = half ? bs : bm;
    float* out      = half ? zs : zm;
    int dst = blockIdx.x * 4 + (threadIdx.x >> 5);
    int lane = threadIdx.x & 31;
    int sub = lane >> 4;        // which of the 2 edges this lane handles
    int c = lane & 15;
    int beg = g_off[dst], end = g_off[dst + 1];
    float acc = 0.f;
    for (int head = 0; head < HH; head++) {
        float edv = ed[dst * HH + head];
        float m = -INFINITY;
        for (int e = beg + lane; e < end; e += 32)
            m = fmaxf(m, lrelu(es[g_srcs[e] * HH + head] + edv));
        for (int o = 16; o > 0; o >>= 1) m = fmaxf(m, __shfl_xor_sync(0xffffffffu, m, o));
        float den = 0.f;
        for (int e = beg + lane; e < end; e += 32)
            den += __expf(lrelu(es[g_srcs[e] * HH + head] + edv) - m);
        for (int o = 16; o > 0; o >>= 1) den += __shfl_xor_sync(0xffffffffu, den, o);
        float inv = 1.f / (den + 1e-16f);
        for (int e = beg; e < end; e += 2) {
            int ee = e + sub;
            if (ee < end) {
                int s = g_srcs[ee];
                float w = __expf(lrelu(es[s * HH + head] + edv) - m) * inv;
                acc = fmaf(w, hs2[s * 128 + half * 64 + head * LATD + c], acc);
            }
        }
    }
    acc += __shfl_down_sync(0xffffffffu, acc, 16);
    if (lane < LATD) out[dst * LATD + lane] = acc * 0.25f + b[lane];
}

// ---------------- fused radix sort + weights + scalar scans ----------------
__device__ __forceinline__ float unmap_key(uint32_t kk) {
    uint32_t m = ~kk;
    return __uint_as_float((m & 0x80000000u) ? (m ^ 0x80000000u) : ~m);
}

__global__ void __launch_bounds__(1024) sortF(const float* __restrict__ esA,
                                              const float* __restrict__ esB) {
    extern __shared__ uint32_t sm[];
    uint32_t* KA = sm;
    uint32_t* VA = sm + 4096;
    uint32_t* KB = sm + 8192;
    uint32_t* VB = sm + 12288;
    uint32_t* WH = sm + 16384;

    int slot = blockIdx.x;
    int t = threadIdx.x;
    int w = t >> 5, lane = t & 31;
    const float* es = (slot < 4) ? esA : esB;
    int head = slot & 3;

    for (int i = t; i < NN; i += 1024) {
        uint32_t b = __float_as_uint(es[i * HH + head]);
        uint32_t m = (b & 0x80000000u) ? ~b : (b | 0x80000000u);
        KA[i] = ~m;
        VA[i] = (uint32_t)i;
    }
    __syncthreads();

    uint32_t *KI = KA, *VI = VA, *KO = KB, *VO = VB;

#pragma unroll
    for (int pass = 0; pass < 4; pass++) {
        int shift = pass * 8;
        for (int i = t; i < 32 * 257; i += 1024) WH[i] = 0;
        __syncthreads();

        uint32_t k_[4], v_[4], d_[4], lr_[4];
#pragma unroll
        for (int r = 0; r < 4; r++) {
            int idx = w * 128 + r * 32 + lane;
            k_[r] = KI[idx];
            v_[r] = VI[idx];
            d_[r] = (k_[r] >> shift) & 255u;
            unsigned mask = __match_any_sync(0xffffffffu, d_[r]);
            int phys = w * 257 + (int)d_[r];
            uint32_t before = WH[phys];
            __syncwarp();
            lr_[r] = before + (uint32_t)__popc(mask & ((1u << lane) - 1u));
            int leader = __ffs((int)mask) - 1;
            if (lane == leader) WH[phys] = before + (uint32_t)__popc(mask);
            __syncwarp();
        }
        __syncthreads();

        uint32_t loc[8], sum = 0;
        int dbase = t >> 2;
        int wbase = (t & 3) * 8;
#pragma unroll
        for (int u = 0; u < 8; u++) {
            loc[u] = WH[(wbase + u) * 257 + dbase];
            sum += loc[u];
        }
        uint32_t totU;
        uint32_t incl = bscan<1024, uint32_t>(sum, totU);
        uint32_t run = incl - sum;
        __syncthreads();
#pragma unroll
        for (int u = 0; u < 8; u++) {
            uint32_t c0 = loc[u];
            WH[(wbase + u) * 257 + dbase] = run;
            run += c0;
        }
        __syncthreads();

#pragma unroll
        for (int r = 0; r < 4; r++) {
            uint32_t dest = WH[w * 257 + (int)d_[r]] + lr_[r];
            KO[dest] = k_[r];
            VO[dest] = v_[r];
        }
        __syncthreads();
        uint32_t* tk = KI; KI = KO; KO = tk;
        uint32_t* tv = VI; VI = VO; VO = tv;
    }

    float mb = unmap_key(KI[0]);
    int base = t * 4;
    float w1v[4], w2v[4];
    float loc1 = 0.f, loc2 = 0.f;
#pragma unroll
    for (int u = 0; u < 4; u++) {
        int i = base + u;
        float kv = unmap_key(KI[i]);
        g_skey[slot * NN + i] = kv;
        g_perm[slot * NN + i] = (int)VI[i];
        float d = kv - mb;
        w1v[u] = __expf(d);
        w2v[u] = __expf(0.2f * d);
        g_w1s[slot * NN + i] = w1v[u];
        g_w2s[slot * NN + i] = w2v[u];
        loc1 += w1v[u];
        loc2 += w2v[u];
    }
    float tot1, tot2;
    float incl1 = bscan<1024, float>(loc1, tot1);
    float incl2 = bscan<1024, float>(loc2, tot2);
    float s = incl1 - loc1;
#pragma unroll
    for (int u = 0; u < 4; u++) { g_s1[slot * (NN + 1) + base + u] = s; s += w1v[u]; }
    if (t == 1023) g_s1[slot * (NN + 1) + NN] = tot1;
    float a2 = tot2 - incl2;
#pragma unroll
    for (int u = 3; u >= 0; u--) { a2 += w2v[u]; g_s2[slot * (NN + 1) + base + u] = a2; }
    if (t == 0) { g_s2[slot * (NN + 1) + NN] = 0.f; g_Mb[slot] = mb; }
}

// ---------------- fused gather + chunk-local scans ----------------
__global__ void __launch_bounds__(C1) vscanC(const float* __restrict__ h) {
    int head = blockIdx.x, ch = blockIdx.y, c = threadIdx.x;
    const int*   perm = g_perm + head * NN + ch * CHLC;
    const float* w1p  = g_w1s + head * NN + ch * CHLC;
    const float* w2p  = g_w2s + head * NN + ch * CHLC;
    long rowbase = (long)head * (NN + 1) + ch * CHLC;
    float hv[CHLC];
    float s = 0.f;
#pragma unroll
    for (int r = 0; r < CHLC; r++) {
        int p = perm[r];
        hv[r] = h[(p * HH + head) * C1 + c];
        s = fmaf(w1p[r], hv[r], s);
        g_P1[(rowbase + r + 1) * C1 + c] = s;
    }
    g_T1[(head * NCHC + ch) * C1 + c] = s;
    s = 0.f;
#pragma unroll
    for (int r = CHLC - 1; r >= 0; r--) {
        s = fmaf(w2p[r], hv[r], s);
        g_S2[(rowbase + r) * C1 + c] = s;
    }
    g_T2[(head * NCHC + ch) * C1 + c] = s;
}

__global__ void __launch_bounds__(128) vscanL(const float* __restrict__ hs2) {
    int slot = blockIdx.x;
    int grp = threadIdx.x >> 4;
    int c = threadIdx.x & 15;
    int ch = blockIdx.y * 8 + grp;
    int half = slot >> 2, head = slot & 3;
    const int*   perm = g_perm + slot * NN + ch * CHLL;
    const float* w1p  = g_w1s + slot * NN + ch * CHLL;
    const float* w2p  = g_w2s + slot * NN + ch * CHLL;
    long rowbase = (long)slot * (NN + 1) + ch * CHLL;
    float hv[CHLL];
    float s = 0.f;
#pragma unroll
    for (int r = 0; r < CHLL; r++) {
        int p = perm[r];
        hv[r] = hs2[p * 128 + half * 64 + head * LATD + c];
        s = fmaf(w1p[r], hv[r], s);
        g_P1[(rowbase + r + 1) * LATD + c] = s;
    }
    g_T1[(slot * NCHL + ch) * LATD + c] = s;
    s = 0.f;
#pragma unroll
    for (int r = CHLL - 1; r >= 0; r--) {
        s = fmaf(w2p[r], hv[r], s);
        g_S2[(rowbase + r) * LATD + c] = s;
    }
    g_T2[(slot * NCHL + ch) * LATD + c] = s;
}

// ---------------- chunk-total prefix/suffix (in place) ----------------
template <int C, int NCHX>
__global__ void tpre_kernel() {
    int slot = blockIdx.x, c = blockIdx.y, t = threadIdx.x;
    float v1 = g_T1[(slot * NCHX + t) * C + c];
    float v2 = g_T2[(slot * NCHX + t) * C + c];
    float tot1, tot2;
    float i1 = bscan<NCHX, float>(v1, tot1);
    float i2 = bscan<NCHX, float>(v2, tot2);
    g_T1[(slot * NCHX + t) * C + c] = i1 - v1;
    g_T2[(slot * NCHX + t) * C + c] = tot2 - i2;
}

__device__ __forceinline__ int bsearch_gt(const float* sk, float t) {
    int lo = 0, hi = NN;
    while (lo < hi) {
        int mid = (lo + hi) >> 1;
        if (sk[mid] > t) lo = mid + 1; else hi = mid;
    }
    return lo;
}

// ---------------- dense GAT layer, C=128, concat ----------------
__global__ void dense_concat(const float* __restrict__ ed, const float* __restrict__ b,
                             float* __restrict__ out) {
    int i = blockIdx.x;
    int head = blockIdx.y;
    int c = threadIdx.x;
    float a = ed[i * HH + head];
    int k = bsearch_gt(g_skey + head * NN, -a);
    float am = a + g_Mb[head];
    float A1 = __expf(am), A2 = __expf(0.2f * am);
    float s1k = g_s1[head * (NN + 1) + k];
    float s2k = g_s2[head * (NN + 1) + k];
    float den = A1 * s1k + A2 * s2k;
    float p1v = 0.f, s2v = 0.f;
    if (k > 0) {
        int q = (k - 1) / CHLC;
        p1v = g_T1[(head * NCHC + q) * C1 + c] + g_P1[((long)head * (NN + 1) + k) * C1 + c];
    }
    if (k < NN) {
        int q = k / CHLC;
        s2v = g_T2[(head * NCHC + q) * C1 + c] + g_S2[((long)head * (NN + 1) + k) * C1 + c];
    }
    float num = A1 * p1v + A2 * s2v;
    out[i * D1 + head * C1 + c] = num / den + b[head * C1 + c];
}

// ---------------- dense GAT mean layers, both halves in one launch ----------------
__global__ void dense_mean2(const float* __restrict__ edm, const float* __restrict__ eds,
                            const float* __restrict__ bm, const float* __restrict__ bs,
                            float* __restrict__ zm, float* __restrict__ zs) {
    __shared__ float sh[64];
    int i = blockIdx.x;
    int half = blockIdx.y;
    int t = threadIdx.x;
    int head = t >> 4;
    int c = t & 15;
    int slot = half * 4 + head;
    const float* ed = half ? eds : edm;
    float a = ed[i * HH + head];
    int k = bsearch_gt(g_skey + slot * NN, -a);
    float am = a + g_Mb[slot];
    float A1 = __expf(am), A2 = __expf(0.2f * am);
    float den = A1 * g_s1[slot * (NN + 1) + k] + A2 * g_s2[slot * (NN + 1) + k];
    float p1v = 0.f, s2v = 0.f;
    if (k > 0) {
        int q = (k - 1) / CHLL;
        p1v = g_T1[(slot * NCHL + q) * LATD + c] + g_P1[((long)slot * (NN + 1) + k) * LATD + c];
    }
    if (k < NN) {
        int q = k / CHLL;
        s2v = g_T2[(slot * NCHL + q) * LATD + c] + g_S2[((long)slot * (NN + 1) + k) * LATD + c];
    }
    float num = A1 * p1v + A2 * s2v;
    sh[t] = num / den;
    __syncthreads();
    if (t < LATD) {
        float* out = half ? zs : zm;
        const float* b = half ? bs : bm;
        out[i * LATD + t] = 0.25f * (sh[t] + sh[16 + t] + sh[32 + t] + sh[48 + t]) + b[t];
    }
}

// ---------------- launch ----------------
extern "C" void kernel_launch(void* const* d_in, const int* in_sizes, int n_in,
                              void* d_out, int out_size) {
    const float* x   = (const float*)d_in[0];
    const int*   ei  = (const int*)d_in[1];
    const float* W1  = (const float*)d_in[3];
    const float* a1s = (const float*)d_in[4];
    const float* a1d = (const float*)d_in[5];
    const float* b1  = (const float*)d_in[6];
    const float* Wm  = (const float*)d_in[7];
    const float* ams = (const float*)d_in[8];
    const float* amd = (const float*)d_in[9];
    const float* bm  = (const float*)d_in[10];
    const float* Ws  = (const float*)d_in[11];
    const float* ass = (const float*)d_in[12];
    const float* asd = (const float*)d_in[13];
    const float* bs  = (const float*)d_in[14];
    float* out = (float*)d_out;
    float* z1m = out;
    float* z1s = out + NN * LATD;
    float* z2m = out + 2 * NN * LATD;
    float* z2s = out + 3 * NN * LATD;

    const int* src = ei;
    const int* dst = ei + EE;

    float *h1, *x1, *x2, *hs2a, *hs2b, *Wc;
    float *es1, *ed1;
    float *es2am, *ed2am, *es2as, *ed2as, *es2bm, *ed2bm, *es2bs, *ed2bs;
    cudaGetSymbolAddress((void**)&h1,    g_h1);
    cudaGetSymbolAddress((void**)&x1,    g_x1);
    cudaGetSymbolAddress((void**)&x2,    g_x2);
    cudaGetSymbolAddress((void**)&hs2a,  g_hs2a);
    cudaGetSymbolAddress((void**)&hs2b,  g_hs2b);
    cudaGetSymbolAddress((void**)&Wc,    g_Wc);
    cudaGetSymbolAddress((void**)&es1,   g_es1);
    cudaGetSymbolAddress((void**)&ed1,   g_ed1);
    cudaGetSymbolAddress((void**)&es2am, g_es2am);
    cudaGetSymbolAddress((void**)&ed2am, g_ed2am);
    cudaGetSymbolAddress((void**)&es2as, g_es2as);
    cudaGetSymbolAddress((void**)&ed2as, g_ed2as);
    cudaGetSymbolAddress((void**)&es2bm, g_es2bm);
    cudaGetSymbolAddress((void**)&ed2bm, g_ed2bm);
    cudaGetSymbolAddress((void**)&es2bs, g_es2bs);
    cudaGetSymbolAddress((void**)&ed2bs, g_ed2bs);

    static cudaStream_t sA = nullptr, sB = nullptr;
    static cudaEvent_t ev0 = nullptr, evW = nullptr, evMain = nullptr, evA = nullptr, evB = nullptr;
    if (sA == nullptr) {
        cudaStreamCreateWithFlags(&sA, cudaStreamNonBlocking);
        cudaStreamCreateWithFlags(&sB, cudaStreamNonBlocking);
        cudaEventCreateWithFlags(&ev0,    cudaEventDisableTiming);
        cudaEventCreateWithFlags(&evW,    cudaEventDisableTiming);
        cudaEventCreateWithFlags(&evMain, cudaEventDisableTiming);
        cudaEventCreateWithFlags(&evA,    cudaEventDisableTiming);
        cudaEventCreateWithFlags(&evB,    cudaEventDisableTiming);
        cudaFuncSetAttribute(mma_gemm, cudaFuncAttributeMaxDynamicSharedMemorySize, 3 * STG_B);
        cudaFuncSetAttribute(sortF, cudaFuncAttributeMaxDynamicSharedMemorySize, SORT_SMEM_B);
    }

    // fork: CSR build (sA) + W-side conversions (sB) overlap convA (main)
    cudaEventRecord(ev0, 0);
    cudaStreamWaitEvent(sA, ev0, 0);
    cudaStreamWaitEvent(sB, ev0, 0);
    csr_zero<<<16, 256, 0, sA>>>();
    csr_count<<<(EE + 255) / 256, 256, 0, sA>>>(dst);
    csr_scan<<<1, 1024, 0, sA>>>();
    csr_scatter<<<(EE + 255) / 256, 256, 0, sA>>>(src, dst);
    csr_self<<<16, 256, 0, sA>>>();

    convBt_kernel<<<dim3(KP / 32, D1 / 32), dim3(32, 8), 0, sB>>>(W1);
    buildWc<<<(D1 * 64 + 255) / 256, 256, 0, sB>>>(Wm, Ws);
    cudaEventRecord(evW, sB);

    convA_kernel<<<1024, 256>>>(x);
    cudaStreamWaitEvent(0, evW, 0);
    mma_gemm<<<dim3(D1 / 128, NN / 128), 256, 3 * STG_B>>>(h1);
    evals_kernel<C1><<<NN, 128>>>(h1, a1s, a1d, es1, ed1);
    cudaEventRecord(evMain, 0);

    // ---- branch A (sparse) ----
    cudaStreamWaitEvent(sA, evMain, 0);
    spagg_concat<<<NN, 128, 0, sA>>>(es1, ed1, h1, b1, x1);
    gemm64<<<dim3(2, NN / 64), 128, 0, sA>>>(x1, Wc, hs2a, NN, 128, D1);
    evals2<<<NN, 256, 0, sA>>>(hs2a, ams, amd, ass, asd, es2am, ed2am, es2as, ed2as);
    spagg_mean2<<<dim3(NN / 4, 2), 128, 0, sA>>>(es2am, ed2am, es2as, ed2as, hs2a,
                                                 bm, bs, z1m, z1s);
    cudaEventRecord(evA, sA);

    // ---- branch B (dense, rank-1 softmax) ----
    cudaStreamWaitEvent(sB, evMain, 0);
    sortF<<<4, 1024, SORT_SMEM_B, sB>>>(es1, es1);
    vscanC<<<dim3(HH, NCHC), C1, 0, sB>>>(h1);
    tpre_kernel<C1, NCHC><<<dim3(HH, C1), NCHC, 0, sB>>>();
    dense_concat<<<dim3(NN, HH), C1, 0, sB>>>(ed1, b1, x2);
    gemm64<<<dim3(2, NN / 64), 128, 0, sB>>>(x2, Wc, hs2b, NN, 128, D1);
    evals2<<<NN, 256, 0, sB>>>(hs2b, ams, amd, ass, asd, es2bm, ed2bm, es2bs, ed2bs);
    sortF<<<NSLOT, 1024, SORT_SMEM_B, sB>>>(es2bm, es2bs);
    vscanL<<<dim3(NSLOT, NCHL / 8), 128, 0, sB>>>(hs2b);
    tpre_kernel<LATD, NCHL><<<dim3(NSLOT, LATD), NCHL, 0, sB>>>();
    dense_mean2<<<dim3(NN, 2), 64, 0, sB>>>(ed2bm, ed2bs, bm, bs, z2m, z2s);
    cudaEventRecord(evB, sB);

    // join
    cudaStreamWaitEvent(0, evA, 0);
    cudaStreamWaitEvent(0, evB, 0);
}

// round 10
// speedup vs baseline: 16.6872x; 1.0002x over previous
#include <cuda_runtime.h>
#include <cuda_bf16.h>
#include <math.h>
#include <stdint.h>

#define NN   4096
#define EE   131072
#define INF_ 3000
#define HH   4
#define C1   128
#define D1   512   // H*C1
#define LATD 16
#define D2   64    // H*LATD
#define ETOT (EE + NN)
#define NCHC 128   // C1 scan chunks
#define CHLC 32    // C1 chunk length
#define NCHL 256   // LATD scan chunks
#define CHLL 16    // LATD chunk length
#define KP   3008  // padded K for MMA (94*32)
#define KST  32    // K per pipeline stage
#define NSTG (KP / KST)
#define ROWP 40    // padded smem row length in bf16 (32 + 8)
#define TILE_B (128 * ROWP * 2)
#define STG_B  (4 * TILE_B)
#define NPIPE 5    // pipeline stages
#define NSLOT 8    // sort slots (2 halves x 4 heads)
#define SORT_SMEM_U32 (4 * 4096 + 32 * 257)
#define SORT_SMEM_B   (SORT_SMEM_U32 * 4)

// ---------------- scratch (static device globals; no allocation) ----------------
__device__ float g_h1[NN * D1];
__device__ float g_x1[NN * D1];
__device__ float g_x2[NN * D1];
__device__ float g_hs2a[NN * 128];
__device__ float g_hs2b[NN * 128];
__device__ float g_Wc[D1 * 128];
__device__ float g_es1[NN * HH];
__device__ float g_ed1[NN * HH];
__device__ float g_es2am[NN * HH];
__device__ float g_ed2am[NN * HH];
__device__ float g_es2as[NN * HH];
__device__ float g_ed2as[NN * HH];
__device__ float g_es2bm[NN * HH];
__device__ float g_ed2bm[NN * HH];
__device__ float g_es2bs[NN * HH];
__device__ float g_ed2bs[NN * HH];
__device__ int   g_off[NN + 1];
__device__ int   g_cur[NN];
__device__ int   g_srcs[ETOT];
__device__ float g_skey[NSLOT * NN];
__device__ int   g_perm[NSLOT * NN];
__device__ float g_w1s[NSLOT * NN];
__device__ float g_w2s[NSLOT * NN];
__device__ float g_Mb[NSLOT];
__device__ float g_s1[NSLOT * (NN + 1)];
__device__ float g_s2[NSLOT * (NN + 1)];
__device__ float g_P1[HH * (NN + 1) * C1];
__device__ float g_S2[HH * (NN + 1) * C1];
__device__ float g_T1[65536];
__device__ float g_T2[65536];
// bf16 hi/lo split operands for HMMA GEMM
__device__ __align__(256) __nv_bfloat16 g_Ahi[(long)NN * KP];
__device__ __align__(256) __nv_bfloat16 g_Alo[(long)NN * KP];
__device__ __align__(256) __nv_bfloat16 g_Bhi[(long)D1 * KP];
__device__ __align__(256) __nv_bfloat16 g_Blo[(long)D1 * KP];

__device__ __forceinline__ float lrelu(float v) { return v > 0.f ? v : 0.2f * v; }

// ---------------- PTX helpers ----------------
__device__ __forceinline__ uint32_t smem_u32(const void* p) {
    return (uint32_t)__cvta_generic_to_shared(p);
}
__device__ __forceinline__ void cp16(uint32_t s, const void* g) {
    asm volatile("cp.async.cg.shared.global [%0], [%1], 16;\n" :: "r"(s), "l"(g));
}
__device__ __forceinline__ void cp_commit() {
    asm volatile("cp.async.commit_group;\n" ::: "memory");
}
template <int W>
__device__ __forceinline__ void cp_wait() {
    asm volatile("cp.async.wait_group %0;\n" :: "n"(W) : "memory");
}

__device__ __forceinline__ void mma_bf16(float& d0, float& d1, float& d2, float& d3,
                                         uint32_t a0, uint32_t a1, uint32_t a2, uint32_t a3,
                                         uint32_t b0, uint32_t b1) {
    asm volatile(
        "mma.sync.aligned.m16n8k16.row.col.f32.bf16.bf16.f32 "
        "{%0,%1,%2,%3}, {%4,%5,%6,%7}, {%8,%9}, {%0,%1,%2,%3};"
        : "+f"(d0), "+f"(d1), "+f"(d2), "+f"(d3)
        : "r"(a0), "r"(a1), "r"(a2), "r"(a3), "r"(b0), "r"(b1));
}

// ---------------- shuffle-based block scan (NT threads, NT%32==0) ----------------
template <int NT, typename T>
__device__ __forceinline__ T bscan(T v, T& total) {
    __shared__ T ws[NT / 32];
    int t = threadIdx.x, lane = t & 31, w = t >> 5;
    __syncthreads();
    T x = v;
#pragma unroll
    for (int o = 1; o < 32; o <<= 1) {
        T y = __shfl_up_sync(0xffffffffu, x, o);
        if (lane >= o) x += y;
    }
    if (lane == 31) ws[w] = x;
    __syncthreads();
    if (t < NT / 32) {
        T s = ws[t];
#pragma unroll
        for (int o = 1; o < NT / 32; o <<= 1) {
            T y = __shfl_up_sync((NT / 32 < 32) ? ((1u << (NT / 32)) - 1u) : 0xffffffffu, s, o);
            if (t >= o) s += y;
        }
        ws[t] = s;
    }
    __syncthreads();
    T off = (w == 0) ? (T)0 : ws[w - 1];
    total = ws[NT / 32 - 1];
    return x + off;
}

// ---------------- fp32 -> bf16 hi/lo conversion of x ----------------
struct __align__(16) bf8 { __nv_bfloat16 v[8]; };
__global__ void convA_kernel(const float* __restrict__ x) {
    const long nch = (long)NN * (KP / 8);
    for (long id = (long)blockIdx.x * blockDim.x + threadIdx.x; id < nch;
         id += (long)gridDim.x * blockDim.x) {
        long row = id / (KP / 8);
        int c = (int)(id % (KP / 8));
        bf8 hi, lo;
        if (c < INF_ / 8) {
            const float* xp = x + row * INF_ + c * 8;
#pragma unroll
            for (int j = 0; j < 8; j++) {
                float v = xp[j];
                __nv_bfloat16 h = __float2bfloat16(v);
                hi.v[j] = h;
                lo.v[j] = __float2bfloat16(v - __bfloat162float(h));
            }
        } else {
#pragma unroll
            for (int j = 0; j < 8; j++) { hi.v[j] = __float2bfloat16(0.f); lo.v[j] = hi.v[j]; }
        }
        *reinterpret_cast<bf8*>(&g_Ahi[row * KP + c * 8]) = hi;
        *reinterpret_cast<bf8*>(&g_Alo[row * KP + c * 8]) = lo;
    }
}

__global__ void convBt_kernel(const float* __restrict__ W) {
    __shared__ float t[32][33];
    int kb = blockIdx.x * 32, nb = blockIdx.y * 32;
    int tx = threadIdx.x, ty = threadIdx.y;
#pragma unroll
    for (int r = 0; r < 32; r += 8) {
        int k = kb + ty + r, n = nb + tx;
        t[ty + r][tx] = (k < INF_) ? W[(long)k * D1 + n] : 0.f;
    }
    __syncthreads();
#pragma unroll
    for (int r = 0; r < 32; r += 8) {
        int n = nb + ty + r, k = kb + tx;
        float v = t[tx][ty + r];
        __nv_bfloat16 h = __float2bfloat16(v);
        g_Bhi[(long)n * KP + k] = h;
        g_Blo[(long)n * KP + k] = __float2bfloat16(v - __bfloat162float(h));
    }
}

// Wc = [Wm | Ws] : [512][128]
__global__ void buildWc(const float* __restrict__ Wm, const float* __restrict__ Ws) {
    int i = blockIdx.x * 256 + threadIdx.x;
    if (i < D1 * 64) {
        int k = i >> 6, n = i & 63;
        g_Wc[k * 128 + n] = Wm[i];
        g_Wc[k * 128 + 64 + n] = Ws[i];
    }
}

// ---------------- HMMA GEMM (h1 = x @ W1), 4(m)x2(n) warp grid, 5-stage pipe ----------------
__global__ void __launch_bounds__(256) mma_gemm(float* __restrict__ Cout) {
    extern __shared__ char smem[];
    const int tid = threadIdx.x;
    const int wid = tid >> 5, lane = tid & 31;
    const int g = lane >> 2, tig = lane & 3;
    const int wm = (wid & 3) * 32;
    const int wn = (wid >> 2) * 64;
    const int bn = blockIdx.x * 128;
    const int bm = blockIdx.y * 128;
    uint32_t sb = smem_u32(smem);

    float acc[2][8][4];
#pragma unroll
    for (int i = 0; i < 2; i++)
#pragma unroll
        for (int j = 0; j < 8; j++)
#pragma unroll
            for (int q = 0; q < 4; q++) acc[i][j][q] = 0.f;

    auto load_stage = [&](int s) {
        uint32_t base = sb + (uint32_t)(s % NPIPE) * STG_B;
        long gk = (long)s * KST;
#pragma unroll
        for (int t = 0; t < 8; t++) {
            int id = tid + t * 256;
            int mat = id >> 9;
            int r = (id >> 2) & 127;
            int c16 = id & 3;
            uint32_t so = base + (uint32_t)mat * TILE_B + (uint32_t)(r * 80 + c16 * 16);
            const __nv_bfloat16* gp;
            if (mat == 0)      gp = &g_Ahi[(long)(bm + r) * KP + gk + c16 * 8];
            else if (mat == 1) gp = &g_Alo[(long)(bm + r) * KP + gk + c16 * 8];
            else if (mat == 2) gp = &g_Bhi[(long)(bn + r) * KP + gk + c16 * 8];
            else               gp = &g_Blo[(long)(bn + r) * KP + gk + c16 * 8];
            cp16(so, gp);
        }
        cp_commit();
    };

    load_stage(0);
    load_stage(1);
    load_stage(2);
    load_stage(3);

    for (int s = 0; s < NSTG; s++) {
        // groups in flight at this point: stages s..min(s+3, NSTG-1)
        int pending_after = NSTG - 1 - s;
        if (pending_after >= 3)      cp_wait<3>();
        else if (pending_after == 2) cp_wait<2>();
        else if (pending_after == 1) cp_wait<1>();
        else                         cp_wait<0>();
        __syncthreads();
        const char* stg = smem + (s % NPIPE) * STG_B;
        const uint32_t* Ah = (const uint32_t*)(stg);
        const uint32_t* Al = (const uint32_t*)(stg + TILE_B);
        const uint32_t* Bh = (const uint32_t*)(stg + 2 * TILE_B);
        const uint32_t* Bl = (const uint32_t*)(stg + 3 * TILE_B);
#pragma unroll
        for (int ks = 0; ks < 2; ks++) {
            int kh = ks * 8;
            uint32_t ah[2][4], al[2][4], bh[8][2], bl[8][2];
#pragma unroll
            for (int tm = 0; tm < 2; tm++) {
                int r = wm + tm * 16 + g;
                ah[tm][0] = Ah[r * 20 + kh + tig];
                ah[tm][1] = Ah[(r + 8) * 20 + kh + tig];
                ah[tm][2] = Ah[r * 20 + kh + 4 + tig];
                ah[tm][3] = Ah[(r + 8) * 20 + kh + 4 + tig];
                al[tm][0] = Al[r * 20 + kh + tig];
                al[tm][1] = Al[(r + 8) * 20 + kh + tig];
                al[tm][2] = Al[r * 20 + kh + 4 + tig];
                al[tm][3] = Al[(r + 8) * 20 + kh + 4 + tig];
            }
#pragma unroll
            for (int tn = 0; tn < 8; tn++) {
                int n = wn + tn * 8 + g;
                bh[tn][0] = Bh[n * 20 + kh + tig];
                bh[tn][1] = Bh[n * 20 + kh + 4 + tig];
                bl[tn][0] = Bl[n * 20 + kh + tig];
                bl[tn][1] = Bl[n * 20 + kh + 4 + tig];
            }
#pragma unroll
            for (int tm = 0; tm < 2; tm++)
#pragma unroll
                for (int tn = 0; tn < 8; tn++) {
                    float* d = acc[tm][tn];
                    mma_bf16(d[0], d[1], d[2], d[3],
                             ah[tm][0], ah[tm][1], ah[tm][2], ah[tm][3],
                             bh[tn][0], bh[tn][1]);
                    mma_bf16(d[0], d[1], d[2], d[3],
                             ah[tm][0], ah[tm][1], ah[tm][2], ah[tm][3],
                             bl[tn][0], bl[tn][1]);
                    mma_bf16(d[0], d[1], d[2], d[3],
                             al[tm][0], al[tm][1], al[tm][2], al[tm][3],
                             bh[tn][0], bh[tn][1]);
                }
        }
        __syncthreads();
        if (s + 4 < NSTG) load_stage(s + 4);
    }

#pragma unroll
    for (int tm = 0; tm < 2; tm++)
#pragma unroll
        for (int tn = 0; tn < 8; tn++) {
            int r0 = bm + wm + tm * 16 + g;
            int c0 = bn + wn + tn * 8 + 2 * tig;
            float* d = acc[tm][tn];
            *reinterpret_cast<float2*>(&Cout[(long)r0 * D1 + c0]) = make_float2(d[0], d[1]);
            *reinterpret_cast<float2*>(&Cout[(long)(r0 + 8) * D1 + c0]) = make_float2(d[2], d[3]);
        }
}

// ---------------- fp32 GEMM 64x64 tile, double buffered ----------------
__global__ void __launch_bounds__(128) gemm64(const float* __restrict__ A,
                                              const float* __restrict__ B,
                                              float* __restrict__ C, int M, int Nn, int K) {
    __shared__ float As[2][64][8];
    __shared__ float Bs[2][8][64];
    const int tid = threadIdx.x;
    const int bm = blockIdx.y * 64;
    const int bn = blockIdx.x * 64;
    const int arow = tid >> 1, acol = (tid & 1) * 4;
    const int brow = tid >> 4, bcol = (tid & 15) * 4;
    const int ty = (tid >> 4) * 8;
    const int tx = (tid & 15) * 4;

    const float* Ag = A + (long)(bm + arow) * K + acol;
    const float* Bg = B + (long)brow * Nn + bn + bcol;
    uint32_t aS[2] = { smem_u32(&As[0][arow][acol]), smem_u32(&As[1][arow][acol]) };
    uint32_t bS[2] = { smem_u32(&Bs[0][brow][bcol]), smem_u32(&Bs[1][brow][bcol]) };

    float acc[8][4];
#pragma unroll
    for (int i = 0; i < 8; i++)
#pragma unroll
        for (int j = 0; j < 4; j++) acc[i][j] = 0.f;

    cp16(aS[0], Ag);
    cp16(bS[0], Bg);
    cp_commit();

    int stage = 0;
    for (int k0 = 0; k0 < K; k0 += 8) {
        if (k0 + 8 < K) {
            cp16(aS[stage ^ 1], Ag + (k0 + 8));
            cp16(bS[stage ^ 1], Bg + (long)(k0 + 8) * Nn);
            cp_commit();
            cp_wait<1>();
        } else {
            cp_wait<0>();
        }
        __syncthreads();
#pragma unroll
        for (int kk = 0; kk < 8; kk++) {
            float4 b0 = *reinterpret_cast<const float4*>(&Bs[stage][kk][tx]);
            float ra[8];
#pragma unroll
            for (int i = 0; i < 8; i++) ra[i] = As[stage][ty + i][kk];
#pragma unroll
            for (int i = 0; i < 8; i++) {
                acc[i][0] = fmaf(ra[i], b0.x, acc[i][0]);
                acc[i][1] = fmaf(ra[i], b0.y, acc[i][1]);
                acc[i][2] = fmaf(ra[i], b0.z, acc[i][2]);
                acc[i][3] = fmaf(ra[i], b0.w, acc[i][3]);
            }
        }
        __syncthreads();
        stage ^= 1;
    }
#pragma unroll
    for (int i = 0; i < 8; i++) {
        float* cp = C + (long)(bm + ty + i) * Nn + bn + tx;
        *reinterpret_cast<float4*>(cp) = make_float4(acc[i][0], acc[i][1], acc[i][2], acc[i][3]);
    }
}

// ---------------- e_src / e_dst, layer 1 (C=128) ----------------
template <int C>
__global__ void evals_kernel(const float* __restrict__ h, const float* __restrict__ asrc,
                             const float* __restrict__ adst, float* __restrict__ es,
                             float* __restrict__ ed) {
    int g = blockIdx.x * 4 + (threadIdx.x >> 5);
    int lane = threadIdx.x & 31;
    int n = g >> 2;
    int head = g & 3;
    float s1 = 0.f, s2 = 0.f;
    for (int c = lane; c < C; c += 32) {
        float hv = h[(n * HH + head) * C + c];
        s1 = fmaf(hv, asrc[head * C + c], s1);
        s2 = fmaf(hv, adst[head * C + c], s2);
    }
    for (int o = 16; o > 0; o >>= 1) {
        s1 += __shfl_xor_sync(0xffffffffu, s1, o);
        s2 += __shfl_xor_sync(0xffffffffu, s2, o);
    }
    if (lane == 0) { es[n * HH + head] = s1; ed[n * HH + head] = s2; }
}

// ---------------- e_src / e_dst for both halves of hs2 (C=16) ----------------
__global__ void evals2(const float* __restrict__ hs2,
                       const float* __restrict__ ams, const float* __restrict__ amd,
                       const float* __restrict__ ass, const float* __restrict__ asd,
                       float* __restrict__ esm, float* __restrict__ edm,
                       float* __restrict__ ess, float* __restrict__ eds) {
    int n = blockIdx.x;
    int w = threadIdx.x >> 5;
    int lane = threadIdx.x & 31;
    int half = w >> 2, head = w & 3;
    const float* avs = half ? ass : ams;
    const float* avd = half ? asd : amd;
    float s1 = 0.f, s2 = 0.f;
    if (lane < LATD) {
        float hv = hs2[n * 128 + half * 64 + head * LATD + lane];
        s1 = hv * avs[head * LATD + lane];
        s2 = hv * avd[head * LATD + lane];
    }
    for (int o = 8; o > 0; o >>= 1) {
        s1 += __shfl_xor_sync(0xffffffffu, s1, o);
        s2 += __shfl_xor_sync(0xffffffffu, s2, o);
    }
    if (lane == 0) {
        (half ? ess : esm)[n * HH + head] = s1;
        (half ? eds : edm)[n * HH + head] = s2;
    }
}

// ---------------- CSR build ----------------
__global__ void csr_zero() {
    int i = blockIdx.x * blockDim.x + threadIdx.x;
    if (i < NN) g_cur[i] = 0;
}
__global__ void csr_count(const int* __restrict__ dst) {
    int e = blockIdx.x * blockDim.x + threadIdx.x;
    if (e < EE) atomicAdd(&g_cur[dst[e]], 1);
}
__global__ void csr_scan() {
    __shared__ int sh[1024];
    int t = threadIdx.x;
    int c[4]; int s = 0;
#pragma unroll
    for (int u = 0; u < 4; u++) { c[u] = g_cur[t * 4 + u] + 1; s += c[u]; }
    sh[t] = s;
    __syncthreads();
    for (int o = 1; o < 1024; o <<= 1) {
        int v = (t >= o) ? sh[t - o] : 0;
        __syncthreads();
        sh[t] += v;
        __syncthreads();
    }
    int base = sh[t] - s;
#pragma unroll
    for (int u = 0; u < 4; u++) {
        g_off[t * 4 + u] = base;
        g_cur[t * 4 + u] = base;
        base += c[u];
    }
    if (t == 1023) g_off[NN] = sh[1023];
}
// merged edge + self-loop scatter
__global__ void csr_scatter2(const int* __restrict__ src, const int* __restrict__ dst) {
    int e = blockIdx.x * blockDim.x + threadIdx.x;
    if (e < EE) {
        int p = atomicAdd(&g_cur[dst[e]], 1);
        g_srcs[p] = src[e];
    } else if (e < ETOT) {
        int n = e - EE;
        int p = atomicAdd(&g_cur[n], 1);
        g_srcs[p] = n;
    }
}

// ---------------- sparse GAT layer, C=128, concat ----------------
__global__ void spagg_concat(const float* __restrict__ es, const float* __restrict__ ed,
                             const float* __restrict__ h, const float* __restrict__ b,
                             float* __restrict__ out) {
    int dst = blockIdx.x;
    int head = threadIdx.x >> 5;
    int lane = threadIdx.x & 31;
    int beg = g_off[dst], end = g_off[dst + 1];
    float edv = ed[dst * HH + head];

    float m = -INFINITY;
    for (int e = beg + lane; e < end; e += 32)
        m = fmaxf(m, lrelu(es[g_srcs[e] * HH + head] + edv));
    for (int o = 16; o > 0; o >>= 1) m = fmaxf(m, __shfl_xor_sync(0xffffffffu, m, o));

    float den = 0.f;
    for (int e = beg + lane; e < end; e += 32)
        den += __expf(lrelu(es[g_srcs[e] * HH + head] + edv) - m);
    for (int o = 16; o > 0; o >>= 1) den += __shfl_xor_sync(0xffffffffu, den, o);
    float inv = 1.f / (den + 1e-16f);

    float a0 = 0.f, a1 = 0.f, a2 = 0.f, a3 = 0.f;
    for (int e = beg; e < end; e++) {
        int s = g_srcs[e];
        float w = __expf(lrelu(es[s * HH + head] + edv) - m) * inv;
        const float* hp = h + s * D1 + head * C1;
        a0 = fmaf(w, hp[lane], a0);
        a1 = fmaf(w, hp[lane + 32], a1);
        a2 = fmaf(w, hp[lane + 64], a2);
        a3 = fmaf(w, hp[lane + 96], a3);
    }
    float* op = out + dst * D1 + head * C1;
    const float* bp = b + head * C1;
    op[lane]      = a0 + bp[lane];
    op[lane + 32] = a1 + bp[lane + 32];
    op[lane + 64] = a2 + bp[lane + 64];
    op[lane + 96] = a3 + bp[lane + 96];
}

// ---------------- sparse GAT mean layers; 2 edges per iter ----------------
__global__ void spagg_mean2(const float* __restrict__ esm, const float* __restrict__ edm,
                            const float* __restrict__ ess, const float* __restrict__ eds,
                            const float* __restrict__ hs2,
                            const float* __restrict__ bm, const float* __restrict__ bs,
                            float* __restrict__ zm, float* __restrict__ zs) {
    int half = blockIdx.y;
    const float* es = half ? ess : esm;
    const float* ed = half ? eds : edm;
    const float* b  = half ? bs : bm;
    float* out      = half ? zs : zm;
    int dst = blockIdx.x * 4 + (threadIdx.x >> 5);
    int lane = threadIdx.x & 31;
    int sub = lane >> 4;
    int c = lane & 15;
    int beg = g_off[dst], end = g_off[dst + 1];
    float acc = 0.f;
    for (int head = 0; head < HH; head++) {
        float edv = ed[dst * HH + head];
        float m = -INFINITY;
        for (int e = beg + lane; e < end; e += 32)
            m = fmaxf(m, lrelu(es[g_srcs[e] * HH + head] + edv));
        for (int o = 16; o > 0; o >>= 1) m = fmaxf(m, __shfl_xor_sync(0xffffffffu, m, o));
        float den = 0.f;
        for (int e = beg + lane; e < end; e += 32)
            den += __expf(lrelu(es[g_srcs[e] * HH + head] + edv) - m);
        for (int o = 16; o > 0; o >>= 1) den += __shfl_xor_sync(0xffffffffu, den, o);
        float inv = 1.f / (den + 1e-16f);
        for (int e = beg; e < end; e += 2) {
            int ee = e + sub;
            if (ee < end) {
                int s = g_srcs[ee];
                float w = __expf(lrelu(es[s * HH + head] + edv) - m) * inv;
                acc = fmaf(w, hs2[s * 128 + half * 64 + head * LATD + c], acc);
            }
        }
    }
    acc += __shfl_down_sync(0xffffffffu, acc, 16);
    if (lane < LATD) out[dst * LATD + lane] = acc * 0.25f + b[lane];
}

// ---------------- fused radix sort + weights + scalar scans ----------------
__device__ __forceinline__ float unmap_key(uint32_t kk) {
    uint32_t m = ~kk;
    return __uint_as_float((m & 0x80000000u) ? (m ^ 0x80000000u) : ~m);
}

__global__ void __launch_bounds__(1024) sortF(const float* __restrict__ esA,
                                              const float* __restrict__ esB) {
    extern __shared__ uint32_t sm[];
    uint32_t* KA = sm;
    uint32_t* VA = sm + 4096;
    uint32_t* KB = sm + 8192;
    uint32_t* VB = sm + 12288;
    uint32_t* WH = sm + 16384;

    int slot = blockIdx.x;
    int t = threadIdx.x;
    int w = t >> 5, lane = t & 31;
    const float* es = (slot < 4) ? esA : esB;
    int head = slot & 3;

    for (int i = t; i < NN; i += 1024) {
        uint32_t b = __float_as_uint(es[i * HH + head]);
        uint32_t m = (b & 0x80000000u) ? ~b : (b | 0x80000000u);
        KA[i] = ~m;
        VA[i] = (uint32_t)i;
    }
    __syncthreads();

    uint32_t *KI = KA, *VI = VA, *KO = KB, *VO = VB;

#pragma unroll
    for (int pass = 0; pass < 4; pass++) {
        int shift = pass * 8;
        for (int i = t; i < 32 * 257; i += 1024) WH[i] = 0;
        __syncthreads();

        uint32_t k_[4], v_[4], d_[4], lr_[4];
#pragma unroll
        for (int r = 0; r < 4; r++) {
            int idx = w * 128 + r * 32 + lane;
            k_[r] = KI[idx];
            v_[r] = VI[idx];
            d_[r] = (k_[r] >> shift) & 255u;
            unsigned mask = __match_any_sync(0xffffffffu, d_[r]);
            int phys = w * 257 + (int)d_[r];
            uint32_t before = WH[phys];
            __syncwarp();
            lr_[r] = before + (uint32_t)__popc(mask & ((1u << lane) - 1u));
            int leader = __ffs((int)mask) - 1;
            if (lane == leader) WH[phys] = before + (uint32_t)__popc(mask);
            __syncwarp();
        }
        __syncthreads();

        uint32_t loc[8], sum = 0;
        int dbase = t >> 2;
        int wbase = (t & 3) * 8;
#pragma unroll
        for (int u = 0; u < 8; u++) {
            loc[u] = WH[(wbase + u) * 257 + dbase];
            sum += loc[u];
        }
        uint32_t totU;
        uint32_t incl = bscan<1024, uint32_t>(sum, totU);
        uint32_t run = incl - sum;
        __syncthreads();
#pragma unroll
        for (int u = 0; u < 8; u++) {
            uint32_t c0 = loc[u];
            WH[(wbase + u) * 257 + dbase] = run;
            run += c0;
        }
        __syncthreads();

#pragma unroll
        for (int r = 0; r < 4; r++) {
            uint32_t dest = WH[w * 257 + (int)d_[r]] + lr_[r];
            KO[dest] = k_[r];
            VO[dest] = v_[r];
        }
        __syncthreads();
        uint32_t* tk = KI; KI = KO; KO = tk;
        uint32_t* tv = VI; VI = VO; VO = tv;
    }

    float mb = unmap_key(KI[0]);
    int base = t * 4;
    float w1v[4], w2v[4];
    float loc1 = 0.f, loc2 = 0.f;
#pragma unroll
    for (int u = 0; u < 4; u++) {
        int i = base + u;
        float kv = unmap_key(KI[i]);
        g_skey[slot * NN + i] = kv;
        g_perm[slot * NN + i] = (int)VI[i];
        float d = kv - mb;
        w1v[u] = __expf(d);
        w2v[u] = __expf(0.2f * d);
        g_w1s[slot * NN + i] = w1v[u];
        g_w2s[slot * NN + i] = w2v[u];
        loc1 += w1v[u];
        loc2 += w2v[u];
    }
    float tot1, tot2;
    float incl1 = bscan<1024, float>(loc1, tot1);
    float incl2 = bscan<1024, float>(loc2, tot2);
    float s = incl1 - loc1;
#pragma unroll
    for (int u = 0; u < 4; u++) { g_s1[slot * (NN + 1) + base + u] = s; s += w1v[u]; }
    if (t == 1023) g_s1[slot * (NN + 1) + NN] = tot1;
    float a2 = tot2 - incl2;
#pragma unroll
    for (int u = 3; u >= 0; u--) { a2 += w2v[u]; g_s2[slot * (NN + 1) + base + u] = a2; }
    if (t == 0) { g_s2[slot * (NN + 1) + NN] = 0.f; g_Mb[slot] = mb; }
}

// ---------------- fused gather + chunk-local scans ----------------
__global__ void __launch_bounds__(C1) vscanC(const float* __restrict__ h) {
    int head = blockIdx.x, ch = blockIdx.y, c = threadIdx.x;
    const int*   perm = g_perm + head * NN + ch * CHLC;
    const float* w1p  = g_w1s + head * NN + ch * CHLC;
    const float* w2p  = g_w2s + head * NN + ch * CHLC;
    long rowbase = (long)head * (NN + 1) + ch * CHLC;
    float hv[CHLC];
    float s = 0.f;
#pragma unroll
    for (int r = 0; r < CHLC; r++) {
        int p = perm[r];
        hv[r] = h[(p * HH + head) * C1 + c];
        s = fmaf(w1p[r], hv[r], s);
        g_P1[(rowbase + r + 1) * C1 + c] = s;
    }
    g_T1[(head * NCHC + ch) * C1 + c] = s;
    s = 0.f;
#pragma unroll
    for (int r = CHLC - 1; r >= 0; r--) {
        s = fmaf(w2p[r], hv[r], s);
        g_S2[(rowbase + r) * C1 + c] = s;
    }
    g_T2[(head * NCHC + ch) * C1 + c] = s;
}

__global__ void __launch_bounds__(128) vscanL(const float* __restrict__ hs2) {
    int slot = blockIdx.x;
    int grp = threadIdx.x >> 4;
    int c = threadIdx.x & 15;
    int ch = blockIdx.y * 8 + grp;
    int half = slot >> 2, head = slot & 3;
    const int*   perm = g_perm + slot * NN + ch * CHLL;
    const float* w1p  = g_w1s + slot * NN + ch * CHLL;
    const float* w2p  = g_w2s + slot * NN + ch * CHLL;
    long rowbase = (long)slot * (NN + 1) + ch * CHLL;
    float hv[CHLL];
    float s = 0.f;
#pragma unroll
    for (int r = 0; r < CHLL; r++) {
        int p = perm[r];
        hv[r] = hs2[p * 128 + half * 64 + head * LATD + c];
        s = fmaf(w1p[r], hv[r], s);
        g_P1[(rowbase + r + 1) * LATD + c] = s;
    }
    g_T1[(slot * NCHL + ch) * LATD + c] = s;
    s = 0.f;
#pragma unroll
    for (int r = CHLL - 1; r >= 0; r--) {
        s = fmaf(w2p[r], hv[r], s);
        g_S2[(rowbase + r) * LATD + c] = s;
    }
    g_T2[(slot * NCHL + ch) * LATD + c] = s;
}

// ---------------- chunk-total prefix/suffix (in place) ----------------
template <int C, int NCHX>
__global__ void tpre_kernel() {
    int slot = blockIdx.x, c = blockIdx.y, t = threadIdx.x;
    float v1 = g_T1[(slot * NCHX + t) * C + c];
    float v2 = g_T2[(slot * NCHX + t) * C + c];
    float tot1, tot2;
    float i1 = bscan<NCHX, float>(v1, tot1);
    float i2 = bscan<NCHX, float>(v2, tot2);
    g_T1[(slot * NCHX + t) * C + c] = i1 - v1;
    g_T2[(slot * NCHX + t) * C + c] = tot2 - i2;
}

__device__ __forceinline__ int bsearch_gt(const float* sk, float t) {
    int lo = 0, hi = NN;
    while (lo < hi) {
        int mid = (lo + hi) >> 1;
        if (sk[mid] > t) lo = mid + 1; else hi = mid;
    }
    return lo;
}

// ---------------- dense GAT layer, C=128, concat ----------------
__global__ void dense_concat(const float* __restrict__ ed, const float* __restrict__ b,
                             float* __restrict__ out) {
    int i = blockIdx.x;
    int head = blockIdx.y;
    int c = threadIdx.x;
    float a = ed[i * HH + head];
    int k = bsearch_gt(g_skey + head * NN, -a);
    float am = a + g_Mb[head];
    float A1 = __expf(am), A2 = __expf(0.2f * am);
    float s1k = g_s1[head * (NN + 1) + k];
    float s2k = g_s2[head * (NN + 1) + k];
    float den = A1 * s1k + A2 * s2k;
    float p1v = 0.f, s2v = 0.f;
    if (k > 0) {
        int q = (k - 1) / CHLC;
        p1v = g_T1[(head * NCHC + q) * C1 + c] + g_P1[((long)head * (NN + 1) + k) * C1 + c];
    }
    if (k < NN) {
        int q = k / CHLC;
        s2v = g_T2[(head * NCHC + q) * C1 + c] + g_S2[((long)head * (NN + 1) + k) * C1 + c];
    }
    float num = A1 * p1v + A2 * s2v;
    out[i * D1 + head * C1 + c] = num / den + b[head * C1 + c];
}

// ---------------- dense GAT mean layers, both halves in one launch ----------------
__global__ void dense_mean2(const float* __restrict__ edm, const float* __restrict__ eds,
                            const float* __restrict__ bm, const float* __restrict__ bs,
                            float* __restrict__ zm, float* __restrict__ zs) {
    __shared__ float sh[64];
    int i = blockIdx.x;
    int half = blockIdx.y;
    int t = threadIdx.x;
    int head = t >> 4;
    int c = t & 15;
    int slot = half * 4 + head;
    const float* ed = half ? eds : edm;
    float a = ed[i * HH + head];
    int k = bsearch_gt(g_skey + slot * NN, -a);
    float am = a + g_Mb[slot];
    float A1 = __expf(am), A2 = __expf(0.2f * am);
    float den = A1 * g_s1[slot * (NN + 1) + k] + A2 * g_s2[slot * (NN + 1) + k];
    float p1v = 0.f, s2v = 0.f;
    if (k > 0) {
        int q = (k - 1) / CHLL;
        p1v = g_T1[(slot * NCHL + q) * LATD + c] + g_P1[((long)slot * (NN + 1) + k) * LATD + c];
    }
    if (k < NN) {
        int q = k / CHLL;
        s2v = g_T2[(slot * NCHL + q) * LATD + c] + g_S2[((long)slot * (NN + 1) + k) * LATD + c];
    }
    float num = A1 * p1v + A2 * s2v;
    sh[t] = num / den;
    __syncthreads();
    if (t < LATD) {
        float* out = half ? zs : zm;
        const float* b = half ? bs : bm;
        out[i * LATD + t] = 0.25f * (sh[t] + sh[16 + t] + sh[32 + t] + sh[48 + t]) + b[t];
    }
}

// ---------------- launch ----------------
extern "C" void kernel_launch(void* const* d_in, const int* in_sizes, int n_in,
                              void* d_out, int out_size) {
    const float* x   = (const float*)d_in[0];
    const int*   ei  = (const int*)d_in[1];
    const float* W1  = (const float*)d_in[3];
    const float* a1s = (const float*)d_in[4];
    const float* a1d = (const float*)d_in[5];
    const float* b1  = (const float*)d_in[6];
    const float* Wm  = (const float*)d_in[7];
    const float* ams = (const float*)d_in[8];
    const float* amd = (const float*)d_in[9];
    const float* bm  = (const float*)d_in[10];
    const float* Ws  = (const float*)d_in[11];
    const float* ass = (const float*)d_in[12];
    const float* asd = (const float*)d_in[13];
    const float* bs  = (const float*)d_in[14];
    float* out = (float*)d_out;
    float* z1m = out;
    float* z1s = out + NN * LATD;
    float* z2m = out + 2 * NN * LATD;
    float* z2s = out + 3 * NN * LATD;

    const int* src = ei;
    const int* dst = ei + EE;

    float *h1, *x1, *x2, *hs2a, *hs2b, *Wc;
    float *es1, *ed1;
    float *es2am, *ed2am, *es2as, *ed2as, *es2bm, *ed2bm, *es2bs, *ed2bs;
    cudaGetSymbolAddress((void**)&h1,    g_h1);
    cudaGetSymbolAddress((void**)&x1,    g_x1);
    cudaGetSymbolAddress((void**)&x2,    g_x2);
    cudaGetSymbolAddress((void**)&hs2a,  g_hs2a);
    cudaGetSymbolAddress((void**)&hs2b,  g_hs2b);
    cudaGetSymbolAddress((void**)&Wc,    g_Wc);
    cudaGetSymbolAddress((void**)&es1,   g_es1);
    cudaGetSymbolAddress((void**)&ed1,   g_ed1);
    cudaGetSymbolAddress((void**)&es2am, g_es2am);
    cudaGetSymbolAddress((void**)&ed2am, g_ed2am);
    cudaGetSymbolAddress((void**)&es2as, g_es2as);
    cudaGetSymbolAddress((void**)&ed2as, g_ed2as);
    cudaGetSymbolAddress((void**)&es2bm, g_es2bm);
    cudaGetSymbolAddress((void**)&ed2bm, g_ed2bm);
    cudaGetSymbolAddress((void**)&es2bs, g_es2bs);
    cudaGetSymbolAddress((void**)&ed2bs, g_ed2bs);

    static cudaStream_t sA = nullptr, sB = nullptr;
    static cudaEvent_t ev0 = nullptr, evW = nullptr, evMain = nullptr, evA = nullptr, evB = nullptr;
    if (sA == nullptr) {
        cudaStreamCreateWithFlags(&sA, cudaStreamNonBlocking);
        cudaStreamCreateWithFlags(&sB, cudaStreamNonBlocking);
        cudaEventCreateWithFlags(&ev0,    cudaEventDisableTiming);
        cudaEventCreateWithFlags(&evW,    cudaEventDisableTiming);
        cudaEventCreateWithFlags(&evMain, cudaEventDisableTiming);
        cudaEventCreateWithFlags(&evA,    cudaEventDisableTiming);
        cudaEventCreateWithFlags(&evB,    cudaEventDisableTiming);
        cudaFuncSetAttribute(mma_gemm, cudaFuncAttributeMaxDynamicSharedMemorySize, NPIPE * STG_B);
        cudaFuncSetAttribute(sortF, cudaFuncAttributeMaxDynamicSharedMemorySize, SORT_SMEM_B);
    }

    // fork: CSR build (sA) + W-side conversions (sB) overlap convA (main)
    cudaEventRecord(ev0, 0);
    cudaStreamWaitEvent(sA, ev0, 0);
    cudaStreamWaitEvent(sB, ev0, 0);
    csr_zero<<<16, 256, 0, sA>>>();
    csr_count<<<(EE + 255) / 256, 256, 0, sA>>>(dst);
    csr_scan<<<1, 1024, 0, sA>>>();
    csr_scatter2<<<(ETOT + 255) / 256, 256, 0, sA>>>(src, dst);

    convBt_kernel<<<dim3(KP / 32, D1 / 32), dim3(32, 8), 0, sB>>>(W1);
    buildWc<<<(D1 * 64 + 255) / 256, 256, 0, sB>>>(Wm, Ws);
    cudaEventRecord(evW, sB);

    convA_kernel<<<1024, 256>>>(x);
    cudaStreamWaitEvent(0, evW, 0);
    mma_gemm<<<dim3(D1 / 128, NN / 128), 256, NPIPE * STG_B>>>(h1);
    evals_kernel<C1><<<NN, 128>>>(h1, a1s, a1d, es1, ed1);
    cudaEventRecord(evMain, 0);

    // ---- branch A (sparse) ----
    cudaStreamWaitEvent(sA, evMain, 0);
    spagg_concat<<<NN, 128, 0, sA>>>(es1, ed1, h1, b1, x1);
    gemm64<<<dim3(2, NN / 64), 128, 0, sA>>>(x1, Wc, hs2a, NN, 128, D1);
    evals2<<<NN, 256, 0, sA>>>(hs2a, ams, amd, ass, asd, es2am, ed2am, es2as, ed2as);
    spagg_mean2<<<dim3(NN / 4, 2), 128, 0, sA>>>(es2am, ed2am, es2as, ed2as, hs2a,
                                                 bm, bs, z1m, z1s);
    cudaEventRecord(evA, sA);

    // ---- branch B (dense, rank-1 softmax) ----
    cudaStreamWaitEvent(sB, evMain, 0);
    sortF<<<4, 1024, SORT_SMEM_B, sB>>>(es1, es1);
    vscanC<<<dim3(HH, NCHC), C1, 0, sB>>>(h1);
    tpre_kernel<C1, NCHC><<<dim3(HH, C1), NCHC, 0, sB>>>();
    dense_concat<<<dim3(NN, HH), C1, 0, sB>>>(ed1, b1, x2);
    gemm64<<<dim3(2, NN / 64), 128, 0, sB>>>(x2, Wc, hs2b, NN, 128, D1);
    evals2<<<NN, 256, 0, sB>>>(hs2b, ams, amd, ass, asd, es2bm, ed2bm, es2bs, ed2bs);
    sortF<<<NSLOT, 1024, SORT_SMEM_B, sB>>>(es2bm, es2bs);
    vscanL<<<dim3(NSLOT, NCHL / 8), 128, 0, sB>>>(hs2b);
    tpre_kernel<LATD, NCHL><<<dim3(NSLOT, LATD), NCHL, 0, sB>>>();
    dense_mean2<<<dim3(NN, 2), 64, 0, sB>>>(ed2bm, ed2bs, bm, bs, z2m, z2s);
    cudaEventRecord(evB, sB);

    // join
    cudaStreamWaitEvent(0, evA, 0);
    cudaStreamWaitEvent(0, evB, 0);
}

// round 11
// speedup vs baseline: 16.9765x; 1.0173x over previous
#include <cuda_runtime.h>
#include <cuda_bf16.h>
#include <math.h>
#include <stdint.h>

#define NN   4096
#define EE   131072
#define INF_ 3000
#define HH   4
#define C1   128
#define D1   512   // H*C1
#define LATD 16
#define D2   64    // H*LATD
#define ETOT (EE + NN)
#define NCHC 128   // C1 scan chunks
#define CHLC 32    // C1 chunk length
#define NCHL 256   // LATD scan chunks
#define CHLL 16    // LATD chunk length
#define KP   3008  // padded K for MMA (94*32)
#define KST  32    // K per pipeline stage
#define NSTG (KP / KST)
#define ROWP 40    // padded smem row length in bf16 (32 + 8)
#define TILE_B (128 * ROWP * 2)
#define STG_B  (4 * TILE_B)
#define NPIPE 5    // pipeline stages
#define NSLOT 8    // sort slots (2 halves x 4 heads)
#define SORT_SMEM_U32 (4 * 4096 + 32 * 257)
#define SORT_SMEM_B   (SORT_SMEM_U32 * 4)

// ---------------- scratch (static device globals; no allocation) ----------------
__device__ float g_h1[NN * D1];
__device__ float g_x1[NN * D1];
__device__ float g_x2[NN * D1];
__device__ float g_hs2a[NN * 128];
__device__ float g_hs2b[NN * 128];
__device__ float g_Wc[D1 * 128];
__device__ float g_es1[NN * HH];
__device__ float g_ed1[NN * HH];
__device__ float g_es2am[NN * HH];
__device__ float g_ed2am[NN * HH];
__device__ float g_es2as[NN * HH];
__device__ float g_ed2as[NN * HH];
__device__ float g_es2bm[NN * HH];
__device__ float g_ed2bm[NN * HH];
__device__ float g_es2bs[NN * HH];
__device__ float g_ed2bs[NN * HH];
__device__ int   g_off[NN + 1];
__device__ int   g_cur[NN];
__device__ int   g_srcs[ETOT];
__device__ float g_skey[NSLOT * NN];
__device__ int   g_perm[NSLOT * NN];
__device__ float g_w1s[NSLOT * NN];
__device__ float g_w2s[NSLOT * NN];
__device__ float g_Mb[NSLOT];
__device__ float g_s1[NSLOT * (NN + 1)];
__device__ float g_s2[NSLOT * (NN + 1)];
__device__ float g_P1[HH * (NN + 1) * C1];
__device__ float g_S2[HH * (NN + 1) * C1];
__device__ float g_T1[65536];
__device__ float g_T2[65536];
// bf16 hi/lo split operands for HMMA GEMM
__device__ __align__(256) __nv_bfloat16 g_Ahi[(long)NN * KP];
__device__ __align__(256) __nv_bfloat16 g_Alo[(long)NN * KP];
__device__ __align__(256) __nv_bfloat16 g_Bhi[(long)D1 * KP];
__device__ __align__(256) __nv_bfloat16 g_Blo[(long)D1 * KP];

__device__ __forceinline__ float lrelu(float v) { return v > 0.f ? v : 0.2f * v; }

// ---------------- PTX helpers ----------------
__device__ __forceinline__ uint32_t smem_u32(const void* p) {
    return (uint32_t)__cvta_generic_to_shared(p);
}
__device__ __forceinline__ void cp16(uint32_t s, const void* g) {
    asm volatile("cp.async.cg.shared.global [%0], [%1], 16;\n" :: "r"(s), "l"(g));
}
__device__ __forceinline__ void cp_commit() {
    asm volatile("cp.async.commit_group;\n" ::: "memory");
}
template <int W>
__device__ __forceinline__ void cp_wait() {
    asm volatile("cp.async.wait_group %0;\n" :: "n"(W) : "memory");
}

__device__ __forceinline__ void mma_bf16(float& d0, float& d1, float& d2, float& d3,
                                         uint32_t a0, uint32_t a1, uint32_t a2, uint32_t a3,
                                         uint32_t b0, uint32_t b1) {
    asm volatile(
        "mma.sync.aligned.m16n8k16.row.col.f32.bf16.bf16.f32 "
        "{%0,%1,%2,%3}, {%4,%5,%6,%7}, {%8,%9}, {%0,%1,%2,%3};"
        : "+f"(d0), "+f"(d1), "+f"(d2), "+f"(d3)
        : "r"(a0), "r"(a1), "r"(a2), "r"(a3), "r"(b0), "r"(b1));
}

// ---------------- shuffle-based block scan (NT threads, NT%32==0) ----------------
template <int NT, typename T>
__device__ __forceinline__ T bscan(T v, T& total) {
    __shared__ T ws[NT / 32];
    int t = threadIdx.x, lane = t & 31, w = t >> 5;
    __syncthreads();
    T x = v;
#pragma unroll
    for (int o = 1; o < 32; o <<= 1) {
        T y = __shfl_up_sync(0xffffffffu, x, o);
        if (lane >= o) x += y;
    }
    if (lane == 31) ws[w] = x;
    __syncthreads();
    if (t < NT / 32) {
        T s = ws[t];
#pragma unroll
        for (int o = 1; o < NT / 32; o <<= 1) {
            T y = __shfl_up_sync((NT / 32 < 32) ? ((1u << (NT / 32)) - 1u) : 0xffffffffu, s, o);
            if (t >= o) s += y;
        }
        ws[t] = s;
    }
    __syncthreads();
    T off = (w == 0) ? (T)0 : ws[w - 1];
    total = ws[NT / 32 - 1];
    return x + off;
}

// ---------------- fp32 -> bf16 hi/lo conversion of x ----------------
struct __align__(16) bf8 { __nv_bfloat16 v[8]; };
__global__ void convA_kernel(const float* __restrict__ x) {
    const long nch = (long)NN * (KP / 8);
    for (long id = (long)blockIdx.x * blockDim.x + threadIdx.x; id < nch;
         id += (long)gridDim.x * blockDim.x) {
        long row = id / (KP / 8);
        int c = (int)(id % (KP / 8));
        bf8 hi, lo;
        if (c < INF_ / 8) {
            const float* xp = x + row * INF_ + c * 8;
#pragma unroll
            for (int j = 0; j < 8; j++) {
                float v = xp[j];
                __nv_bfloat16 h = __float2bfloat16(v);
                hi.v[j] = h;
                lo.v[j] = __float2bfloat16(v - __bfloat162float(h));
            }
        } else {
#pragma unroll
            for (int j = 0; j < 8; j++) { hi.v[j] = __float2bfloat16(0.f); lo.v[j] = hi.v[j]; }
        }
        *reinterpret_cast<bf8*>(&g_Ahi[row * KP + c * 8]) = hi;
        *reinterpret_cast<bf8*>(&g_Alo[row * KP + c * 8]) = lo;
    }
}

__global__ void convBt_kernel(const float* __restrict__ W) {
    __shared__ float t[32][33];
    int kb = blockIdx.x * 32, nb = blockIdx.y * 32;
    int tx = threadIdx.x, ty = threadIdx.y;
#pragma unroll
    for (int r = 0; r < 32; r += 8) {
        int k = kb + ty + r, n = nb + tx;
        t[ty + r][tx] = (k < INF_) ? W[(long)k * D1 + n] : 0.f;
    }
    __syncthreads();
#pragma unroll
    for (int r = 0; r < 32; r += 8) {
        int n = nb + ty + r, k = kb + tx;
        float v = t[tx][ty + r];
        __nv_bfloat16 h = __float2bfloat16(v);
        g_Bhi[(long)n * KP + k] = h;
        g_Blo[(long)n * KP + k] = __float2bfloat16(v - __bfloat162float(h));
    }
}

// Wc = [Wm | Ws] : [512][128]
__global__ void buildWc(const float* __restrict__ Wm, const float* __restrict__ Ws) {
    int i = blockIdx.x * 256 + threadIdx.x;
    if (i < D1 * 64) {
        int k = i >> 6, n = i & 63;
        g_Wc[k * 128 + n] = Wm[i];
        g_Wc[k * 128 + 64 + n] = Ws[i];
    }
}

// ---------------- HMMA GEMM (h1 = x @ W1) with fused layer-1 evals ----------------
// Each CTA covers 128 rows x one full head (blockIdx.x == head), so es1/ed1
// for its rows are computed CTA-locally in the epilogue.
__global__ void __launch_bounds__(256) mma_gemm(float* __restrict__ Cout,
                                                const float* __restrict__ asrc,
                                                const float* __restrict__ adst,
                                                float* __restrict__ es,
                                                float* __restrict__ ed) {
    extern __shared__ char smem[];
    const int tid = threadIdx.x;
    const int wid = tid >> 5, lane = tid & 31;
    const int g = lane >> 2, tig = lane & 3;
    const int wm = (wid & 3) * 32;
    const int wn = (wid >> 2) * 64;
    const int head = blockIdx.x;
    const int bn = head * 128;
    const int bm = blockIdx.y * 128;
    uint32_t sb = smem_u32(smem);

    float acc[2][8][4];
#pragma unroll
    for (int i = 0; i < 2; i++)
#pragma unroll
        for (int j = 0; j < 8; j++)
#pragma unroll
            for (int q = 0; q < 4; q++) acc[i][j][q] = 0.f;

    auto load_stage = [&](int s) {
        uint32_t base = sb + (uint32_t)(s % NPIPE) * STG_B;
        long gk = (long)s * KST;
#pragma unroll
        for (int t = 0; t < 8; t++) {
            int id = tid + t * 256;
            int mat = id >> 9;
            int r = (id >> 2) & 127;
            int c16 = id & 3;
            uint32_t so = base + (uint32_t)mat * TILE_B + (uint32_t)(r * 80 + c16 * 16);
            const __nv_bfloat16* gp;
            if (mat == 0)      gp = &g_Ahi[(long)(bm + r) * KP + gk + c16 * 8];
            else if (mat == 1) gp = &g_Alo[(long)(bm + r) * KP + gk + c16 * 8];
            else if (mat == 2) gp = &g_Bhi[(long)(bn + r) * KP + gk + c16 * 8];
            else               gp = &g_Blo[(long)(bn + r) * KP + gk + c16 * 8];
            cp16(so, gp);
        }
        cp_commit();
    };

    load_stage(0);
    load_stage(1);
    load_stage(2);
    load_stage(3);

    for (int s = 0; s < NSTG; s++) {
        int pending_after = NSTG - 1 - s;
        if (pending_after >= 3)      cp_wait<3>();
        else if (pending_after == 2) cp_wait<2>();
        else if (pending_after == 1) cp_wait<1>();
        else                         cp_wait<0>();
        __syncthreads();
        const char* stg = smem + (s % NPIPE) * STG_B;
        const uint32_t* Ah = (const uint32_t*)(stg);
        const uint32_t* Al = (const uint32_t*)(stg + TILE_B);
        const uint32_t* Bh = (const uint32_t*)(stg + 2 * TILE_B);
        const uint32_t* Bl = (const uint32_t*)(stg + 3 * TILE_B);
#pragma unroll
        for (int ks = 0; ks < 2; ks++) {
            int kh = ks * 8;
            uint32_t ah[2][4], al[2][4], bh[8][2], bl[8][2];
#pragma unroll
            for (int tm = 0; tm < 2; tm++) {
                int r = wm + tm * 16 + g;
                ah[tm][0] = Ah[r * 20 + kh + tig];
                ah[tm][1] = Ah[(r + 8) * 20 + kh + tig];
                ah[tm][2] = Ah[r * 20 + kh + 4 + tig];
                ah[tm][3] = Ah[(r + 8) * 20 + kh + 4 + tig];
                al[tm][0] = Al[r * 20 + kh + tig];
                al[tm][1] = Al[(r + 8) * 20 + kh + tig];
                al[tm][2] = Al[r * 20 + kh + 4 + tig];
                al[tm][3] = Al[(r + 8) * 20 + kh + 4 + tig];
            }
#pragma unroll
            for (int tn = 0; tn < 8; tn++) {
                int n = wn + tn * 8 + g;
                bh[tn][0] = Bh[n * 20 + kh + tig];
                bh[tn][1] = Bh[n * 20 + kh + 4 + tig];
                bl[tn][0] = Bl[n * 20 + kh + tig];
                bl[tn][1] = Bl[n * 20 + kh + 4 + tig];
            }
#pragma unroll
            for (int tm = 0; tm < 2; tm++)
#pragma unroll
                for (int tn = 0; tn < 8; tn++) {
                    float* d = acc[tm][tn];
                    mma_bf16(d[0], d[1], d[2], d[3],
                             ah[tm][0], ah[tm][1], ah[tm][2], ah[tm][3],
                             bh[tn][0], bh[tn][1]);
                    mma_bf16(d[0], d[1], d[2], d[3],
                             ah[tm][0], ah[tm][1], ah[tm][2], ah[tm][3],
                             bl[tn][0], bl[tn][1]);
                    mma_bf16(d[0], d[1], d[2], d[3],
                             al[tm][0], al[tm][1], al[tm][2], al[tm][3],
                             bh[tn][0], bh[tn][1]);
                }
        }
        __syncthreads();
        if (s + 4 < NSTG) load_stage(s + 4);
    }

    // write h1 tile
#pragma unroll
    for (int tm = 0; tm < 2; tm++)
#pragma unroll
        for (int tn = 0; tn < 8; tn++) {
            int r0 = bm + wm + tm * 16 + g;
            int c0 = bn + wn + tn * 8 + 2 * tig;
            float* d = acc[tm][tn];
            *reinterpret_cast<float2*>(&Cout[(long)r0 * D1 + c0]) = make_float2(d[0], d[1]);
            *reinterpret_cast<float2*>(&Cout[(long)(r0 + 8) * D1 + c0]) = make_float2(d[2], d[3]);
        }

    // fused evals epilogue: es/ed for this CTA's 128 rows, this head
    float* esbuf = (float*)smem;
    float* edbuf = esbuf + 128;
    if (tid < 128) { esbuf[tid] = 0.f; edbuf[tid] = 0.f; }
    __syncthreads();
    const float* asv = asrc + head * C1;
    const float* adv = adst + head * C1;
    float pes[2][2] = {{0.f, 0.f}, {0.f, 0.f}};
    float ped[2][2] = {{0.f, 0.f}, {0.f, 0.f}};
#pragma unroll
    for (int tm = 0; tm < 2; tm++)
#pragma unroll
        for (int tn = 0; tn < 8; tn++) {
            int c0 = wn + tn * 8 + 2 * tig;
            float a0s = asv[c0], a1s_ = asv[c0 + 1];
            float a0d = adv[c0], a1d_ = adv[c0 + 1];
            float* d = acc[tm][tn];
            pes[tm][0] = fmaf(d[0], a0s, fmaf(d[1], a1s_, pes[tm][0]));
            pes[tm][1] = fmaf(d[2], a0s, fmaf(d[3], a1s_, pes[tm][1]));
            ped[tm][0] = fmaf(d[0], a0d, fmaf(d[1], a1d_, ped[tm][0]));
            ped[tm][1] = fmaf(d[2], a0d, fmaf(d[3], a1d_, ped[tm][1]));
        }
#pragma unroll
    for (int off = 1; off <= 2; off <<= 1)
#pragma unroll
        for (int tm = 0; tm < 2; tm++)
#pragma unroll
            for (int q = 0; q < 2; q++) {
                pes[tm][q] += __shfl_xor_sync(0xffffffffu, pes[tm][q], off);
                ped[tm][q] += __shfl_xor_sync(0xffffffffu, ped[tm][q], off);
            }
    if (tig == 0) {
#pragma unroll
        for (int tm = 0; tm < 2; tm++) {
            int r0 = wm + tm * 16 + g;
            atomicAdd(&esbuf[r0], pes[tm][0]);
            atomicAdd(&esbuf[r0 + 8], pes[tm][1]);
            atomicAdd(&edbuf[r0], ped[tm][0]);
            atomicAdd(&edbuf[r0 + 8], ped[tm][1]);
        }
    }
    __syncthreads();
    if (tid < 128) {
        es[(bm + tid) * HH + head] = esbuf[tid];
        ed[(bm + tid) * HH + head] = edbuf[tid];
    }
}

// ---------------- fp32 GEMM 64x64 (Nn=128) with fused evals2 epilogue ----------------
__global__ void __launch_bounds__(128) gemm64e(const float* __restrict__ A,
                                               const float* __restrict__ B,
                                               float* __restrict__ C, int K,
                                               const float* __restrict__ ams,
                                               const float* __restrict__ amd,
                                               const float* __restrict__ ass,
                                               const float* __restrict__ asd,
                                               float* __restrict__ esm, float* __restrict__ edm,
                                               float* __restrict__ ess, float* __restrict__ eds) {
    const int Nn = 128;
    __shared__ float As[2][64][8];
    __shared__ float Bs[2][8][64];
    __shared__ float esb[64][4], edb[64][4];
    const int tid = threadIdx.x;
    const int bm = blockIdx.y * 64;
    const int bn = blockIdx.x * 64;
    const int arow = tid >> 1, acol = (tid & 1) * 4;
    const int brow = tid >> 4, bcol = (tid & 15) * 4;
    const int ty = (tid >> 4) * 8;
    const int tx = (tid & 15) * 4;

    const float* Ag = A + (long)(bm + arow) * K + acol;
    const float* Bg = B + (long)brow * Nn + bn + bcol;
    uint32_t aS[2] = { smem_u32(&As[0][arow][acol]), smem_u32(&As[1][arow][acol]) };
    uint32_t bS[2] = { smem_u32(&Bs[0][brow][bcol]), smem_u32(&Bs[1][brow][bcol]) };

    float acc[8][4];
#pragma unroll
    for (int i = 0; i < 8; i++)
#pragma unroll
        for (int j = 0; j < 4; j++) acc[i][j] = 0.f;

    cp16(aS[0], Ag);
    cp16(bS[0], Bg);
    cp_commit();

    int stage = 0;
    for (int k0 = 0; k0 < K; k0 += 8) {
        if (k0 + 8 < K) {
            cp16(aS[stage ^ 1], Ag + (k0 + 8));
            cp16(bS[stage ^ 1], Bg + (long)(k0 + 8) * Nn);
            cp_commit();
            cp_wait<1>();
        } else {
            cp_wait<0>();
        }
        __syncthreads();
#pragma unroll
        for (int kk = 0; kk < 8; kk++) {
            float4 b0 = *reinterpret_cast<const float4*>(&Bs[stage][kk][tx]);
            float ra[8];
#pragma unroll
            for (int i = 0; i < 8; i++) ra[i] = As[stage][ty + i][kk];
#pragma unroll
            for (int i = 0; i < 8; i++) {
                acc[i][0] = fmaf(ra[i], b0.x, acc[i][0]);
                acc[i][1] = fmaf(ra[i], b0.y, acc[i][1]);
                acc[i][2] = fmaf(ra[i], b0.z, acc[i][2]);
                acc[i][3] = fmaf(ra[i], b0.w, acc[i][3]);
            }
        }
        __syncthreads();
        stage ^= 1;
    }
#pragma unroll
    for (int i = 0; i < 8; i++) {
        float* cp = C + (long)(bm + ty + i) * Nn + bn + tx;
        *reinterpret_cast<float4*>(cp) = make_float4(acc[i][0], acc[i][1], acc[i][2], acc[i][3]);
    }

    // fused evals2 epilogue: this CTA covers 64 rows x 4 heads of one half
    int half = bn >> 6;
    const float* avs = half ? ass : ams;
    const float* avd = half ? asd : amd;
    float* eso = half ? ess : esm;
    float* edo = half ? eds : edm;
    int headT = (tid & 15) >> 2;         // head owned by this thread's 4 cols
    int cc = tx & 15;                    // col offset within head (0,4,8,12)
    float pes[8], ped[8];
#pragma unroll
    for (int i = 0; i < 8; i++) {
        float s1 = 0.f, s2 = 0.f;
#pragma unroll
        for (int j = 0; j < 4; j++) {
            float av = avs[headT * LATD + cc + j];
            float dv = avd[headT * LATD + cc + j];
            s1 = fmaf(acc[i][j], av, s1);
            s2 = fmaf(acc[i][j], dv, s2);
        }
        pes[i] = s1;
        ped[i] = s2;
    }
#pragma unroll
    for (int off = 1; off <= 2; off <<= 1)
#pragma unroll
        for (int i = 0; i < 8; i++) {
            pes[i] += __shfl_xor_sync(0xffffffffu, pes[i], off);
            ped[i] += __shfl_xor_sync(0xffffffffu, ped[i], off);
        }
    if ((tid & 3) == 0) {
#pragma unroll
        for (int i = 0; i < 8; i++) {
            esb[ty + i][headT] = pes[i];
            edb[ty + i][headT] = ped[i];
        }
    }
    __syncthreads();
    for (int idx = tid; idx < 64 * 4; idx += 128) {
        int r = idx >> 2, h = idx & 3;
        eso[(bm + r) * HH + h] = esb[r][h];
        edo[(bm + r) * HH + h] = edb[r][h];
    }
}

// ---------------- CSR build ----------------
__global__ void csr_zero() {
    int i = blockIdx.x * blockDim.x + threadIdx.x;
    if (i < NN) g_cur[i] = 0;
}
__global__ void csr_count(const int* __restrict__ dst) {
    int e = blockIdx.x * blockDim.x + threadIdx.x;
    if (e < EE) atomicAdd(&g_cur[dst[e]], 1);
}
__global__ void csr_scan() {
    __shared__ int sh[1024];
    int t = threadIdx.x;
    int c[4]; int s = 0;
#pragma unroll
    for (int u = 0; u < 4; u++) { c[u] = g_cur[t * 4 + u] + 1; s += c[u]; }
    sh[t] = s;
    __syncthreads();
    for (int o = 1; o < 1024; o <<= 1) {
        int v = (t >= o) ? sh[t - o] : 0;
        __syncthreads();
        sh[t] += v;
        __syncthreads();
    }
    int base = sh[t] - s;
#pragma unroll
    for (int u = 0; u < 4; u++) {
        g_off[t * 4 + u] = base;
        g_cur[t * 4 + u] = base;
        base += c[u];
    }
    if (t == 1023) g_off[NN] = sh[1023];
}
__global__ void csr_scatter2(const int* __restrict__ src, const int* __restrict__ dst) {
    int e = blockIdx.x * blockDim.x + threadIdx.x;
    if (e < EE) {
        int p = atomicAdd(&g_cur[dst[e]], 1);
        g_srcs[p] = src[e];
    } else if (e < ETOT) {
        int n = e - EE;
        int p = atomicAdd(&g_cur[n], 1);
        g_srcs[p] = n;
    }
}

// ---------------- sparse GAT layer, C=128, concat ----------------
__global__ void spagg_concat(const float* __restrict__ es, const float* __restrict__ ed,
                             const float* __restrict__ h, const float* __restrict__ b,
                             float* __restrict__ out) {
    int dst = blockIdx.x;
    int head = threadIdx.x >> 5;
    int lane = threadIdx.x & 31;
    int beg = g_off[dst], end = g_off[dst + 1];
    float edv = ed[dst * HH + head];

    float m = -INFINITY;
    for (int e = beg + lane; e < end; e += 32)
        m = fmaxf(m, lrelu(es[g_srcs[e] * HH + head] + edv));
    for (int o = 16; o > 0; o >>= 1) m = fmaxf(m, __shfl_xor_sync(0xffffffffu, m, o));

    float den = 0.f;
    for (int e = beg + lane; e < end; e += 32)
        den += __expf(lrelu(es[g_srcs[e] * HH + head] + edv) - m);
    for (int o = 16; o > 0; o >>= 1) den += __shfl_xor_sync(0xffffffffu, den, o);
    float inv = 1.f / (den + 1e-16f);

    float a0 = 0.f, a1 = 0.f, a2 = 0.f, a3 = 0.f;
    for (int e = beg; e < end; e++) {
        int s = g_srcs[e];
        float w = __expf(lrelu(es[s * HH + head] + edv) - m) * inv;
        const float* hp = h + s * D1 + head * C1;
        a0 = fmaf(w, hp[lane], a0);
        a1 = fmaf(w, hp[lane + 32], a1);
        a2 = fmaf(w, hp[lane + 64], a2);
        a3 = fmaf(w, hp[lane + 96], a3);
    }
    float* op = out + dst * D1 + head * C1;
    const float* bp = b + head * C1;
    op[lane]      = a0 + bp[lane];
    op[lane + 32] = a1 + bp[lane + 32];
    op[lane + 64] = a2 + bp[lane + 64];
    op[lane + 96] = a3 + bp[lane + 96];
}

// ---------------- sparse GAT mean layers; 2 edges per iter ----------------
__global__ void spagg_mean2(const float* __restrict__ esm, const float* __restrict__ edm,
                            const float* __restrict__ ess, const float* __restrict__ eds,
                            const float* __restrict__ hs2,
                            const float* __restrict__ bm, const float* __restrict__ bs,
                            float* __restrict__ zm, float* __restrict__ zs) {
    int half = blockIdx.y;
    const float* es = half ? ess : esm;
    const float* ed = half ? eds : edm;
    const float* b  = half ? bs : bm;
    float* out      = half ? zs : zm;
    int dst = blockIdx.x * 4 + (threadIdx.x >> 5);
    int lane = threadIdx.x & 31;
    int sub = lane >> 4;
    int c = lane & 15;
    int beg = g_off[dst], end = g_off[dst + 1];
    float acc = 0.f;
    for (int head = 0; head < HH; head++) {
        float edv = ed[dst * HH + head];
        float m = -INFINITY;
        for (int e = beg + lane; e < end; e += 32)
            m = fmaxf(m, lrelu(es[g_srcs[e] * HH + head] + edv));
        for (int o = 16; o > 0; o >>= 1) m = fmaxf(m, __shfl_xor_sync(0xffffffffu, m, o));
        float den = 0.f;
        for (int e = beg + lane; e < end; e += 32)
            den += __expf(lrelu(es[g_srcs[e] * HH + head] + edv) - m);
        for (int o = 16; o > 0; o >>= 1) den += __shfl_xor_sync(0xffffffffu, den, o);
        float inv = 1.f / (den + 1e-16f);
        for (int e = beg; e < end; e += 2) {
            int ee = e + sub;
            if (ee < end) {
                int s = g_srcs[ee];
                float w = __expf(lrelu(es[s * HH + head] + edv) - m) * inv;
                acc = fmaf(w, hs2[s * 128 + half * 64 + head * LATD + c], acc);
            }
        }
    }
    acc += __shfl_down_sync(0xffffffffu, acc, 16);
    if (lane < LATD) out[dst * LATD + lane] = acc * 0.25f + b[lane];
}

// ---------------- fused radix sort + weights + scalar scans ----------------
__device__ __forceinline__ float unmap_key(uint32_t kk) {
    uint32_t m = ~kk;
    return __uint_as_float((m & 0x80000000u) ? (m ^ 0x80000000u) : ~m);
}

__global__ void __launch_bounds__(1024) sortF(const float* __restrict__ esA,
                                              const float* __restrict__ esB) {
    extern __shared__ uint32_t sm[];
    uint32_t* KA = sm;
    uint32_t* VA = sm + 4096;
    uint32_t* KB = sm + 8192;
    uint32_t* VB = sm + 12288;
    uint32_t* WH = sm + 16384;

    int slot = blockIdx.x;
    int t = threadIdx.x;
    int w = t >> 5, lane = t & 31;
    const float* es = (slot < 4) ? esA : esB;
    int head = slot & 3;

    for (int i = t; i < NN; i += 1024) {
        uint32_t b = __float_as_uint(es[i * HH + head]);
        uint32_t m = (b & 0x80000000u) ? ~b : (b | 0x80000000u);
        KA[i] = ~m;
        VA[i] = (uint32_t)i;
    }
    __syncthreads();

    uint32_t *KI = KA, *VI = VA, *KO = KB, *VO = VB;

#pragma unroll
    for (int pass = 0; pass < 4; pass++) {
        int shift = pass * 8;
        for (int i = t; i < 32 * 257; i += 1024) WH[i] = 0;
        __syncthreads();

        uint32_t k_[4], v_[4], d_[4], lr_[4];
#pragma unroll
        for (int r = 0; r < 4; r++) {
            int idx = w * 128 + r * 32 + lane;
            k_[r] = KI[idx];
            v_[r] = VI[idx];
            d_[r] = (k_[r] >> shift) & 255u;
            unsigned mask = __match_any_sync(0xffffffffu, d_[r]);
            int phys = w * 257 + (int)d_[r];
            uint32_t before = WH[phys];
            __syncwarp();
            lr_[r] = before + (uint32_t)__popc(mask & ((1u << lane) - 1u));
            int leader = __ffs((int)mask) - 1;
            if (lane == leader) WH[phys] = before + (uint32_t)__popc(mask);
            __syncwarp();
        }
        __syncthreads();

        uint32_t loc[8], sum = 0;
        int dbase = t >> 2;
        int wbase = (t & 3) * 8;
#pragma unroll
        for (int u = 0; u < 8; u++) {
            loc[u] = WH[(wbase + u) * 257 + dbase];
            sum += loc[u];
        }
        uint32_t totU;
        uint32_t incl = bscan<1024, uint32_t>(sum, totU);
        uint32_t run = incl - sum;
        __syncthreads();
#pragma unroll
        for (int u = 0; u < 8; u++) {
            uint32_t c0 = loc[u];
            WH[(wbase + u) * 257 + dbase] = run;
            run += c0;
        }
        __syncthreads();

#pragma unroll
        for (int r = 0; r < 4; r++) {
            uint32_t dest = WH[w * 257 + (int)d_[r]] + lr_[r];
            KO[dest] = k_[r];
            VO[dest] = v_[r];
        }
        __syncthreads();
        uint32_t* tk = KI; KI = KO; KO = tk;
        uint32_t* tv = VI; VI = VO; VO = tv;
    }

    float mb = unmap_key(KI[0]);
    int base = t * 4;
    float w1v[4], w2v[4];
    float loc1 = 0.f, loc2 = 0.f;
#pragma unroll
    for (int u = 0; u < 4; u++) {
        int i = base + u;
        float kv = unmap_key(KI[i]);
        g_skey[slot * NN + i] = kv;
        g_perm[slot * NN + i] = (int)VI[i];
        float d = kv - mb;
        w1v[u] = __expf(d);
        w2v[u] = __expf(0.2f * d);
        g_w1s[slot * NN + i] = w1v[u];
        g_w2s[slot * NN + i] = w2v[u];
        loc1 += w1v[u];
        loc2 += w2v[u];
    }
    float tot1, tot2;
    float incl1 = bscan<1024, float>(loc1, tot1);
    float incl2 = bscan<1024, float>(loc2, tot2);
    float s = incl1 - loc1;
#pragma unroll
    for (int u = 0; u < 4; u++) { g_s1[slot * (NN + 1) + base + u] = s; s += w1v[u]; }
    if (t == 1023) g_s1[slot * (NN + 1) + NN] = tot1;
    float a2 = tot2 - incl2;
#pragma unroll
    for (int u = 3; u >= 0; u--) { a2 += w2v[u]; g_s2[slot * (NN + 1) + base + u] = a2; }
    if (t == 0) { g_s2[slot * (NN + 1) + NN] = 0.f; g_Mb[slot] = mb; }
}

// ---------------- fused gather + chunk-local scans ----------------
__global__ void __launch_bounds__(C1) vscanC(const float* __restrict__ h) {
    int head = blockIdx.x, ch = blockIdx.y, c = threadIdx.x;
    const int*   perm = g_perm + head * NN + ch * CHLC;
    const float* w1p  = g_w1s + head * NN + ch * CHLC;
    const float* w2p  = g_w2s + head * NN + ch * CHLC;
    long rowbase = (long)head * (NN + 1) + ch * CHLC;
    float hv[CHLC];
    float s = 0.f;
#pragma unroll
    for (int r = 0; r < CHLC; r++) {
        int p = perm[r];
        hv[r] = h[(p * HH + head) * C1 + c];
        s = fmaf(w1p[r], hv[r], s);
        g_P1[(rowbase + r + 1) * C1 + c] = s;
    }
    g_T1[(head * NCHC + ch) * C1 + c] = s;
    s = 0.f;
#pragma unroll
    for (int r = CHLC - 1; r >= 0; r--) {
        s = fmaf(w2p[r], hv[r], s);
        g_S2[(rowbase + r) * C1 + c] = s;
    }
    g_T2[(head * NCHC + ch) * C1 + c] = s;
}

__global__ void __launch_bounds__(128) vscanL(const float* __restrict__ hs2) {
    int slot = blockIdx.x;
    int grp = threadIdx.x >> 4;
    int c = threadIdx.x & 15;
    int ch = blockIdx.y * 8 + grp;
    int half = slot >> 2, head = slot & 3;
    const int*   perm = g_perm + slot * NN + ch * CHLL;
    const float* w1p  = g_w1s + slot * NN + ch * CHLL;
    const float* w2p  = g_w2s + slot * NN + ch * CHLL;
    long rowbase = (long)slot * (NN + 1) + ch * CHLL;
    float hv[CHLL];
    float s = 0.f;
#pragma unroll
    for (int r = 0; r < CHLL; r++) {
        int p = perm[r];
        hv[r] = hs2[p * 128 + half * 64 + head * LATD + c];
        s = fmaf(w1p[r], hv[r], s);
        g_P1[(rowbase + r + 1) * LATD + c] = s;
    }
    g_T1[(slot * NCHL + ch) * LATD + c] = s;
    s = 0.f;
#pragma unroll
    for (int r = CHLL - 1; r >= 0; r--) {
        s = fmaf(w2p[r], hv[r], s);
        g_S2[(rowbase + r) * LATD + c] = s;
    }
    g_T2[(slot * NCHL + ch) * LATD + c] = s;
}

// ---------------- chunk-total prefix/suffix (in place) ----------------
template <int C, int NCHX>
__global__ void tpre_kernel() {
    int slot = blockIdx.x, c = blockIdx.y, t = threadIdx.x;
    float v1 = g_T1[(slot * NCHX + t) * C + c];
    float v2 = g_T2[(slot * NCHX + t) * C + c];
    float tot1, tot2;
    float i1 = bscan<NCHX, float>(v1, tot1);
    float i2 = bscan<NCHX, float>(v2, tot2);
    g_T1[(slot * NCHX + t) * C + c] = i1 - v1;
    g_T2[(slot * NCHX + t) * C + c] = tot2 - i2;
}

__device__ __forceinline__ int bsearch_gt(const float* sk, float t) {
    int lo = 0, hi = NN;
    while (lo < hi) {
        int mid = (lo + hi) >> 1;
        if (sk[mid] > t) lo = mid + 1; else hi = mid;
    }
    return lo;
}

// ---------------- dense GAT layer, C=128, concat ----------------
__global__ void dense_concat(const float* __restrict__ ed, const float* __restrict__ b,
                             float* __restrict__ out) {
    int i = blockIdx.x;
    int head = blockIdx.y;
    int c = threadIdx.x;
    float a = ed[i * HH + head];
    int k = bsearch_gt(g_skey + head * NN, -a);
    float am = a + g_Mb[head];
    float A1 = __expf(am), A2 = __expf(0.2f * am);
    float s1k = g_s1[head * (NN + 1) + k];
    float s2k = g_s2[head * (NN + 1) + k];
    float den = A1 * s1k + A2 * s2k;
    float p1v = 0.f, s2v = 0.f;
    if (k > 0) {
        int q = (k - 1) / CHLC;
        p1v = g_T1[(head * NCHC + q) * C1 + c] + g_P1[((long)head * (NN + 1) + k) * C1 + c];
    }
    if (k < NN) {
        int q = k / CHLC;
        s2v = g_T2[(head * NCHC + q) * C1 + c] + g_S2[((long)head * (NN + 1) + k) * C1 + c];
    }
    float num = A1 * p1v + A2 * s2v;
    out[i * D1 + head * C1 + c] = num / den + b[head * C1 + c];
}

// ---------------- dense GAT mean layers, both halves in one launch ----------------
__global__ void dense_mean2(const float* __restrict__ edm, const float* __restrict__ eds,
                            const float* __restrict__ bm, const float* __restrict__ bs,
                            float* __restrict__ zm, float* __restrict__ zs) {
    __shared__ float sh[64];
    int i = blockIdx.x;
    int half = blockIdx.y;
    int t = threadIdx.x;
    int head = t >> 4;
    int c = t & 15;
    int slot = half * 4 + head;
    const float* ed = half ? eds : edm;
    float a = ed[i * HH + head];
    int k = bsearch_gt(g_skey + slot * NN, -a);
    float am = a + g_Mb[slot];
    float A1 = __expf(am), A2 = __expf(0.2f * am);
    float den = A1 * g_s1[slot * (NN + 1) + k] + A2 * g_s2[slot * (NN + 1) + k];
    float p1v = 0.f, s2v = 0.f;
    if (k > 0) {
        int q = (k - 1) / CHLL;
        p1v = g_T1[(slot * NCHL + q) * LATD + c] + g_P1[((long)slot * (NN + 1) + k) * LATD + c];
    }
    if (k < NN) {
        int q = k / CHLL;
        s2v = g_T2[(slot * NCHL + q) * LATD + c] + g_S2[((long)slot * (NN + 1) + k) * LATD + c];
    }
    float num = A1 * p1v + A2 * s2v;
    sh[t] = num / den;
    __syncthreads();
    if (t < LATD) {
        float* out = half ? zs : zm;
        const float* b = half ? bs : bm;
        out[i * LATD + t] = 0.25f * (sh[t] + sh[16 + t] + sh[32 + t] + sh[48 + t]) + b[t];
    }
}

// ---------------- launch ----------------
extern "C" void kernel_launch(void* const* d_in, const int* in_sizes, int n_in,
                              void* d_out, int out_size) {
    const float* x   = (const float*)d_in[0];
    const int*   ei  = (const int*)d_in[1];
    const float* W1  = (const float*)d_in[3];
    const float* a1s = (const float*)d_in[4];
    const float* a1d = (const float*)d_in[5];
    const float* b1  = (const float*)d_in[6];
    const float* Wm  = (const float*)d_in[7];
    const float* ams = (const float*)d_in[8];
    const float* amd = (const float*)d_in[9];
    const float* bm  = (const float*)d_in[10];
    const float* Ws  = (const float*)d_in[11];
    const float* ass = (const float*)d_in[12];
    const float* asd = (const float*)d_in[13];
    const float* bs  = (const float*)d_in[14];
    float* out = (float*)d_out;
    float* z1m = out;
    float* z1s = out + NN * LATD;
    float* z2m = out + 2 * NN * LATD;
    float* z2s = out + 3 * NN * LATD;

    const int* src = ei;
    const int* dst = ei + EE;

    float *h1, *x1, *x2, *hs2a, *hs2b, *Wc;
    float *es1, *ed1;
    float *es2am, *ed2am, *es2as, *ed2as, *es2bm, *ed2bm, *es2bs, *ed2bs;
    cudaGetSymbolAddress((void**)&h1,    g_h1);
    cudaGetSymbolAddress((void**)&x1,    g_x1);
    cudaGetSymbolAddress((void**)&x2,    g_x2);
    cudaGetSymbolAddress((void**)&hs2a,  g_hs2a);
    cudaGetSymbolAddress((void**)&hs2b,  g_hs2b);
    cudaGetSymbolAddress((void**)&Wc,    g_Wc);
    cudaGetSymbolAddress((void**)&es1,   g_es1);
    cudaGetSymbolAddress((void**)&ed1,   g_ed1);
    cudaGetSymbolAddress((void**)&es2am, g_es2am);
    cudaGetSymbolAddress((void**)&ed2am, g_ed2am);
    cudaGetSymbolAddress((void**)&es2as, g_es2as);
    cudaGetSymbolAddress((void**)&ed2as, g_ed2as);
    cudaGetSymbolAddress((void**)&es2bm, g_es2bm);
    cudaGetSymbolAddress((void**)&ed2bm, g_ed2bm);
    cudaGetSymbolAddress((void**)&es2bs, g_es2bs);
    cudaGetSymbolAddress((void**)&ed2bs, g_ed2bs);

    static cudaStream_t sA = nullptr, sB = nullptr;
    static cudaEvent_t ev0 = nullptr, evW = nullptr, evMain = nullptr, evA = nullptr, evB = nullptr;
    if (sA == nullptr) {
        cudaStreamCreateWithFlags(&sA, cudaStreamNonBlocking);
        cudaStreamCreateWithFlags(&sB, cudaStreamNonBlocking);
        cudaEventCreateWithFlags(&ev0,    cudaEventDisableTiming);
        cudaEventCreateWithFlags(&evW,    cudaEventDisableTiming);
        cudaEventCreateWithFlags(&evMain, cudaEventDisableTiming);
        cudaEventCreateWithFlags(&evA,    cudaEventDisableTiming);
        cudaEventCreateWithFlags(&evB,    cudaEventDisableTiming);
        cudaFuncSetAttribute(mma_gemm, cudaFuncAttributeMaxDynamicSharedMemorySize, NPIPE * STG_B);
        cudaFuncSetAttribute(sortF, cudaFuncAttributeMaxDynamicSharedMemorySize, SORT_SMEM_B);
    }

    // fork: CSR build (sA) + W-side conversions (sB) overlap convA (main)
    cudaEventRecord(ev0, 0);
    cudaStreamWaitEvent(sA, ev0, 0);
    cudaStreamWaitEvent(sB, ev0, 0);
    csr_zero<<<16, 256, 0, sA>>>();
    csr_count<<<(EE + 255) / 256, 256, 0, sA>>>(dst);
    csr_scan<<<1, 1024, 0, sA>>>();
    csr_scatter2<<<(ETOT + 255) / 256, 256, 0, sA>>>(src, dst);

    convBt_kernel<<<dim3(KP / 32, D1 / 32), dim3(32, 8), 0, sB>>>(W1);
    buildWc<<<(D1 * 64 + 255) / 256, 256, 0, sB>>>(Wm, Ws);
    cudaEventRecord(evW, sB);

    convA_kernel<<<1024, 256>>>(x);
    cudaStreamWaitEvent(0, evW, 0);
    mma_gemm<<<dim3(D1 / 128, NN / 128), 256, NPIPE * STG_B>>>(h1, a1s, a1d, es1, ed1);
    cudaEventRecord(evMain, 0);

    // ---- branch A (sparse) ----
    cudaStreamWaitEvent(sA, evMain, 0);
    spagg_concat<<<NN, 128, 0, sA>>>(es1, ed1, h1, b1, x1);
    gemm64e<<<dim3(2, NN / 64), 128, 0, sA>>>(x1, Wc, hs2a, D1,
                                              ams, amd, ass, asd,
                                              es2am, ed2am, es2as, ed2as);
    spagg_mean2<<<dim3(NN / 4, 2), 128, 0, sA>>>(es2am, ed2am, es2as, ed2as, hs2a,
                                                 bm, bs, z1m, z1s);
    cudaEventRecord(evA, sA);

    // ---- branch B (dense, rank-1 softmax) ----
    cudaStreamWaitEvent(sB, evMain, 0);
    sortF<<<4, 1024, SORT_SMEM_B, sB>>>(es1, es1);
    vscanC<<<dim3(HH, NCHC), C1, 0, sB>>>(h1);
    tpre_kernel<C1, NCHC><<<dim3(HH, C1), NCHC, 0, sB>>>();
    dense_concat<<<dim3(NN, HH), C1, 0, sB>>>(ed1, b1, x2);
    gemm64e<<<dim3(2, NN / 64), 128, 0, sB>>>(x2, Wc, hs2b, D1,
                                              ams, amd, ass, asd,
                                              es2bm, ed2bm, es2bs, ed2bs);
    sortF<<<NSLOT, 1024, SORT_SMEM_B, sB>>>(es2bm, es2bs);
    vscanL<<<dim3(NSLOT, NCHL / 8), 128, 0, sB>>>(hs2b);
    tpre_kernel<LATD, NCHL><<<dim3(NSLOT, LATD), NCHL, 0, sB>>>();
    dense_mean2<<<dim3(NN, 2), 64, 0, sB>>>(ed2bm, ed2bs, bm, bs, z2m, z2s);
    cudaEventRecord(evB, sB);

    // join
    cudaStreamWaitEvent(0, evA, 0);
    cudaStreamWaitEvent(0, evB, 0);
}